// round 12
// baseline (speedup 1.0000x reference)
#include <cuda_runtime.h>
#include <cuda_bf16.h>
#include <cuda_fp16.h>
#include <cstdint>

// Problem constants
#define Bsz 2
#define Lseq 2048
#define DM 1024
#define DI 2048          // d_inner
#define Hh 32            // heads
#define Pp 64            // headdim
#define Nn 128           // d_state
#define CONVD 2304       // conv_dim = d_inner + 2*N
#define PROJ 4384        // 2*DI + 2*N + H
#define PROJPAD 4480     // 35*128
#define CHK 64           // block_len
#define NCHUNK 32        // L / CHK
#define ML (Bsz*Lseq)    // 4096 rows
#define EPSV 1.1920929e-07f

// ------------------------- scratch (device globals) -------------------------
__device__ float g_zxbcdt[(size_t)ML * PROJ];
__device__ float g_xbc[(size_t)ML * CONVD];
__device__ float g_dt[(size_t)ML * Hh];
__device__ float g_adt[(size_t)ML * Hh];
__device__ float g_Y[(size_t)ML * DI];
__device__ float g_states[(size_t)Bsz * NCHUNK * Hh * Pp * Nn];
__device__ float g_lastA[Bsz * NCHUNK * Hh];
__device__ float g_cs[Bsz * NCHUNK * Hh * CHK];
__device__ float g_G[(size_t)Bsz * NCHUNK * CHK * CHK];

// fp16 buffers
__device__ __half g_xh[(size_t)ML * DM];
__device__ __half g_wih[(size_t)PROJPAD * DM];
__device__ __half g_ych[(size_t)ML * DI];
__device__ __half g_woh[(size_t)DM * DI];

// ------------------------- helpers ------------------------------------------
__device__ __forceinline__ uint32_t smem_to_u32(const void* p) {
    uint32_t a;
    asm("{ .reg .u64 t; cvta.to.shared.u64 t, %1; cvt.u32.u64 %0, t; }" : "=r"(a) : "l"(p));
    return a;
}
__device__ __forceinline__ void ldmx4(uint32_t* r, uint32_t addr) {
    asm volatile("ldmatrix.sync.aligned.m8n8.x4.shared.b16 {%0,%1,%2,%3}, [%4];"
                 : "=r"(r[0]), "=r"(r[1]), "=r"(r[2]), "=r"(r[3]) : "r"(addr));
}
__device__ __forceinline__ void ldmx4t(uint32_t* r, uint32_t addr) {
    asm volatile("ldmatrix.sync.aligned.m8n8.x4.trans.shared.b16 {%0,%1,%2,%3}, [%4];"
                 : "=r"(r[0]), "=r"(r[1]), "=r"(r[2]), "=r"(r[3]) : "r"(addr));
}
__device__ __forceinline__ void mma16816h(float* c, const uint32_t* a,
                                          uint32_t b0, uint32_t b1) {
    asm volatile("mma.sync.aligned.m16n8k16.row.col.f32.f16.f16.f32 "
                 "{%0,%1,%2,%3}, {%4,%5,%6,%7}, {%8,%9}, {%0,%1,%2,%3};"
                 : "+f"(c[0]), "+f"(c[1]), "+f"(c[2]), "+f"(c[3])
                 : "r"(a[0]), "r"(a[1]), "r"(a[2]), "r"(a[3]), "r"(b0), "r"(b1));
}
__device__ __forceinline__ void cpasync16(uint32_t dst, const void* src) {
    asm volatile("cp.async.cg.shared.global [%0], [%1], 16;" :: "r"(dst), "l"(src));
}
#define CP_COMMIT() asm volatile("cp.async.commit_group;" ::: "memory")
#define CP_WAIT(n)  asm volatile("cp.async.wait_group %0;" :: "n"(n) : "memory")

// ------------------- merged fp16 convert (x, W_in pad, W_out) ---------------
#define CVT_NX  ((size_t)ML * DM)
#define CVT_NW  ((size_t)PROJPAD * DM)
#define CVT_NWO ((size_t)DM * DI)
__global__ void cvt_all_kernel(const float* __restrict__ x,
                               const float* __restrict__ w_in,
                               const float* __restrict__ w_out)
{
    size_t i = (size_t)blockIdx.x * blockDim.x + threadIdx.x;
    if (i < CVT_NX) {
        g_xh[i] = __float2half_rn(x[i]);
    } else if (i < CVT_NX + CVT_NW) {
        size_t j = i - CVT_NX;
        int r = (int)(j / DM);
        g_wih[j] = __float2half_rn((r < PROJ) ? w_in[j] : 0.f);
    } else if (i < CVT_NX + CVT_NW + CVT_NWO) {
        size_t j = i - CVT_NX - CVT_NW;
        g_woh[j] = __float2half_rn(w_out[j]);
    }
}

// ------------------------- fp16 mma.sync GEMM (128x128 tile, BK=64) ----------
#define SROW 72             // 64 fp16 + 8 pad
#define GST  (128 * SROW)
#define GSMEM_BYTES (2 * 2 * GST * 2)

__global__ __launch_bounds__(256) void gemm_fp16(
    const __half* __restrict__ A, const __half* __restrict__ Bw,
    const float* __restrict__ res, float* __restrict__ C,
    int K, int Nstore)
{
    extern __shared__ __align__(16) __half gsm[];
    int tid = threadIdx.x;
    int lane = tid & 31, wid = tid >> 5;
    int warp_m = wid >> 1, warp_n = wid & 1;
    int bn = blockIdx.x * 128;
    int bm = blockIdx.y * 128;

    int NC = K >> 6;

    float c[2][8][4];
#pragma unroll
    for (int i = 0; i < 2; i++)
#pragma unroll
        for (int j = 0; j < 8; j++)
#pragma unroll
            for (int q = 0; q < 4; q++) c[i][j][q] = 0.f;

    auto load_chunk = [&](int ci, int s) {
        int kk = ci * 64;
#pragma unroll
        for (int it = 0; it < 8; it++) {
            int t = tid + it * 256;
            int tile = t >> 10;
            int idx = t & 1023;
            int row = idx >> 3;
            int sg = idx & 7;
            const __half* src = tile ? (Bw + (size_t)(bn + row) * K + kk + sg * 8)
                                     : (A + (size_t)(bm + row) * K + kk + sg * 8);
            uint32_t dst = smem_to_u32(gsm + (size_t)(s * 2 + tile) * GST + row * SROW + sg * 8);
            cpasync16(dst, src);
        }
        CP_COMMIT();
    };

    load_chunk(0, 0);
    for (int ci = 0; ci < NC; ci++) {
        int s = ci & 1;
        if (ci + 1 < NC) { load_chunk(ci + 1, s ^ 1); CP_WAIT(1); }
        else CP_WAIT(0);
        __syncthreads();

        uint32_t a_base = smem_to_u32(gsm + (size_t)(s * 2 + 0) * GST);
        uint32_t b_base = smem_to_u32(gsm + (size_t)(s * 2 + 1) * GST);
#pragma unroll
        for (int k0 = 0; k0 < 64; k0 += 16) {
            uint32_t a[2][4];
#pragma unroll
            for (int im = 0; im < 2; im++) {
                uint32_t addr = a_base
                    + (uint32_t)(warp_m * 32 + im * 16 + (lane & 15)) * (SROW * 2)
                    + (uint32_t)(k0 + ((lane >> 4) << 3)) * 2;
                ldmx4(a[im], addr);
            }
            uint32_t bf[4][4];
#pragma unroll
            for (int ib = 0; ib < 4; ib++) {
                uint32_t addr = b_base
                    + (uint32_t)(warp_n * 64 + ib * 16 + (((lane >> 3) & 1) << 3) + (lane & 7)) * (SROW * 2)
                    + (uint32_t)(k0 + ((lane >> 4) << 3)) * 2;
                ldmx4(bf[ib], addr);
            }
#pragma unroll
            for (int im = 0; im < 2; im++)
#pragma unroll
                for (int in = 0; in < 8; in++) {
                    int ib = in >> 1, wh = in & 1;
                    mma16816h(c[im][in], a[im], bf[ib][wh], bf[ib][2 + wh]);
                }
        }
        __syncthreads();
    }

    int gp = lane >> 2, tg = lane & 3;
#pragma unroll
    for (int im = 0; im < 2; im++) {
        int m0 = bm + warp_m * 32 + im * 16;
#pragma unroll
        for (int in = 0; in < 8; in++) {
            int n = bn + warp_n * 64 + in * 8 + tg * 2;
            if (n >= Nstore) continue;
#pragma unroll
            for (int half = 0; half < 2; half++) {
                int m = m0 + gp + half * 8;
                float2 v;
                v.x = c[im][in][half * 2 + 0];
                v.y = c[im][in][half * 2 + 1];
                if (res) {
                    const float2 rv = *(const float2*)(res + (size_t)m * Nstore + n);
                    v.x += rv.x; v.y += rv.y;
                }
                *(float2*)(C + (size_t)m * Nstore + n) = v;
            }
        }
    }
}

// ----------------- exact fp32 dt GEMM: 64 blocks x 64 rows ------------------
#define DTS_X   0
#define DTS_W   (64 * 132)
#define DTSM_BYTES ((64 * 132 + 32 * 131) * 4)

__global__ __launch_bounds__(256) void dtfix_kernel(
    const float* __restrict__ x, const float* __restrict__ in_proj_w,
    const float* __restrict__ A_log, const float* __restrict__ dt_bias)
{
    extern __shared__ float dts[];
    float* sx = dts + DTS_X;
    float* sw = dts + DTS_W;
    int r0 = blockIdx.x * 64;
    int tid = threadIdx.x;
    int hg = tid & 7, rg = tid >> 3;
    int rr0 = rg * 2, hh0 = hg * 4;
    float acc[2][4];
#pragma unroll
    for (int i = 0; i < 2; i++)
#pragma unroll
        for (int j = 0; j < 4; j++) acc[i][j] = 0.f;

    for (int kc = 0; kc < 8; kc++) {
        int k0 = kc * 128;
        for (int t = tid; t < 2048; t += 256) {
            int r = t >> 5, q = (t & 31) * 4;
            float4 v = *(const float4*)(x + (size_t)(r0 + r) * DM + k0 + q);
            *(float4*)(sx + r * 132 + q) = v;
        }
        for (int t = tid; t < 1024; t += 256) {
            int r = t >> 5, q = (t & 31) * 4;
            float4 v = *(const float4*)(in_proj_w + (size_t)(DI + CONVD + r) * DM + k0 + q);
            sw[r * 131 + q + 0] = v.x; sw[r * 131 + q + 1] = v.y;
            sw[r * 131 + q + 2] = v.z; sw[r * 131 + q + 3] = v.w;
        }
        __syncthreads();
#pragma unroll 4
        for (int k = 0; k < 128; k++) {
            float x0 = sx[rr0 * 132 + k];
            float x1 = sx[(rr0 + 1) * 132 + k];
            float w0 = sw[(hh0 + 0) * 131 + k];
            float w1 = sw[(hh0 + 1) * 131 + k];
            float w2 = sw[(hh0 + 2) * 131 + k];
            float w3 = sw[(hh0 + 3) * 131 + k];
            acc[0][0] = fmaf(x0, w0, acc[0][0]);
            acc[0][1] = fmaf(x0, w1, acc[0][1]);
            acc[0][2] = fmaf(x0, w2, acc[0][2]);
            acc[0][3] = fmaf(x0, w3, acc[0][3]);
            acc[1][0] = fmaf(x1, w0, acc[1][0]);
            acc[1][1] = fmaf(x1, w1, acc[1][1]);
            acc[1][2] = fmaf(x1, w2, acc[1][2]);
            acc[1][3] = fmaf(x1, w3, acc[1][3]);
        }
        __syncthreads();
    }
#pragma unroll
    for (int i = 0; i < 2; i++) {
        int ml = r0 + rr0 + i;
#pragma unroll
        for (int j = 0; j < 4; j++) {
            int h = hh0 + j;
            float raw = acc[i][j] + dt_bias[h];
            float sp = (raw > 20.f) ? raw : log1pf(expf(raw));
            g_dt[ml * Hh + h] = sp;
            g_adt[ml * Hh + h] = -expf(A_log[h]) * sp;
        }
    }
}

// ------------- causal depthwise conv + double silu (smem-tiled) -------------
__device__ __forceinline__ float silu_f(float x) { return x / (1.f + expf(-x)); }

__global__ __launch_bounds__(256) void conv_kernel(const float* __restrict__ conv_w)
{
    __shared__ float sxm[35][132];
    int cc = blockIdx.x;
    int ytile = blockIdx.y;
    int b = ytile >> 6;
    int l0 = (ytile & 63) * 32;
    int tid = threadIdx.x;
    int ch_base = cc * 128;

    for (int t = tid; t < 35 * 32; t += 256) {
        int r = t >> 5, q = (t & 31) * 4;
        int ls = l0 - 3 + r;
        float4 v = make_float4(0.f, 0.f, 0.f, 0.f);
        if (ls >= 0 && r < 32 + 3)
            v = *(const float4*)(g_zxbcdt + ((size_t)(b * Lseq + ls)) * PROJ + DI + ch_base + q);
        *(float4*)(&sxm[r][q]) = v;
    }
    __syncthreads();

    int tx = tid & 31, ty = tid >> 5;
    int ch4 = tx * 4;
    float4 w0 = *(const float4*)(conv_w + (ch_base + ch4 + 0) * 4);
    float4 w1 = *(const float4*)(conv_w + (ch_base + ch4 + 1) * 4);
    float4 w2 = *(const float4*)(conv_w + (ch_base + ch4 + 2) * 4);
    float4 w3 = *(const float4*)(conv_w + (ch_base + ch4 + 3) * 4);
#pragma unroll
    for (int li = 0; li < 4; li++) {
        int lloc = ty * 4 + li;
        float a0 = 0.f, a1 = 0.f, a2 = 0.f, a3 = 0.f;
#pragma unroll
        for (int j = 0; j < 4; j++) {
            const float* row = &sxm[lloc + j][ch4];
            a0 = fmaf(row[0], (&w0.x)[j], a0);
            a1 = fmaf(row[1], (&w1.x)[j], a1);
            a2 = fmaf(row[2], (&w2.x)[j], a2);
            a3 = fmaf(row[3], (&w3.x)[j], a3);
        }
        float4 o;
        o.x = silu_f(silu_f(a0));
        o.y = silu_f(silu_f(a1));
        o.z = silu_f(silu_f(a2));
        o.w = silu_f(silu_f(a3));
        *(float4*)(g_xbc + (size_t)(b * Lseq + l0 + lloc) * CONVD + ch_base + ch4) = o;
    }
}

// ------------- G = C * B^T per (b,c), 4-way split over l --------------------
__global__ __launch_bounds__(256) void gmat_kernel()
{
    int c = blockIdx.x, b = blockIdx.y, z = blockIdx.z;
    __shared__ float sB[64][33];
    __shared__ float sC[16][33];
    int tid = threadIdx.x;
    int tx = tid & 15, ty = tid >> 4;
    int lloc = ty, s0 = tx * 4;
    size_t rowbase = (size_t)(b * Lseq + c * CHK);
    int lg = z * 16;
    float g4[4] = {0.f, 0.f, 0.f, 0.f};

    for (int nc = 0; nc < Nn; nc += 32) {
        for (int t = tid; t < 64 * 8; t += 256) {
            int l = t >> 3, q = (t & 7) * 4;
            float4 bv = *(const float4*)(g_xbc + (rowbase + l) * CONVD + DI + nc + q);
            sB[l][q + 0] = bv.x; sB[l][q + 1] = bv.y;
            sB[l][q + 2] = bv.z; sB[l][q + 3] = bv.w;
        }
        if (tid < 16 * 8) {
            int l = tid >> 3, q = (tid & 7) * 4;
            float4 cv = *(const float4*)(g_xbc + (rowbase + lg + l) * CONVD + DI + Nn + nc + q);
            sC[l][q + 0] = cv.x; sC[l][q + 1] = cv.y;
            sC[l][q + 2] = cv.z; sC[l][q + 3] = cv.w;
        }
        __syncthreads();
#pragma unroll
        for (int n = 0; n < 32; n++) {
            float cr = sC[lloc][n];
            g4[0] = fmaf(cr, sB[s0 + 0][n], g4[0]);
            g4[1] = fmaf(cr, sB[s0 + 1][n], g4[1]);
            g4[2] = fmaf(cr, sB[s0 + 2][n], g4[2]);
            g4[3] = fmaf(cr, sB[s0 + 3][n], g4[3]);
        }
        __syncthreads();
    }
    float* Gp = g_G + ((size_t)(b * NCHUNK + c)) * (CHK * CHK);
    float4 v = make_float4(g4[0], g4[1], g4[2], g4[3]);
    *(float4*)(Gp + (lg + lloc) * 64 + s0) = v;
}

// -------------- per-chunk SSD via tensor cores, 2 heads per CTA --------------
__global__ __launch_bounds__(256) void chunk_kernel()
{
    __shared__ __half sM[64][72];
    __shared__ __half sX[64][72];
    __shared__ __half sB[64][136];
    __shared__ float scs[64];
    int c = blockIdx.x, hp = blockIdx.y, b = blockIdx.z;
    int tid = threadIdx.x, lane = tid & 31, wid = tid >> 5;
    size_t rowbase = (size_t)(b * Lseq + c * CHK);

    // shared-across-heads B tile, loaded once
    for (int i = tid; i < 64 * 32; i += 256) {
        int l = i >> 5, q = (i & 31) * 4;
        float4 v = *(const float4*)(g_xbc + (rowbase + l) * CONVD + DI + q);
        sB[l][q + 0] = __float2half_rn(v.x);
        sB[l][q + 1] = __float2half_rn(v.y);
        sB[l][q + 2] = __float2half_rn(v.z);
        sB[l][q + 3] = __float2half_rn(v.w);
    }

    int gp = lane >> 2, tg = lane & 3;
    const float* Gp = g_G + ((size_t)(b * NCHUNK + c)) * (CHK * CHK);

    for (int it = 0; it < 2; it++) {
        int h = hp * 2 + it;

        if (wid == 0) {
            float v0 = g_adt[(rowbase + lane) * Hh + h];
            float v1 = g_adt[(rowbase + 32 + lane) * Hh + h];
#pragma unroll
            for (int off = 1; off < 32; off <<= 1) {
                float t = __shfl_up_sync(0xFFFFFFFF, v0, off);
                if (lane >= off) v0 += t;
            }
            float tot = __shfl_sync(0xFFFFFFFF, v0, 31);
#pragma unroll
            for (int off = 1; off < 32; off <<= 1) {
                float t = __shfl_up_sync(0xFFFFFFFF, v1, off);
                if (lane >= off) v1 += t;
            }
            v1 += tot;
            scs[lane] = v0;
            scs[32 + lane] = v1;
        }
        for (int i = tid; i < 64 * 16; i += 256) {
            int l = i >> 4, q = (i & 15) * 4;
            float4 v = *(const float4*)(g_xbc + (rowbase + l) * CONVD + h * 64 + q);
            float d = g_dt[(rowbase + l) * Hh + h];
            sX[l][q + 0] = __float2half_rn(v.x * d);
            sX[l][q + 1] = __float2half_rn(v.y * d);
            sX[l][q + 2] = __float2half_rn(v.z * d);
            sX[l][q + 3] = __float2half_rn(v.w * d);
        }
        __syncthreads();

        {
            int tx = tid & 15, ty = tid >> 4;
            int l0 = ty * 4, s0 = tx * 4;
#pragma unroll
            for (int i = 0; i < 4; i++) {
                int l = l0 + i;
                float4 gv = *(const float4*)(Gp + l * 64 + s0);
                float csl = scs[l];
                sM[l][s0 + 0] = __float2half_rn((s0 + 0 <= l) ? gv.x * expf(csl - scs[s0 + 0]) : 0.f);
                sM[l][s0 + 1] = __float2half_rn((s0 + 1 <= l) ? gv.y * expf(csl - scs[s0 + 1]) : 0.f);
                sM[l][s0 + 2] = __float2half_rn((s0 + 2 <= l) ? gv.z * expf(csl - scs[s0 + 2]) : 0.f);
                sM[l][s0 + 3] = __float2half_rn((s0 + 3 <= l) ? gv.w * expf(csl - scs[s0 + 3]) : 0.f);
            }
        }
        __syncthreads();

        {
            int wm = wid & 3, wn = wid >> 2;
            float cy[4][4];
#pragma unroll
            for (int i = 0; i < 4; i++)
#pragma unroll
                for (int j = 0; j < 4; j++) cy[i][j] = 0.f;
#pragma unroll
            for (int k0 = 0; k0 < 64; k0 += 16) {
                uint32_t a[4];
                ldmx4(a, smem_to_u32(&sM[wm * 16 + (lane & 15)][k0 + ((lane >> 4) << 3)]));
#pragma unroll
                for (int g = 0; g < 2; g++) {
                    uint32_t bf[4];
                    ldmx4t(bf, smem_to_u32(&sX[k0 + (lane & 15)][wn * 32 + g * 16 + ((lane >> 4) << 3)]));
                    mma16816h(cy[g * 2 + 0], a, bf[0], bf[1]);
                    mma16816h(cy[g * 2 + 1], a, bf[2], bf[3]);
                }
            }
#pragma unroll
            for (int nb = 0; nb < 4; nb++) {
                int p = wn * 32 + nb * 8 + tg * 2;
#pragma unroll
                for (int hf = 0; hf < 2; hf++) {
                    int l = wm * 16 + gp + hf * 8;
                    float2 v = make_float2(cy[nb][hf * 2 + 0], cy[nb][hf * 2 + 1]);
                    *(float2*)(g_Y + (rowbase + l) * DI + h * 64 + p) = v;
                }
            }
        }
        __syncthreads();

        {
            float alast = scs[63];
            for (int i = tid; i < 64 * 64; i += 256) {
                int l = i >> 6, p = i & 63;
                float e = expf(alast - scs[l]);
                sX[l][p] = __float2half_rn(__half2float(sX[l][p]) * e);
            }
        }
        __syncthreads();

        {
            int pmw = wid & 3, nw = wid >> 2;
            int p0 = pmw * 16, n0 = nw * 64;
            float cs2[8][4];
#pragma unroll
            for (int i = 0; i < 8; i++)
#pragma unroll
                for (int j = 0; j < 4; j++) cs2[i][j] = 0.f;
#pragma unroll
            for (int k0 = 0; k0 < 64; k0 += 16) {
                uint32_t r[4];
                ldmx4t(r, smem_to_u32(&sX[k0 + (lane & 15)][p0 + ((lane >> 4) << 3)]));
                uint32_t a[4] = {r[0], r[2], r[1], r[3]};
#pragma unroll
                for (int g = 0; g < 4; g++) {
                    uint32_t bf[4];
                    ldmx4t(bf, smem_to_u32(&sB[k0 + (lane & 15)][n0 + g * 16 + ((lane >> 4) << 3)]));
                    mma16816h(cs2[g * 2 + 0], a, bf[0], bf[1]);
                    mma16816h(cs2[g * 2 + 1], a, bf[2], bf[3]);
                }
            }
            size_t sbase = (((size_t)(b * NCHUNK + c)) * Hh + h) * (Pp * Nn);
#pragma unroll
            for (int nb = 0; nb < 8; nb++) {
                int n = n0 + nb * 8 + tg * 2;
#pragma unroll
                for (int hf = 0; hf < 2; hf++) {
                    int p = p0 + gp + hf * 8;
                    float2 v = make_float2(cs2[nb][hf * 2 + 0], cs2[nb][hf * 2 + 1]);
                    *(float2*)(g_states + sbase + (size_t)p * Nn + n) = v;
                }
            }
        }

        if (tid < 64) g_cs[((b * NCHUNK + c) * Hh + h) * CHK + tid] = scs[tid];
        if (tid == 0) g_lastA[(b * NCHUNK + c) * Hh + h] = scs[63];
        __syncthreads();
    }
}

// ---------- inter-chunk scan, 8-way sliced, float4 ---------------------------
__global__ __launch_bounds__(256) void scan_kernel(const float* __restrict__ init_state,
                                                   float* __restrict__ fstate_out)
{
    int bh = blockIdx.x;
    int h = bh & (Hh - 1), b = bh >> 5;
    int off = blockIdx.y * 1024 + threadIdx.x * 4;
    size_t ibase = ((size_t)(b * Hh + h)) * (Pp * Nn);
    float4 run = *(const float4*)(init_state + ibase + off);
    for (int c = 0; c < NCHUNK; c++) {
        float dec = expf(g_lastA[(b * NCHUNK + c) * Hh + h]);
        size_t idx = (((size_t)(b * NCHUNK + c)) * Hh + h) * (Pp * Nn) + off;
        float4 v = *(const float4*)(g_states + idx);
        *(float4*)(g_states + idx) = run;
        run.x = fmaf(dec, run.x, v.x);
        run.y = fmaf(dec, run.y, v.y);
        run.z = fmaf(dec, run.z, v.z);
        run.w = fmaf(dec, run.w, v.w);
    }
    *(float4*)(fstate_out + ibase + off) = run;
}

// --------- Y_off + D*X epilogue via tensor cores, 2 heads per CTA -----------
__global__ __launch_bounds__(256) void yoff_kernel(const float* __restrict__ D_param)
{
    __shared__ __half sC[64][136];
    __shared__ __half sS[64][136];
    __shared__ float scs[64];
    int c = blockIdx.x, hp = blockIdx.y, b = blockIdx.z;
    int tid = threadIdx.x, lane = tid & 31, wid = tid >> 5;
    size_t rowbase = (size_t)(b * Lseq + c * CHK);

    // head-invariant C tile, loaded once
    for (int t = tid; t < 64 * 32; t += 256) {
        int r = t >> 5, q = (t & 31) * 4;
        float4 cv = *(const float4*)(g_xbc + (rowbase + r) * CONVD + DI + Nn + q);
        sC[r][q + 0] = __float2half_rn(cv.x);
        sC[r][q + 1] = __float2half_rn(cv.y);
        sC[r][q + 2] = __float2half_rn(cv.z);
        sC[r][q + 3] = __float2half_rn(cv.w);
    }

    int gp = lane >> 2, tg = lane & 3;
    for (int it = 0; it < 2; it++) {
        int h = hp * 2 + it;
        if (tid < 64) scs[tid] = g_cs[((b * NCHUNK + c) * Hh + h) * CHK + tid];

        size_t sbase = (((size_t)(b * NCHUNK + c)) * Hh + h) * (Pp * Nn);
        for (int t = tid; t < 64 * 32; t += 256) {
            int r = t >> 5, q = (t & 31) * 4;
            float4 sv = *(const float4*)(g_states + sbase + (size_t)r * Nn + q);
            sS[r][q + 0] = __float2half_rn(sv.x);
            sS[r][q + 1] = __float2half_rn(sv.y);
            sS[r][q + 2] = __float2half_rn(sv.z);
            sS[r][q + 3] = __float2half_rn(sv.w);
        }
        __syncthreads();

        int wm = wid & 3, wn = wid >> 2;
        int l0 = wm * 16, p0 = wn * 32;
        float acc[4][4];
#pragma unroll
        for (int i = 0; i < 4; i++)
#pragma unroll
            for (int j = 0; j < 4; j++) acc[i][j] = 0.f;

#pragma unroll
        for (int k0 = 0; k0 < Nn; k0 += 16) {
            uint32_t a[4];
            ldmx4(a, smem_to_u32(&sC[l0 + (lane & 15)][k0 + ((lane >> 4) << 3)]));
            uint32_t bf[2][4];
#pragma unroll
            for (int g = 0; g < 2; g++)
                ldmx4(bf[g], smem_to_u32(
                    &sS[p0 + g * 16 + (((lane >> 3) & 1) << 3) + (lane & 7)][k0 + ((lane >> 4) << 3)]));
#pragma unroll
            for (int nb = 0; nb < 4; nb++) {
                int ib = nb >> 1, wh = nb & 1;
                mma16816h(acc[nb], a, bf[ib][wh], bf[ib][2 + wh]);
            }
        }
        float Dh = D_param[h];
#pragma unroll
        for (int nb = 0; nb < 4; nb++) {
            int p = p0 + nb * 8 + tg * 2;
#pragma unroll
            for (int hf = 0; hf < 2; hf++) {
                int l = l0 + gp + hf * 8;
                float e = expf(scs[l]);
                size_t gi = (rowbase + l) * DI + h * 64 + p;
                float2 yv = *(const float2*)(g_Y + gi);
                float2 xv = *(const float2*)(g_xbc + (rowbase + l) * CONVD + h * 64 + p);
                yv.x += e * acc[nb][hf * 2 + 0] + Dh * xv.x;
                yv.y += e * acc[nb][hf * 2 + 1] + Dh * xv.y;
                *(float2*)(g_Y + gi) = yv;
            }
        }
        __syncthreads();
    }
}

// -------- RMSNorm * norm_w * sigmoid(z) -> fp16 y_core directly --------------
__global__ __launch_bounds__(256) void rms_cvt_kernel(const float* __restrict__ norm_w)
{
    int row = blockIdx.x;
    int tid = threadIdx.x, lane = tid & 31, wid = tid >> 5;
    __shared__ float red[8];
    const float* y = g_Y + (size_t)row * DI;
    float ss = 0.f;
    for (int j = tid; j < DI; j += 256) { float v = y[j]; ss = fmaf(v, v, ss); }
#pragma unroll
    for (int off = 16; off > 0; off >>= 1) ss += __shfl_xor_sync(0xFFFFFFFF, ss, off);
    if (lane == 0) red[wid] = ss;
    __syncthreads();
    if (wid == 0) {
        float v = (lane < 8) ? red[lane] : 0.f;
#pragma unroll
        for (int off = 4; off > 0; off >>= 1) v += __shfl_xor_sync(0xFFFFFFFF, v, off);
        if (lane == 0) red[0] = v;
    }
    __syncthreads();
    float scale = rsqrtf(red[0] / (float)DI + EPSV);
    __half* ph = g_ych + (size_t)row * DI;
    for (int j = tid; j < DI; j += 256) {
        float z = g_zxbcdt[(size_t)row * PROJ + j];
        float sig = 1.f / (1.f + expf(-z));
        ph[j] = __float2half_rn(y[j] * scale * norm_w[j] * sig);
    }
}

// ------------------------- launch ------------------------------------------
extern "C" void kernel_launch(void* const* d_in, const int* in_sizes, int n_in,
                              void* d_out, int out_size)
{
    const float* x         = (const float*)d_in[0];
    const float* state     = (const float*)d_in[1];
    const float* in_proj_w = (const float*)d_in[2];
    const float* conv_w    = (const float*)d_in[3];
    const float* A_log     = (const float*)d_in[4];
    const float* dt_bias   = (const float*)d_in[5];
    const float* D_param   = (const float*)d_in[6];
    const float* norm_w    = (const float*)d_in[7];
    const float* out_proj_w= (const float*)d_in[8];
    float* out = (float*)d_out;

    float* zx;   cudaGetSymbolAddress((void**)&zx, g_zxbcdt);
    __half *xh, *wih, *ych, *woh;
    cudaGetSymbolAddress((void**)&xh, g_xh);
    cudaGetSymbolAddress((void**)&wih, g_wih);
    cudaGetSymbolAddress((void**)&ych, g_ych);
    cudaGetSymbolAddress((void**)&woh, g_woh);

    cudaFuncSetAttribute(gemm_fp16, cudaFuncAttributeMaxDynamicSharedMemorySize, GSMEM_BYTES);
    cudaFuncSetAttribute(dtfix_kernel, cudaFuncAttributeMaxDynamicSharedMemorySize, DTSM_BYTES);

    // 1) merged fp16 converts
    {
        size_t total = CVT_NX + CVT_NW + CVT_NWO;
        cvt_all_kernel<<<(unsigned)((total + 255) / 256), 256>>>(x, in_proj_w, out_proj_w);
    }
    // 2) in_proj GEMM (fp16, 128x128 tiles, BK=64)
    gemm_fp16<<<dim3(PROJPAD / 128, ML / 128), 256, GSMEM_BYTES>>>(
        xh, wih, nullptr, zx, DM, PROJ);
    // 3) exact fp32 dt
    dtfix_kernel<<<ML / 64, 256, DTSM_BYTES>>>(x, in_proj_w, A_log, dt_bias);
    // 4) conv + double silu (smem-tiled)
    conv_kernel<<<dim3(CONVD / 128, Bsz * (Lseq / 32)), 256>>>(conv_w);
    // 5) G = C B^T once per (b,c), 4-way l-split
    gmat_kernel<<<dim3(NCHUNK, Bsz, 4), 256>>>();
    // 6) per-chunk SSD (tensor cores, 2 heads/CTA)
    chunk_kernel<<<dim3(NCHUNK, Hh / 2, Bsz), 256>>>();
    // 7) inter-chunk scan + final state
    scan_kernel<<<dim3(Bsz * Hh, 8), 256>>>(state, out + (size_t)ML * DM);
    // 8) Y_off + D*X (tensor cores, 2 heads/CTA)
    yoff_kernel<<<dim3(NCHUNK, Hh / 2, Bsz), 256>>>(D_param);
    // 9) RMSNorm + gate + fp16 convert
    rms_cvt_kernel<<<ML, 256>>>(norm_w);
    // 10) out_proj GEMM (fp16) + residual -> d_out
    gemm_fp16<<<dim3(DM / 128, ML / 128), 256, GSMEM_BYTES>>>(
        ych, woh, x, out, DI, DM);
}

// round 13
// speedup vs baseline: 1.0415x; 1.0415x over previous
#include <cuda_runtime.h>
#include <cuda_bf16.h>
#include <cuda_fp16.h>
#include <cstdint>

// Problem constants
#define Bsz 2
#define Lseq 2048
#define DM 1024
#define DI 2048          // d_inner
#define Hh 32            // heads
#define Pp 64            // headdim
#define Nn 128           // d_state
#define CONVD 2304       // conv_dim = d_inner + 2*N
#define PROJ 4384        // 2*DI + 2*N + H
#define PROJPAD 4480     // 35*128
#define CHK 64           // block_len
#define NCHUNK 32        // L / CHK
#define ML (Bsz*Lseq)    // 4096 rows
#define EPSV 1.1920929e-07f

// ------------------------- scratch (device globals) -------------------------
__device__ float g_zxbcdt[(size_t)ML * PROJ];
__device__ float g_xbc[(size_t)ML * CONVD];
__device__ float g_dt[(size_t)ML * Hh];
__device__ float g_adt[(size_t)ML * Hh];
__device__ float g_Y[(size_t)ML * DI];
__device__ float g_states[(size_t)Bsz * NCHUNK * Hh * Pp * Nn];
__device__ float g_lastA[Bsz * NCHUNK * Hh];
__device__ float g_cs[Bsz * NCHUNK * Hh * CHK];
__device__ float g_G[(size_t)Bsz * NCHUNK * CHK * CHK];

// fp16 buffers
__device__ __half g_xh[(size_t)ML * DM];
__device__ __half g_wih[(size_t)PROJPAD * DM];
__device__ __half g_ych[(size_t)ML * DI];
__device__ __half g_woh[(size_t)DM * DI];

// ------------------------- helpers ------------------------------------------
__device__ __forceinline__ uint32_t smem_to_u32(const void* p) {
    uint32_t a;
    asm("{ .reg .u64 t; cvta.to.shared.u64 t, %1; cvt.u32.u64 %0, t; }" : "=r"(a) : "l"(p));
    return a;
}
__device__ __forceinline__ void ldmx4(uint32_t* r, uint32_t addr) {
    asm volatile("ldmatrix.sync.aligned.m8n8.x4.shared.b16 {%0,%1,%2,%3}, [%4];"
                 : "=r"(r[0]), "=r"(r[1]), "=r"(r[2]), "=r"(r[3]) : "r"(addr));
}
__device__ __forceinline__ void ldmx4t(uint32_t* r, uint32_t addr) {
    asm volatile("ldmatrix.sync.aligned.m8n8.x4.trans.shared.b16 {%0,%1,%2,%3}, [%4];"
                 : "=r"(r[0]), "=r"(r[1]), "=r"(r[2]), "=r"(r[3]) : "r"(addr));
}
__device__ __forceinline__ void mma16816h(float* c, const uint32_t* a,
                                          uint32_t b0, uint32_t b1) {
    asm volatile("mma.sync.aligned.m16n8k16.row.col.f32.f16.f16.f32 "
                 "{%0,%1,%2,%3}, {%4,%5,%6,%7}, {%8,%9}, {%0,%1,%2,%3};"
                 : "+f"(c[0]), "+f"(c[1]), "+f"(c[2]), "+f"(c[3])
                 : "r"(a[0]), "r"(a[1]), "r"(a[2]), "r"(a[3]), "r"(b0), "r"(b1));
}
__device__ __forceinline__ void cpasync16(uint32_t dst, const void* src) {
    asm volatile("cp.async.cg.shared.global [%0], [%1], 16;" :: "r"(dst), "l"(src));
}
#define CP_COMMIT() asm volatile("cp.async.commit_group;" ::: "memory")
#define CP_WAIT(n)  asm volatile("cp.async.wait_group %0;" :: "n"(n) : "memory")

// ------------------- merged fp16 convert (x, W_in pad, W_out) ---------------
#define CVT_NX  ((size_t)ML * DM)
#define CVT_NW  ((size_t)PROJPAD * DM)
#define CVT_NWO ((size_t)DM * DI)
__global__ void cvt_all_kernel(const float* __restrict__ x,
                               const float* __restrict__ w_in,
                               const float* __restrict__ w_out)
{
    size_t i = (size_t)blockIdx.x * blockDim.x + threadIdx.x;
    if (i < CVT_NX) {
        g_xh[i] = __float2half_rn(x[i]);
    } else if (i < CVT_NX + CVT_NW) {
        size_t j = i - CVT_NX;
        int r = (int)(j / DM);
        g_wih[j] = __float2half_rn((r < PROJ) ? w_in[j] : 0.f);
    } else if (i < CVT_NX + CVT_NW + CVT_NWO) {
        size_t j = i - CVT_NX - CVT_NW;
        g_woh[j] = __float2half_rn(w_out[j]);
    }
}

// ------------------------- fp16 mma.sync GEMM (128x128 tile, BK=64) ----------
#define SROW 72             // 64 fp16 + 8 pad
#define GST  (128 * SROW)
#define GSMEM_BYTES (2 * 2 * GST * 2)

__global__ __launch_bounds__(256) void gemm_fp16(
    const __half* __restrict__ A, const __half* __restrict__ Bw,
    const float* __restrict__ res, float* __restrict__ C,
    int K, int Nstore)
{
    extern __shared__ __align__(16) __half gsm[];
    int tid = threadIdx.x;
    int lane = tid & 31, wid = tid >> 5;
    int warp_m = wid >> 1, warp_n = wid & 1;
    int bn = blockIdx.x * 128;
    int bm = blockIdx.y * 128;

    int NC = K >> 6;

    float c[2][8][4];
#pragma unroll
    for (int i = 0; i < 2; i++)
#pragma unroll
        for (int j = 0; j < 8; j++)
#pragma unroll
            for (int q = 0; q < 4; q++) c[i][j][q] = 0.f;

    auto load_chunk = [&](int ci, int s) {
        int kk = ci * 64;
#pragma unroll
        for (int it = 0; it < 8; it++) {
            int t = tid + it * 256;
            int tile = t >> 10;
            int idx = t & 1023;
            int row = idx >> 3;
            int sg = idx & 7;
            const __half* src = tile ? (Bw + (size_t)(bn + row) * K + kk + sg * 8)
                                     : (A + (size_t)(bm + row) * K + kk + sg * 8);
            uint32_t dst = smem_to_u32(gsm + (size_t)(s * 2 + tile) * GST + row * SROW + sg * 8);
            cpasync16(dst, src);
        }
        CP_COMMIT();
    };

    load_chunk(0, 0);
    for (int ci = 0; ci < NC; ci++) {
        int s = ci & 1;
        if (ci + 1 < NC) { load_chunk(ci + 1, s ^ 1); CP_WAIT(1); }
        else CP_WAIT(0);
        __syncthreads();

        uint32_t a_base = smem_to_u32(gsm + (size_t)(s * 2 + 0) * GST);
        uint32_t b_base = smem_to_u32(gsm + (size_t)(s * 2 + 1) * GST);
#pragma unroll
        for (int k0 = 0; k0 < 64; k0 += 16) {
            uint32_t a[2][4];
#pragma unroll
            for (int im = 0; im < 2; im++) {
                uint32_t addr = a_base
                    + (uint32_t)(warp_m * 32 + im * 16 + (lane & 15)) * (SROW * 2)
                    + (uint32_t)(k0 + ((lane >> 4) << 3)) * 2;
                ldmx4(a[im], addr);
            }
            uint32_t bf[4][4];
#pragma unroll
            for (int ib = 0; ib < 4; ib++) {
                uint32_t addr = b_base
                    + (uint32_t)(warp_n * 64 + ib * 16 + (((lane >> 3) & 1) << 3) + (lane & 7)) * (SROW * 2)
                    + (uint32_t)(k0 + ((lane >> 4) << 3)) * 2;
                ldmx4(bf[ib], addr);
            }
#pragma unroll
            for (int im = 0; im < 2; im++)
#pragma unroll
                for (int in = 0; in < 8; in++) {
                    int ib = in >> 1, wh = in & 1;
                    mma16816h(c[im][in], a[im], bf[ib][wh], bf[ib][2 + wh]);
                }
        }
        __syncthreads();
    }

    int gp = lane >> 2, tg = lane & 3;
#pragma unroll
    for (int im = 0; im < 2; im++) {
        int m0 = bm + warp_m * 32 + im * 16;
#pragma unroll
        for (int in = 0; in < 8; in++) {
            int n = bn + warp_n * 64 + in * 8 + tg * 2;
            if (n >= Nstore) continue;
#pragma unroll
            for (int half = 0; half < 2; half++) {
                int m = m0 + gp + half * 8;
                float2 v;
                v.x = c[im][in][half * 2 + 0];
                v.y = c[im][in][half * 2 + 1];
                if (res) {
                    const float2 rv = *(const float2*)(res + (size_t)m * Nstore + n);
                    v.x += rv.x; v.y += rv.y;
                }
                *(float2*)(C + (size_t)m * Nstore + n) = v;
            }
        }
    }
}

// ----------------- exact fp32 dt GEMM: 64 blocks x 64 rows ------------------
#define DTS_X   0
#define DTS_W   (64 * 132)
#define DTSM_BYTES ((64 * 132 + 32 * 131) * 4)

__global__ __launch_bounds__(256) void dtfix_kernel(
    const float* __restrict__ x, const float* __restrict__ in_proj_w,
    const float* __restrict__ A_log, const float* __restrict__ dt_bias)
{
    extern __shared__ float dts[];
    float* sx = dts + DTS_X;
    float* sw = dts + DTS_W;
    int r0 = blockIdx.x * 64;
    int tid = threadIdx.x;
    int hg = tid & 7, rg = tid >> 3;
    int rr0 = rg * 2, hh0 = hg * 4;
    float acc[2][4];
#pragma unroll
    for (int i = 0; i < 2; i++)
#pragma unroll
        for (int j = 0; j < 4; j++) acc[i][j] = 0.f;

    for (int kc = 0; kc < 8; kc++) {
        int k0 = kc * 128;
        for (int t = tid; t < 2048; t += 256) {
            int r = t >> 5, q = (t & 31) * 4;
            float4 v = *(const float4*)(x + (size_t)(r0 + r) * DM + k0 + q);
            *(float4*)(sx + r * 132 + q) = v;
        }
        for (int t = tid; t < 1024; t += 256) {
            int r = t >> 5, q = (t & 31) * 4;
            float4 v = *(const float4*)(in_proj_w + (size_t)(DI + CONVD + r) * DM + k0 + q);
            sw[r * 131 + q + 0] = v.x; sw[r * 131 + q + 1] = v.y;
            sw[r * 131 + q + 2] = v.z; sw[r * 131 + q + 3] = v.w;
        }
        __syncthreads();
#pragma unroll 4
        for (int k = 0; k < 128; k++) {
            float x0 = sx[rr0 * 132 + k];
            float x1 = sx[(rr0 + 1) * 132 + k];
            float w0 = sw[(hh0 + 0) * 131 + k];
            float w1 = sw[(hh0 + 1) * 131 + k];
            float w2 = sw[(hh0 + 2) * 131 + k];
            float w3 = sw[(hh0 + 3) * 131 + k];
            acc[0][0] = fmaf(x0, w0, acc[0][0]);
            acc[0][1] = fmaf(x0, w1, acc[0][1]);
            acc[0][2] = fmaf(x0, w2, acc[0][2]);
            acc[0][3] = fmaf(x0, w3, acc[0][3]);
            acc[1][0] = fmaf(x1, w0, acc[1][0]);
            acc[1][1] = fmaf(x1, w1, acc[1][1]);
            acc[1][2] = fmaf(x1, w2, acc[1][2]);
            acc[1][3] = fmaf(x1, w3, acc[1][3]);
        }
        __syncthreads();
    }
#pragma unroll
    for (int i = 0; i < 2; i++) {
        int ml = r0 + rr0 + i;
#pragma unroll
        for (int j = 0; j < 4; j++) {
            int h = hh0 + j;
            float raw = acc[i][j] + dt_bias[h];
            float sp = (raw > 20.f) ? raw : log1pf(expf(raw));
            g_dt[ml * Hh + h] = sp;
            g_adt[ml * Hh + h] = -expf(A_log[h]) * sp;
        }
    }
}

// ------------- causal depthwise conv + double silu (smem-tiled) -------------
__device__ __forceinline__ float silu_f(float x) { return x / (1.f + expf(-x)); }

__global__ __launch_bounds__(256) void conv_kernel(const float* __restrict__ conv_w)
{
    __shared__ float sxm[35][132];
    int cc = blockIdx.x;
    int ytile = blockIdx.y;
    int b = ytile >> 6;
    int l0 = (ytile & 63) * 32;
    int tid = threadIdx.x;
    int ch_base = cc * 128;

    for (int t = tid; t < 35 * 32; t += 256) {
        int r = t >> 5, q = (t & 31) * 4;
        int ls = l0 - 3 + r;
        float4 v = make_float4(0.f, 0.f, 0.f, 0.f);
        if (ls >= 0 && r < 32 + 3)
            v = *(const float4*)(g_zxbcdt + ((size_t)(b * Lseq + ls)) * PROJ + DI + ch_base + q);
        *(float4*)(&sxm[r][q]) = v;
    }
    __syncthreads();

    int tx = tid & 31, ty = tid >> 5;
    int ch4 = tx * 4;
    float4 w0 = *(const float4*)(conv_w + (ch_base + ch4 + 0) * 4);
    float4 w1 = *(const float4*)(conv_w + (ch_base + ch4 + 1) * 4);
    float4 w2 = *(const float4*)(conv_w + (ch_base + ch4 + 2) * 4);
    float4 w3 = *(const float4*)(conv_w + (ch_base + ch4 + 3) * 4);
#pragma unroll
    for (int li = 0; li < 4; li++) {
        int lloc = ty * 4 + li;
        float a0 = 0.f, a1 = 0.f, a2 = 0.f, a3 = 0.f;
#pragma unroll
        for (int j = 0; j < 4; j++) {
            const float* row = &sxm[lloc + j][ch4];
            a0 = fmaf(row[0], (&w0.x)[j], a0);
            a1 = fmaf(row[1], (&w1.x)[j], a1);
            a2 = fmaf(row[2], (&w2.x)[j], a2);
            a3 = fmaf(row[3], (&w3.x)[j], a3);
        }
        float4 o;
        o.x = silu_f(silu_f(a0));
        o.y = silu_f(silu_f(a1));
        o.z = silu_f(silu_f(a2));
        o.w = silu_f(silu_f(a3));
        *(float4*)(g_xbc + (size_t)(b * Lseq + l0 + lloc) * CONVD + ch_base + ch4) = o;
    }
}

// ------------- G = C * B^T per (b,c), 4-way split over l --------------------
__global__ __launch_bounds__(256) void gmat_kernel()
{
    int c = blockIdx.x, b = blockIdx.y, z = blockIdx.z;
    __shared__ float sB[64][33];
    __shared__ float sC[16][33];
    int tid = threadIdx.x;
    int tx = tid & 15, ty = tid >> 4;
    int lloc = ty, s0 = tx * 4;
    size_t rowbase = (size_t)(b * Lseq + c * CHK);
    int lg = z * 16;
    float g4[4] = {0.f, 0.f, 0.f, 0.f};

    for (int nc = 0; nc < Nn; nc += 32) {
        for (int t = tid; t < 64 * 8; t += 256) {
            int l = t >> 3, q = (t & 7) * 4;
            float4 bv = *(const float4*)(g_xbc + (rowbase + l) * CONVD + DI + nc + q);
            sB[l][q + 0] = bv.x; sB[l][q + 1] = bv.y;
            sB[l][q + 2] = bv.z; sB[l][q + 3] = bv.w;
        }
        if (tid < 16 * 8) {
            int l = tid >> 3, q = (tid & 7) * 4;
            float4 cv = *(const float4*)(g_xbc + (rowbase + lg + l) * CONVD + DI + Nn + nc + q);
            sC[l][q + 0] = cv.x; sC[l][q + 1] = cv.y;
            sC[l][q + 2] = cv.z; sC[l][q + 3] = cv.w;
        }
        __syncthreads();
#pragma unroll
        for (int n = 0; n < 32; n++) {
            float cr = sC[lloc][n];
            g4[0] = fmaf(cr, sB[s0 + 0][n], g4[0]);
            g4[1] = fmaf(cr, sB[s0 + 1][n], g4[1]);
            g4[2] = fmaf(cr, sB[s0 + 2][n], g4[2]);
            g4[3] = fmaf(cr, sB[s0 + 3][n], g4[3]);
        }
        __syncthreads();
    }
    float* Gp = g_G + ((size_t)(b * NCHUNK + c)) * (CHK * CHK);
    float4 v = make_float4(g4[0], g4[1], g4[2], g4[3]);
    *(float4*)(Gp + (lg + lloc) * 64 + s0) = v;
}

// -------------- per-chunk SSD via tensor cores (fp16 mma) -------------------
// sX = X*dt (for Y_diag); sXd = X*dt*exp(alast-cs) (for states), built together.
__global__ __launch_bounds__(256) void chunk_kernel()
{
    __shared__ __half sM[64][72];
    __shared__ __half sX[64][72];
    __shared__ __half sXd[64][72];
    __shared__ __half sB[64][136];
    __shared__ float scs[64];
    int c = blockIdx.x, h = blockIdx.y, b = blockIdx.z;
    int tid = threadIdx.x, lane = tid & 31, wid = tid >> 5;
    size_t rowbase = (size_t)(b * Lseq + c * CHK);

    if (wid == 0) {
        float v0 = g_adt[(rowbase + lane) * Hh + h];
        float v1 = g_adt[(rowbase + 32 + lane) * Hh + h];
#pragma unroll
        for (int off = 1; off < 32; off <<= 1) {
            float t = __shfl_up_sync(0xFFFFFFFF, v0, off);
            if (lane >= off) v0 += t;
        }
        float tot = __shfl_sync(0xFFFFFFFF, v0, 31);
#pragma unroll
        for (int off = 1; off < 32; off <<= 1) {
            float t = __shfl_up_sync(0xFFFFFFFF, v1, off);
            if (lane >= off) v1 += t;
        }
        v1 += tot;
        scs[lane] = v0;
        scs[32 + lane] = v1;
    }
    // B tile (no scs dependency)
    for (int i = tid; i < 64 * 32; i += 256) {
        int l = i >> 5, q = (i & 31) * 4;
        float4 v = *(const float4*)(g_xbc + (rowbase + l) * CONVD + DI + q);
        sB[l][q + 0] = __float2half_rn(v.x);
        sB[l][q + 1] = __float2half_rn(v.y);
        sB[l][q + 2] = __float2half_rn(v.z);
        sB[l][q + 3] = __float2half_rn(v.w);
    }
    __syncthreads();   // scs ready

    float alast = scs[63];
    for (int i = tid; i < 64 * 16; i += 256) {
        int l = i >> 4, q = (i & 15) * 4;
        float4 v = *(const float4*)(g_xbc + (rowbase + l) * CONVD + h * 64 + q);
        float d = g_dt[(rowbase + l) * Hh + h];
        float e = expf(alast - scs[l]);
        float x0 = v.x * d, x1 = v.y * d, x2 = v.z * d, x3 = v.w * d;
        sX[l][q + 0] = __float2half_rn(x0);
        sX[l][q + 1] = __float2half_rn(x1);
        sX[l][q + 2] = __float2half_rn(x2);
        sX[l][q + 3] = __float2half_rn(x3);
        sXd[l][q + 0] = __float2half_rn(x0 * e);
        sXd[l][q + 1] = __float2half_rn(x1 * e);
        sXd[l][q + 2] = __float2half_rn(x2 * e);
        sXd[l][q + 3] = __float2half_rn(x3 * e);
    }
    {
        int tx = tid & 15, ty = tid >> 4;
        int l0 = ty * 4, s0 = tx * 4;
        const float* Gp = g_G + ((size_t)(b * NCHUNK + c)) * (CHK * CHK);
#pragma unroll
        for (int i = 0; i < 4; i++) {
            int l = l0 + i;
            float4 gv = *(const float4*)(Gp + l * 64 + s0);
            float csl = scs[l];
            sM[l][s0 + 0] = __float2half_rn((s0 + 0 <= l) ? gv.x * expf(csl - scs[s0 + 0]) : 0.f);
            sM[l][s0 + 1] = __float2half_rn((s0 + 1 <= l) ? gv.y * expf(csl - scs[s0 + 1]) : 0.f);
            sM[l][s0 + 2] = __float2half_rn((s0 + 2 <= l) ? gv.z * expf(csl - scs[s0 + 2]) : 0.f);
            sM[l][s0 + 3] = __float2half_rn((s0 + 3 <= l) ? gv.w * expf(csl - scs[s0 + 3]) : 0.f);
        }
    }
    __syncthreads();

    int gp = lane >> 2, tg = lane & 3;
    // matmul1: Y_diag = M @ X
    {
        int wm = wid & 3, wn = wid >> 2;
        float cy[4][4];
#pragma unroll
        for (int i = 0; i < 4; i++)
#pragma unroll
            for (int j = 0; j < 4; j++) cy[i][j] = 0.f;
#pragma unroll
        for (int k0 = 0; k0 < 64; k0 += 16) {
            uint32_t a[4];
            ldmx4(a, smem_to_u32(&sM[wm * 16 + (lane & 15)][k0 + ((lane >> 4) << 3)]));
#pragma unroll
            for (int g = 0; g < 2; g++) {
                uint32_t bf[4];
                ldmx4t(bf, smem_to_u32(&sX[k0 + (lane & 15)][wn * 32 + g * 16 + ((lane >> 4) << 3)]));
                mma16816h(cy[g * 2 + 0], a, bf[0], bf[1]);
                mma16816h(cy[g * 2 + 1], a, bf[2], bf[3]);
            }
        }
#pragma unroll
        for (int nb = 0; nb < 4; nb++) {
            int p = wn * 32 + nb * 8 + tg * 2;
#pragma unroll
            for (int hf = 0; hf < 2; hf++) {
                int l = wm * 16 + gp + hf * 8;
                float2 v = make_float2(cy[nb][hf * 2 + 0], cy[nb][hf * 2 + 1]);
                *(float2*)(g_Y + (rowbase + l) * DI + h * 64 + p) = v;
            }
        }
    }

    // matmul2: S = sXd^T @ B  (no barrier needed: sXd/sB written before last sync)
    {
        int pmw = wid & 3, nw = wid >> 2;
        int p0 = pmw * 16, n0 = nw * 64;
        float cs2[8][4];
#pragma unroll
        for (int i = 0; i < 8; i++)
#pragma unroll
            for (int j = 0; j < 4; j++) cs2[i][j] = 0.f;
#pragma unroll
        for (int k0 = 0; k0 < 64; k0 += 16) {
            uint32_t r[4];
            ldmx4t(r, smem_to_u32(&sXd[k0 + (lane & 15)][p0 + ((lane >> 4) << 3)]));
            uint32_t a[4] = {r[0], r[2], r[1], r[3]};
#pragma unroll
            for (int g = 0; g < 4; g++) {
                uint32_t bf[4];
                ldmx4t(bf, smem_to_u32(&sB[k0 + (lane & 15)][n0 + g * 16 + ((lane >> 4) << 3)]));
                mma16816h(cs2[g * 2 + 0], a, bf[0], bf[1]);
                mma16816h(cs2[g * 2 + 1], a, bf[2], bf[3]);
            }
        }
        size_t sbase = (((size_t)(b * NCHUNK + c)) * Hh + h) * (Pp * Nn);
#pragma unroll
        for (int nb = 0; nb < 8; nb++) {
            int n = n0 + nb * 8 + tg * 2;
#pragma unroll
            for (int hf = 0; hf < 2; hf++) {
                int p = p0 + gp + hf * 8;
                float2 v = make_float2(cs2[nb][hf * 2 + 0], cs2[nb][hf * 2 + 1]);
                *(float2*)(g_states + sbase + (size_t)p * Nn + n) = v;
            }
        }
    }

    if (tid < 64) g_cs[((b * NCHUNK + c) * Hh + h) * CHK + tid] = scs[tid];
    if (tid == 0) g_lastA[(b * NCHUNK + c) * Hh + h] = scs[63];
}

// ---------- inter-chunk scan, 8-way sliced, float4 ---------------------------
__global__ __launch_bounds__(256) void scan_kernel(const float* __restrict__ init_state,
                                                   float* __restrict__ fstate_out)
{
    int bh = blockIdx.x;
    int h = bh & (Hh - 1), b = bh >> 5;
    int off = blockIdx.y * 1024 + threadIdx.x * 4;
    size_t ibase = ((size_t)(b * Hh + h)) * (Pp * Nn);
    float4 run = *(const float4*)(init_state + ibase + off);
    for (int c = 0; c < NCHUNK; c++) {
        float dec = expf(g_lastA[(b * NCHUNK + c) * Hh + h]);
        size_t idx = (((size_t)(b * NCHUNK + c)) * Hh + h) * (Pp * Nn) + off;
        float4 v = *(const float4*)(g_states + idx);
        *(float4*)(g_states + idx) = run;
        run.x = fmaf(dec, run.x, v.x);
        run.y = fmaf(dec, run.y, v.y);
        run.z = fmaf(dec, run.z, v.z);
        run.w = fmaf(dec, run.w, v.w);
    }
    *(float4*)(fstate_out + ibase + off) = run;
}

// --------------- Y_off + D*X epilogue via tensor cores ----------------------
__global__ __launch_bounds__(256) void yoff_kernel(const float* __restrict__ D_param)
{
    __shared__ __half sC[64][136];
    __shared__ __half sS[64][136];
    __shared__ float scs[64];
    int c = blockIdx.x, h = blockIdx.y, b = blockIdx.z;
    int tid = threadIdx.x, lane = tid & 31, wid = tid >> 5;
    size_t rowbase = (size_t)(b * Lseq + c * CHK);
    if (tid < 64) scs[tid] = g_cs[((b * NCHUNK + c) * Hh + h) * CHK + tid];

    size_t sbase = (((size_t)(b * NCHUNK + c)) * Hh + h) * (Pp * Nn);
    for (int t = tid; t < 64 * 32; t += 256) {
        int r = t >> 5, q = (t & 31) * 4;
        float4 cv = *(const float4*)(g_xbc + (rowbase + r) * CONVD + DI + Nn + q);
        sC[r][q + 0] = __float2half_rn(cv.x);
        sC[r][q + 1] = __float2half_rn(cv.y);
        sC[r][q + 2] = __float2half_rn(cv.z);
        sC[r][q + 3] = __float2half_rn(cv.w);
        float4 sv = *(const float4*)(g_states + sbase + (size_t)r * Nn + q);
        sS[r][q + 0] = __float2half_rn(sv.x);
        sS[r][q + 1] = __float2half_rn(sv.y);
        sS[r][q + 2] = __float2half_rn(sv.z);
        sS[r][q + 3] = __float2half_rn(sv.w);
    }
    __syncthreads();

    int wm = wid & 3, wn = wid >> 2;
    int l0 = wm * 16, p0 = wn * 32;
    float acc[4][4];
#pragma unroll
    for (int i = 0; i < 4; i++)
#pragma unroll
        for (int j = 0; j < 4; j++) acc[i][j] = 0.f;

#pragma unroll
    for (int k0 = 0; k0 < Nn; k0 += 16) {
        uint32_t a[4];
        ldmx4(a, smem_to_u32(&sC[l0 + (lane & 15)][k0 + ((lane >> 4) << 3)]));
        uint32_t bf[2][4];
#pragma unroll
        for (int g = 0; g < 2; g++)
            ldmx4(bf[g], smem_to_u32(
                &sS[p0 + g * 16 + (((lane >> 3) & 1) << 3) + (lane & 7)][k0 + ((lane >> 4) << 3)]));
#pragma unroll
        for (int nb = 0; nb < 4; nb++) {
            int ib = nb >> 1, wh = nb & 1;
            mma16816h(acc[nb], a, bf[ib][wh], bf[ib][2 + wh]);
        }
    }
    float Dh = D_param[h];
    int gp = lane >> 2, tg = lane & 3;
#pragma unroll
    for (int nb = 0; nb < 4; nb++) {
        int p = p0 + nb * 8 + tg * 2;
#pragma unroll
        for (int hf = 0; hf < 2; hf++) {
            int l = l0 + gp + hf * 8;
            float e = expf(scs[l]);
            size_t gi = (rowbase + l) * DI + h * 64 + p;
            float2 yv = *(const float2*)(g_Y + gi);
            float2 xv = *(const float2*)(g_xbc + (rowbase + l) * CONVD + h * 64 + p);
            yv.x += e * acc[nb][hf * 2 + 0] + Dh * xv.x;
            yv.y += e * acc[nb][hf * 2 + 1] + Dh * xv.y;
            *(float2*)(g_Y + gi) = yv;
        }
    }
}

// -------- RMSNorm * norm_w * sigmoid(z) -> fp16 y_core directly --------------
__global__ __launch_bounds__(256) void rms_cvt_kernel(const float* __restrict__ norm_w)
{
    int row = blockIdx.x;
    int tid = threadIdx.x, lane = tid & 31, wid = tid >> 5;
    __shared__ float red[8];
    const float* y = g_Y + (size_t)row * DI;
    float ss = 0.f;
    for (int j = tid; j < DI; j += 256) { float v = y[j]; ss = fmaf(v, v, ss); }
#pragma unroll
    for (int off = 16; off > 0; off >>= 1) ss += __shfl_xor_sync(0xFFFFFFFF, ss, off);
    if (lane == 0) red[wid] = ss;
    __syncthreads();
    if (wid == 0) {
        float v = (lane < 8) ? red[lane] : 0.f;
#pragma unroll
        for (int off = 4; off > 0; off >>= 1) v += __shfl_xor_sync(0xFFFFFFFF, v, off);
        if (lane == 0) red[0] = v;
    }
    __syncthreads();
    float scale = rsqrtf(red[0] / (float)DI + EPSV);
    __half* ph = g_ych + (size_t)row * DI;
    for (int j = tid; j < DI; j += 256) {
        float z = g_zxbcdt[(size_t)row * PROJ + j];
        float sig = 1.f / (1.f + expf(-z));
        ph[j] = __float2half_rn(y[j] * scale * norm_w[j] * sig);
    }
}

// ------------------------- launch ------------------------------------------
extern "C" void kernel_launch(void* const* d_in, const int* in_sizes, int n_in,
                              void* d_out, int out_size)
{
    const float* x         = (const float*)d_in[0];
    const float* state     = (const float*)d_in[1];
    const float* in_proj_w = (const float*)d_in[2];
    const float* conv_w    = (const float*)d_in[3];
    const float* A_log     = (const float*)d_in[4];
    const float* dt_bias   = (const float*)d_in[5];
    const float* D_param   = (const float*)d_in[6];
    const float* norm_w    = (const float*)d_in[7];
    const float* out_proj_w= (const float*)d_in[8];
    float* out = (float*)d_out;

    float* zx;   cudaGetSymbolAddress((void**)&zx, g_zxbcdt);
    __half *xh, *wih, *ych, *woh;
    cudaGetSymbolAddress((void**)&xh, g_xh);
    cudaGetSymbolAddress((void**)&wih, g_wih);
    cudaGetSymbolAddress((void**)&ych, g_ych);
    cudaGetSymbolAddress((void**)&woh, g_woh);

    cudaFuncSetAttribute(gemm_fp16, cudaFuncAttributeMaxDynamicSharedMemorySize, GSMEM_BYTES);
    cudaFuncSetAttribute(dtfix_kernel, cudaFuncAttributeMaxDynamicSharedMemorySize, DTSM_BYTES);

    // 1) merged fp16 converts
    {
        size_t total = CVT_NX + CVT_NW + CVT_NWO;
        cvt_all_kernel<<<(unsigned)((total + 255) / 256), 256>>>(x, in_proj_w, out_proj_w);
    }
    // 2) in_proj GEMM (fp16, 128x128 tiles, BK=64)
    gemm_fp16<<<dim3(PROJPAD / 128, ML / 128), 256, GSMEM_BYTES>>>(
        xh, wih, nullptr, zx, DM, PROJ);
    // 3) exact fp32 dt
    dtfix_kernel<<<ML / 64, 256, DTSM_BYTES>>>(x, in_proj_w, A_log, dt_bias);
    // 4) conv + double silu (smem-tiled)
    conv_kernel<<<dim3(CONVD / 128, Bsz * (Lseq / 32)), 256>>>(conv_w);
    // 5) G = C B^T once per (b,c), 4-way l-split
    gmat_kernel<<<dim3(NCHUNK, Bsz, 4), 256>>>();
    // 6) per-chunk SSD (tensor cores, fused decayed-X buffer)
    chunk_kernel<<<dim3(NCHUNK, Hh, Bsz), 256>>>();
    // 7) inter-chunk scan + final state
    scan_kernel<<<dim3(Bsz * Hh, 8), 256>>>(state, out + (size_t)ML * DM);
    // 8) Y_off + D*X (tensor cores)
    yoff_kernel<<<dim3(NCHUNK, Hh, Bsz), 256>>>(D_param);
    // 9) RMSNorm + gate + fp16 convert
    rms_cvt_kernel<<<ML, 256>>>(norm_w);
    // 10) out_proj GEMM (fp16) + residual -> d_out
    gemm_fp16<<<dim3(DM / 128, ML / 128), 256, GSMEM_BYTES>>>(
        ych, woh, x, out, DI, DM);
}

// round 14
// speedup vs baseline: 1.1388x; 1.0934x over previous
#include <cuda_runtime.h>
#include <cuda_bf16.h>
#include <cuda_fp16.h>
#include <cstdint>

// Problem constants
#define Bsz 2
#define Lseq 2048
#define DM 1024
#define DI 2048          // d_inner
#define Hh 32            // heads
#define Pp 64            // headdim
#define Nn 128           // d_state
#define CONVD 2304       // conv_dim = d_inner + 2*N
#define PROJ 4384        // 2*DI + 2*N + H
#define PROJPAD 4480     // 35*128
#define CHK 64           // block_len
#define NCHUNK 32        // L / CHK
#define ML (Bsz*Lseq)    // 4096 rows
#define EPSV 1.1920929e-07f

// ------------------------- scratch (device globals) -------------------------
__device__ float g_zxbcdt[(size_t)ML * PROJ];
__device__ float g_xbc[(size_t)ML * CONVD];
__device__ float g_dt[(size_t)ML * Hh];
__device__ float g_adt[(size_t)ML * Hh];
__device__ float g_Y[(size_t)ML * DI];
__device__ float g_states[(size_t)Bsz * NCHUNK * Hh * Pp * Nn];
__device__ float g_lastA[Bsz * NCHUNK * Hh];           // stores exp(lastA)
__device__ float g_cs[Bsz * NCHUNK * Hh * CHK];        // stores exp(cs)
__device__ float g_G[(size_t)Bsz * NCHUNK * CHK * CHK];

// fp16 buffers
__device__ __half g_xh[(size_t)ML * DM];
__device__ __half g_wih[(size_t)PROJPAD * DM];
__device__ __half g_ych[(size_t)ML * DI];
__device__ __half g_woh[(size_t)DM * DI];

// ------------------------- helpers ------------------------------------------
__device__ __forceinline__ uint32_t smem_to_u32(const void* p) {
    uint32_t a;
    asm("{ .reg .u64 t; cvta.to.shared.u64 t, %1; cvt.u32.u64 %0, t; }" : "=r"(a) : "l"(p));
    return a;
}
__device__ __forceinline__ void ldmx4(uint32_t* r, uint32_t addr) {
    asm volatile("ldmatrix.sync.aligned.m8n8.x4.shared.b16 {%0,%1,%2,%3}, [%4];"
                 : "=r"(r[0]), "=r"(r[1]), "=r"(r[2]), "=r"(r[3]) : "r"(addr));
}
__device__ __forceinline__ void ldmx4t(uint32_t* r, uint32_t addr) {
    asm volatile("ldmatrix.sync.aligned.m8n8.x4.trans.shared.b16 {%0,%1,%2,%3}, [%4];"
                 : "=r"(r[0]), "=r"(r[1]), "=r"(r[2]), "=r"(r[3]) : "r"(addr));
}
__device__ __forceinline__ void mma16816h(float* c, const uint32_t* a,
                                          uint32_t b0, uint32_t b1) {
    asm volatile("mma.sync.aligned.m16n8k16.row.col.f32.f16.f16.f32 "
                 "{%0,%1,%2,%3}, {%4,%5,%6,%7}, {%8,%9}, {%0,%1,%2,%3};"
                 : "+f"(c[0]), "+f"(c[1]), "+f"(c[2]), "+f"(c[3])
                 : "r"(a[0]), "r"(a[1]), "r"(a[2]), "r"(a[3]), "r"(b0), "r"(b1));
}
__device__ __forceinline__ void cpasync16(uint32_t dst, const void* src) {
    asm volatile("cp.async.cg.shared.global [%0], [%1], 16;" :: "r"(dst), "l"(src));
}
#define CP_COMMIT() asm volatile("cp.async.commit_group;" ::: "memory")
#define CP_WAIT(n)  asm volatile("cp.async.wait_group %0;" :: "n"(n) : "memory")

// ------------------- merged fp16 convert (x, W_in pad, W_out) ---------------
#define CVT_NX  ((size_t)ML * DM)
#define CVT_NW  ((size_t)PROJPAD * DM)
#define CVT_NWO ((size_t)DM * DI)
__global__ void cvt_all_kernel(const float* __restrict__ x,
                               const float* __restrict__ w_in,
                               const float* __restrict__ w_out)
{
    size_t i = (size_t)blockIdx.x * blockDim.x + threadIdx.x;
    if (i < CVT_NX) {
        g_xh[i] = __float2half_rn(x[i]);
    } else if (i < CVT_NX + CVT_NW) {
        size_t j = i - CVT_NX;
        int r = (int)(j / DM);
        g_wih[j] = __float2half_rn((r < PROJ) ? w_in[j] : 0.f);
    } else if (i < CVT_NX + CVT_NW + CVT_NWO) {
        size_t j = i - CVT_NX - CVT_NW;
        g_woh[j] = __float2half_rn(w_out[j]);
    }
}

// ------------------------- fp16 mma.sync GEMM (128x128 tile, BK=64) ----------
#define SROW 72             // 64 fp16 + 8 pad
#define GST  (128 * SROW)
#define GSMEM_BYTES (2 * 2 * GST * 2)

__global__ __launch_bounds__(256) void gemm_fp16(
    const __half* __restrict__ A, const __half* __restrict__ Bw,
    const float* __restrict__ res, float* __restrict__ C,
    int K, int Nstore)
{
    extern __shared__ __align__(16) __half gsm[];
    int tid = threadIdx.x;
    int lane = tid & 31, wid = tid >> 5;
    int warp_m = wid >> 1, warp_n = wid & 1;
    int bn = blockIdx.x * 128;
    int bm = blockIdx.y * 128;

    int NC = K >> 6;

    float c[2][8][4];
#pragma unroll
    for (int i = 0; i < 2; i++)
#pragma unroll
        for (int j = 0; j < 8; j++)
#pragma unroll
            for (int q = 0; q < 4; q++) c[i][j][q] = 0.f;

    auto load_chunk = [&](int ci, int s) {
        int kk = ci * 64;
#pragma unroll
        for (int it = 0; it < 8; it++) {
            int t = tid + it * 256;
            int tile = t >> 10;
            int idx = t & 1023;
            int row = idx >> 3;
            int sg = idx & 7;
            const __half* src = tile ? (Bw + (size_t)(bn + row) * K + kk + sg * 8)
                                     : (A + (size_t)(bm + row) * K + kk + sg * 8);
            uint32_t dst = smem_to_u32(gsm + (size_t)(s * 2 + tile) * GST + row * SROW + sg * 8);
            cpasync16(dst, src);
        }
        CP_COMMIT();
    };

    load_chunk(0, 0);
    for (int ci = 0; ci < NC; ci++) {
        int s = ci & 1;
        if (ci + 1 < NC) { load_chunk(ci + 1, s ^ 1); CP_WAIT(1); }
        else CP_WAIT(0);
        __syncthreads();

        uint32_t a_base = smem_to_u32(gsm + (size_t)(s * 2 + 0) * GST);
        uint32_t b_base = smem_to_u32(gsm + (size_t)(s * 2 + 1) * GST);
#pragma unroll
        for (int k0 = 0; k0 < 64; k0 += 16) {
            uint32_t a[2][4];
#pragma unroll
            for (int im = 0; im < 2; im++) {
                uint32_t addr = a_base
                    + (uint32_t)(warp_m * 32 + im * 16 + (lane & 15)) * (SROW * 2)
                    + (uint32_t)(k0 + ((lane >> 4) << 3)) * 2;
                ldmx4(a[im], addr);
            }
            uint32_t bf[4][4];
#pragma unroll
            for (int ib = 0; ib < 4; ib++) {
                uint32_t addr = b_base
                    + (uint32_t)(warp_n * 64 + ib * 16 + (((lane >> 3) & 1) << 3) + (lane & 7)) * (SROW * 2)
                    + (uint32_t)(k0 + ((lane >> 4) << 3)) * 2;
                ldmx4(bf[ib], addr);
            }
#pragma unroll
            for (int im = 0; im < 2; im++)
#pragma unroll
                for (int in = 0; in < 8; in++) {
                    int ib = in >> 1, wh = in & 1;
                    mma16816h(c[im][in], a[im], bf[ib][wh], bf[ib][2 + wh]);
                }
        }
        __syncthreads();
    }

    int gp = lane >> 2, tg = lane & 3;
#pragma unroll
    for (int im = 0; im < 2; im++) {
        int m0 = bm + warp_m * 32 + im * 16;
#pragma unroll
        for (int in = 0; in < 8; in++) {
            int n = bn + warp_n * 64 + in * 8 + tg * 2;
            if (n >= Nstore) continue;
#pragma unroll
            for (int half = 0; half < 2; half++) {
                int m = m0 + gp + half * 8;
                float2 v;
                v.x = c[im][in][half * 2 + 0];
                v.y = c[im][in][half * 2 + 1];
                if (res) {
                    const float2 rv = *(const float2*)(res + (size_t)m * Nstore + n);
                    v.x += rv.x; v.y += rv.y;
                }
                *(float2*)(C + (size_t)m * Nstore + n) = v;
            }
        }
    }
}

// ----------------- exact fp32 dt GEMM: 64 blocks x 64 rows ------------------
#define DTS_X   0
#define DTS_W   (64 * 132)
#define DTSM_BYTES ((64 * 132 + 32 * 131) * 4)

__global__ __launch_bounds__(256) void dtfix_kernel(
    const float* __restrict__ x, const float* __restrict__ in_proj_w,
    const float* __restrict__ A_log, const float* __restrict__ dt_bias)
{
    extern __shared__ float dts[];
    float* sx = dts + DTS_X;
    float* sw = dts + DTS_W;
    int r0 = blockIdx.x * 64;
    int tid = threadIdx.x;
    int hg = tid & 7, rg = tid >> 3;
    int rr0 = rg * 2, hh0 = hg * 4;
    float acc[2][4];
#pragma unroll
    for (int i = 0; i < 2; i++)
#pragma unroll
        for (int j = 0; j < 4; j++) acc[i][j] = 0.f;

    for (int kc = 0; kc < 8; kc++) {
        int k0 = kc * 128;
        for (int t = tid; t < 2048; t += 256) {
            int r = t >> 5, q = (t & 31) * 4;
            float4 v = *(const float4*)(x + (size_t)(r0 + r) * DM + k0 + q);
            *(float4*)(sx + r * 132 + q) = v;
        }
        for (int t = tid; t < 1024; t += 256) {
            int r = t >> 5, q = (t & 31) * 4;
            float4 v = *(const float4*)(in_proj_w + (size_t)(DI + CONVD + r) * DM + k0 + q);
            sw[r * 131 + q + 0] = v.x; sw[r * 131 + q + 1] = v.y;
            sw[r * 131 + q + 2] = v.z; sw[r * 131 + q + 3] = v.w;
        }
        __syncthreads();
#pragma unroll 4
        for (int k = 0; k < 128; k++) {
            float x0 = sx[rr0 * 132 + k];
            float x1 = sx[(rr0 + 1) * 132 + k];
            float w0 = sw[(hh0 + 0) * 131 + k];
            float w1 = sw[(hh0 + 1) * 131 + k];
            float w2 = sw[(hh0 + 2) * 131 + k];
            float w3 = sw[(hh0 + 3) * 131 + k];
            acc[0][0] = fmaf(x0, w0, acc[0][0]);
            acc[0][1] = fmaf(x0, w1, acc[0][1]);
            acc[0][2] = fmaf(x0, w2, acc[0][2]);
            acc[0][3] = fmaf(x0, w3, acc[0][3]);
            acc[1][0] = fmaf(x1, w0, acc[1][0]);
            acc[1][1] = fmaf(x1, w1, acc[1][1]);
            acc[1][2] = fmaf(x1, w2, acc[1][2]);
            acc[1][3] = fmaf(x1, w3, acc[1][3]);
        }
        __syncthreads();
    }
#pragma unroll
    for (int i = 0; i < 2; i++) {
        int ml = r0 + rr0 + i;
#pragma unroll
        for (int j = 0; j < 4; j++) {
            int h = hh0 + j;
            float raw = acc[i][j] + dt_bias[h];
            float sp = (raw > 20.f) ? raw : log1pf(expf(raw));
            g_dt[ml * Hh + h] = sp;
            g_adt[ml * Hh + h] = -expf(A_log[h]) * sp;
        }
    }
}

// ------------- causal depthwise conv + double silu (smem-tiled) -------------
__device__ __forceinline__ float silu_f(float x) { return x / (1.f + expf(-x)); }

__global__ __launch_bounds__(256) void conv_kernel(const float* __restrict__ conv_w)
{
    __shared__ float sxm[35][132];
    int cc = blockIdx.x;
    int ytile = blockIdx.y;
    int b = ytile >> 6;
    int l0 = (ytile & 63) * 32;
    int tid = threadIdx.x;
    int ch_base = cc * 128;

    for (int t = tid; t < 35 * 32; t += 256) {
        int r = t >> 5, q = (t & 31) * 4;
        int ls = l0 - 3 + r;
        float4 v = make_float4(0.f, 0.f, 0.f, 0.f);
        if (ls >= 0 && r < 32 + 3)
            v = *(const float4*)(g_zxbcdt + ((size_t)(b * Lseq + ls)) * PROJ + DI + ch_base + q);
        *(float4*)(&sxm[r][q]) = v;
    }
    __syncthreads();

    int tx = tid & 31, ty = tid >> 5;
    int ch4 = tx * 4;
    float4 w0 = *(const float4*)(conv_w + (ch_base + ch4 + 0) * 4);
    float4 w1 = *(const float4*)(conv_w + (ch_base + ch4 + 1) * 4);
    float4 w2 = *(const float4*)(conv_w + (ch_base + ch4 + 2) * 4);
    float4 w3 = *(const float4*)(conv_w + (ch_base + ch4 + 3) * 4);
#pragma unroll
    for (int li = 0; li < 4; li++) {
        int lloc = ty * 4 + li;
        float a0 = 0.f, a1 = 0.f, a2 = 0.f, a3 = 0.f;
#pragma unroll
        for (int j = 0; j < 4; j++) {
            const float* row = &sxm[lloc + j][ch4];
            a0 = fmaf(row[0], (&w0.x)[j], a0);
            a1 = fmaf(row[1], (&w1.x)[j], a1);
            a2 = fmaf(row[2], (&w2.x)[j], a2);
            a3 = fmaf(row[3], (&w3.x)[j], a3);
        }
        float4 o;
        o.x = silu_f(silu_f(a0));
        o.y = silu_f(silu_f(a1));
        o.z = silu_f(silu_f(a2));
        o.w = silu_f(silu_f(a3));
        *(float4*)(g_xbc + (size_t)(b * Lseq + l0 + lloc) * CONVD + ch_base + ch4) = o;
    }
}

// ------------- G = C * B^T per (b,c), 4-way split over l --------------------
__global__ __launch_bounds__(256) void gmat_kernel()
{
    int c = blockIdx.x, b = blockIdx.y, z = blockIdx.z;
    __shared__ float sB[64][33];
    __shared__ float sC[16][33];
    int tid = threadIdx.x;
    int tx = tid & 15, ty = tid >> 4;
    int lloc = ty, s0 = tx * 4;
    size_t rowbase = (size_t)(b * Lseq + c * CHK);
    int lg = z * 16;
    float g4[4] = {0.f, 0.f, 0.f, 0.f};

    for (int nc = 0; nc < Nn; nc += 32) {
        for (int t = tid; t < 64 * 8; t += 256) {
            int l = t >> 3, q = (t & 7) * 4;
            float4 bv = *(const float4*)(g_xbc + (rowbase + l) * CONVD + DI + nc + q);
            sB[l][q + 0] = bv.x; sB[l][q + 1] = bv.y;
            sB[l][q + 2] = bv.z; sB[l][q + 3] = bv.w;
        }
        if (tid < 16 * 8) {
            int l = tid >> 3, q = (tid & 7) * 4;
            float4 cv = *(const float4*)(g_xbc + (rowbase + lg + l) * CONVD + DI + Nn + nc + q);
            sC[l][q + 0] = cv.x; sC[l][q + 1] = cv.y;
            sC[l][q + 2] = cv.z; sC[l][q + 3] = cv.w;
        }
        __syncthreads();
#pragma unroll
        for (int n = 0; n < 32; n++) {
            float cr = sC[lloc][n];
            g4[0] = fmaf(cr, sB[s0 + 0][n], g4[0]);
            g4[1] = fmaf(cr, sB[s0 + 1][n], g4[1]);
            g4[2] = fmaf(cr, sB[s0 + 2][n], g4[2]);
            g4[3] = fmaf(cr, sB[s0 + 3][n], g4[3]);
        }
        __syncthreads();
    }
    float* Gp = g_G + ((size_t)(b * NCHUNK + c)) * (CHK * CHK);
    float4 v = make_float4(g4[0], g4[1], g4[2], g4[3]);
    *(float4*)(Gp + (lg + lloc) * 64 + s0) = v;
}

// -------------- per-chunk SSD via tensor cores (fp16 mma) -------------------
__global__ __launch_bounds__(256) void chunk_kernel()
{
    __shared__ __half sM[64][72];
    __shared__ __half sX[64][72];
    __shared__ __half sXd[64][72];
    __shared__ __half sB[64][136];
    __shared__ float scs[64];
    __shared__ float sDec[64];
    int c = blockIdx.x, h = blockIdx.y, b = blockIdx.z;
    int tid = threadIdx.x, lane = tid & 31, wid = tid >> 5;
    size_t rowbase = (size_t)(b * Lseq + c * CHK);

    if (wid == 0) {
        float v0 = g_adt[(rowbase + lane) * Hh + h];
        float v1 = g_adt[(rowbase + 32 + lane) * Hh + h];
#pragma unroll
        for (int off = 1; off < 32; off <<= 1) {
            float t = __shfl_up_sync(0xFFFFFFFF, v0, off);
            if (lane >= off) v0 += t;
        }
        float tot = __shfl_sync(0xFFFFFFFF, v0, 31);
#pragma unroll
        for (int off = 1; off < 32; off <<= 1) {
            float t = __shfl_up_sync(0xFFFFFFFF, v1, off);
            if (lane >= off) v1 += t;
        }
        v1 += tot;
        float alast = __shfl_sync(0xFFFFFFFF, v1, 31);
        scs[lane] = v0;
        scs[32 + lane] = v1;
        sDec[lane] = expf(alast - v0);
        sDec[32 + lane] = expf(alast - v1);
    }
    // B tile (no scs dependency)
    for (int i = tid; i < 64 * 32; i += 256) {
        int l = i >> 5, q = (i & 31) * 4;
        float4 v = *(const float4*)(g_xbc + (rowbase + l) * CONVD + DI + q);
        sB[l][q + 0] = __float2half_rn(v.x);
        sB[l][q + 1] = __float2half_rn(v.y);
        sB[l][q + 2] = __float2half_rn(v.z);
        sB[l][q + 3] = __float2half_rn(v.w);
    }
    __syncthreads();   // scs/sDec ready

    for (int i = tid; i < 64 * 16; i += 256) {
        int l = i >> 4, q = (i & 15) * 4;
        float4 v = *(const float4*)(g_xbc + (rowbase + l) * CONVD + h * 64 + q);
        float d = g_dt[(rowbase + l) * Hh + h];
        float e = sDec[l];
        float x0 = v.x * d, x1 = v.y * d, x2 = v.z * d, x3 = v.w * d;
        sX[l][q + 0] = __float2half_rn(x0);
        sX[l][q + 1] = __float2half_rn(x1);
        sX[l][q + 2] = __float2half_rn(x2);
        sX[l][q + 3] = __float2half_rn(x3);
        sXd[l][q + 0] = __float2half_rn(x0 * e);
        sXd[l][q + 1] = __float2half_rn(x1 * e);
        sXd[l][q + 2] = __float2half_rn(x2 * e);
        sXd[l][q + 3] = __float2half_rn(x3 * e);
    }
    {
        int tx = tid & 15, ty = tid >> 4;
        int l0 = ty * 4, s0 = tx * 4;
        const float* Gp = g_G + ((size_t)(b * NCHUNK + c)) * (CHK * CHK);
#pragma unroll
        for (int i = 0; i < 4; i++) {
            int l = l0 + i;
            if (s0 > l) {
                // fully above diagonal: zeros, no exp
                sM[l][s0 + 0] = __float2half_rn(0.f);
                sM[l][s0 + 1] = __float2half_rn(0.f);
                sM[l][s0 + 2] = __float2half_rn(0.f);
                sM[l][s0 + 3] = __float2half_rn(0.f);
            } else {
                float4 gv = *(const float4*)(Gp + l * 64 + s0);
                float csl = scs[l];
                if (s0 + 3 <= l) {
                    sM[l][s0 + 0] = __float2half_rn(gv.x * expf(csl - scs[s0 + 0]));
                    sM[l][s0 + 1] = __float2half_rn(gv.y * expf(csl - scs[s0 + 1]));
                    sM[l][s0 + 2] = __float2half_rn(gv.z * expf(csl - scs[s0 + 2]));
                    sM[l][s0 + 3] = __float2half_rn(gv.w * expf(csl - scs[s0 + 3]));
                } else {
                    sM[l][s0 + 0] = __float2half_rn((s0 + 0 <= l) ? gv.x * expf(csl - scs[s0 + 0]) : 0.f);
                    sM[l][s0 + 1] = __float2half_rn((s0 + 1 <= l) ? gv.y * expf(csl - scs[s0 + 1]) : 0.f);
                    sM[l][s0 + 2] = __float2half_rn((s0 + 2 <= l) ? gv.z * expf(csl - scs[s0 + 2]) : 0.f);
                    sM[l][s0 + 3] = __float2half_rn((s0 + 3 <= l) ? gv.w * expf(csl - scs[s0 + 3]) : 0.f);
                }
            }
        }
    }
    __syncthreads();

    int gp = lane >> 2, tg = lane & 3;
    // matmul1: Y_diag = M @ X
    {
        int wm = wid & 3, wn = wid >> 2;
        float cy[4][4];
#pragma unroll
        for (int i = 0; i < 4; i++)
#pragma unroll
            for (int j = 0; j < 4; j++) cy[i][j] = 0.f;
#pragma unroll
        for (int k0 = 0; k0 < 64; k0 += 16) {
            uint32_t a[4];
            ldmx4(a, smem_to_u32(&sM[wm * 16 + (lane & 15)][k0 + ((lane >> 4) << 3)]));
#pragma unroll
            for (int g = 0; g < 2; g++) {
                uint32_t bf[4];
                ldmx4t(bf, smem_to_u32(&sX[k0 + (lane & 15)][wn * 32 + g * 16 + ((lane >> 4) << 3)]));
                mma16816h(cy[g * 2 + 0], a, bf[0], bf[1]);
                mma16816h(cy[g * 2 + 1], a, bf[2], bf[3]);
            }
        }
#pragma unroll
        for (int nb = 0; nb < 4; nb++) {
            int p = wn * 32 + nb * 8 + tg * 2;
#pragma unroll
            for (int hf = 0; hf < 2; hf++) {
                int l = wm * 16 + gp + hf * 8;
                float2 v = make_float2(cy[nb][hf * 2 + 0], cy[nb][hf * 2 + 1]);
                *(float2*)(g_Y + (rowbase + l) * DI + h * 64 + p) = v;
            }
        }
    }

    // matmul2: S = sXd^T @ B
    {
        int pmw = wid & 3, nw = wid >> 2;
        int p0 = pmw * 16, n0 = nw * 64;
        float cs2[8][4];
#pragma unroll
        for (int i = 0; i < 8; i++)
#pragma unroll
            for (int j = 0; j < 4; j++) cs2[i][j] = 0.f;
#pragma unroll
        for (int k0 = 0; k0 < 64; k0 += 16) {
            uint32_t r[4];
            ldmx4t(r, smem_to_u32(&sXd[k0 + (lane & 15)][p0 + ((lane >> 4) << 3)]));
            uint32_t a[4] = {r[0], r[2], r[1], r[3]};
#pragma unroll
            for (int g = 0; g < 4; g++) {
                uint32_t bf[4];
                ldmx4t(bf, smem_to_u32(&sB[k0 + (lane & 15)][n0 + g * 16 + ((lane >> 4) << 3)]));
                mma16816h(cs2[g * 2 + 0], a, bf[0], bf[1]);
                mma16816h(cs2[g * 2 + 1], a, bf[2], bf[3]);
            }
        }
        size_t sbase = (((size_t)(b * NCHUNK + c)) * Hh + h) * (Pp * Nn);
#pragma unroll
        for (int nb = 0; nb < 8; nb++) {
            int n = n0 + nb * 8 + tg * 2;
#pragma unroll
            for (int hf = 0; hf < 2; hf++) {
                int p = p0 + gp + hf * 8;
                float2 v = make_float2(cs2[nb][hf * 2 + 0], cs2[nb][hf * 2 + 1]);
                *(float2*)(g_states + sbase + (size_t)p * Nn + n) = v;
            }
        }
    }

    if (tid < 64) g_cs[((b * NCHUNK + c) * Hh + h) * CHK + tid] = expf(scs[tid]);
    if (tid == 0) g_lastA[(b * NCHUNK + c) * Hh + h] = expf(scs[63]);
}

// ---------- inter-chunk scan, 8-way sliced, float4 (dec pre-exp'd) ----------
__global__ __launch_bounds__(256) void scan_kernel(const float* __restrict__ init_state,
                                                   float* __restrict__ fstate_out)
{
    int bh = blockIdx.x;
    int h = bh & (Hh - 1), b = bh >> 5;
    int off = blockIdx.y * 1024 + threadIdx.x * 4;
    size_t ibase = ((size_t)(b * Hh + h)) * (Pp * Nn);
    float4 run = *(const float4*)(init_state + ibase + off);
    for (int c = 0; c < NCHUNK; c++) {
        float dec = g_lastA[(b * NCHUNK + c) * Hh + h];
        size_t idx = (((size_t)(b * NCHUNK + c)) * Hh + h) * (Pp * Nn) + off;
        float4 v = *(const float4*)(g_states + idx);
        *(float4*)(g_states + idx) = run;
        run.x = fmaf(dec, run.x, v.x);
        run.y = fmaf(dec, run.y, v.y);
        run.z = fmaf(dec, run.z, v.z);
        run.w = fmaf(dec, run.w, v.w);
    }
    *(float4*)(fstate_out + ibase + off) = run;
}

// --------------- Y_off + D*X epilogue via tensor cores (cs pre-exp'd) -------
__global__ __launch_bounds__(256) void yoff_kernel(const float* __restrict__ D_param)
{
    __shared__ __half sC[64][136];
    __shared__ __half sS[64][136];
    __shared__ float scs[64];
    int c = blockIdx.x, h = blockIdx.y, b = blockIdx.z;
    int tid = threadIdx.x, lane = tid & 31, wid = tid >> 5;
    size_t rowbase = (size_t)(b * Lseq + c * CHK);
    if (tid < 64) scs[tid] = g_cs[((b * NCHUNK + c) * Hh + h) * CHK + tid];

    size_t sbase = (((size_t)(b * NCHUNK + c)) * Hh + h) * (Pp * Nn);
    for (int t = tid; t < 64 * 32; t += 256) {
        int r = t >> 5, q = (t & 31) * 4;
        float4 cv = *(const float4*)(g_xbc + (rowbase + r) * CONVD + DI + Nn + q);
        sC[r][q + 0] = __float2half_rn(cv.x);
        sC[r][q + 1] = __float2half_rn(cv.y);
        sC[r][q + 2] = __float2half_rn(cv.z);
        sC[r][q + 3] = __float2half_rn(cv.w);
        float4 sv = *(const float4*)(g_states + sbase + (size_t)r * Nn + q);
        sS[r][q + 0] = __float2half_rn(sv.x);
        sS[r][q + 1] = __float2half_rn(sv.y);
        sS[r][q + 2] = __float2half_rn(sv.z);
        sS[r][q + 3] = __float2half_rn(sv.w);
    }
    __syncthreads();

    int wm = wid & 3, wn = wid >> 2;
    int l0 = wm * 16, p0 = wn * 32;
    float acc[4][4];
#pragma unroll
    for (int i = 0; i < 4; i++)
#pragma unroll
        for (int j = 0; j < 4; j++) acc[i][j] = 0.f;

#pragma unroll
    for (int k0 = 0; k0 < Nn; k0 += 16) {
        uint32_t a[4];
        ldmx4(a, smem_to_u32(&sC[l0 + (lane & 15)][k0 + ((lane >> 4) << 3)]));
        uint32_t bf[2][4];
#pragma unroll
        for (int g = 0; g < 2; g++)
            ldmx4(bf[g], smem_to_u32(
                &sS[p0 + g * 16 + (((lane >> 3) & 1) << 3) + (lane & 7)][k0 + ((lane >> 4) << 3)]));
#pragma unroll
        for (int nb = 0; nb < 4; nb++) {
            int ib = nb >> 1, wh = nb & 1;
            mma16816h(acc[nb], a, bf[ib][wh], bf[ib][2 + wh]);
        }
    }
    float Dh = D_param[h];
    int gp = lane >> 2, tg = lane & 3;
#pragma unroll
    for (int nb = 0; nb < 4; nb++) {
        int p = p0 + nb * 8 + tg * 2;
#pragma unroll
        for (int hf = 0; hf < 2; hf++) {
            int l = l0 + gp + hf * 8;
            float e = scs[l];   // exp(cs_l), precomputed
            size_t gi = (rowbase + l) * DI + h * 64 + p;
            float2 yv = *(const float2*)(g_Y + gi);
            float2 xv = *(const float2*)(g_xbc + (rowbase + l) * CONVD + h * 64 + p);
            yv.x += e * acc[nb][hf * 2 + 0] + Dh * xv.x;
            yv.y += e * acc[nb][hf * 2 + 1] + Dh * xv.y;
            *(float2*)(g_Y + gi) = yv;
        }
    }
}

// -------- RMSNorm * norm_w * sigmoid(z) -> fp16 y_core (float4) --------------
__global__ __launch_bounds__(256) void rms_cvt_kernel(const float* __restrict__ norm_w)
{
    int row = blockIdx.x;
    int tid = threadIdx.x, lane = tid & 31, wid = tid >> 5;
    __shared__ float red[8];
    const float* y = g_Y + (size_t)row * DI;
    float ss = 0.f;
#pragma unroll
    for (int it = 0; it < 2; it++) {
        int j = (tid + it * 256) * 4;
        float4 v = *(const float4*)(y + j);
        ss = fmaf(v.x, v.x, ss);
        ss = fmaf(v.y, v.y, ss);
        ss = fmaf(v.z, v.z, ss);
        ss = fmaf(v.w, v.w, ss);
    }
#pragma unroll
    for (int off = 16; off > 0; off >>= 1) ss += __shfl_xor_sync(0xFFFFFFFF, ss, off);
    if (lane == 0) red[wid] = ss;
    __syncthreads();
    if (wid == 0) {
        float v = (lane < 8) ? red[lane] : 0.f;
#pragma unroll
        for (int off = 4; off > 0; off >>= 1) v += __shfl_xor_sync(0xFFFFFFFF, v, off);
        if (lane == 0) red[0] = v;
    }
    __syncthreads();
    float scale = rsqrtf(red[0] / (float)DI + EPSV);
    __half* ph = g_ych + (size_t)row * DI;
#pragma unroll
    for (int it = 0; it < 2; it++) {
        int j = (tid + it * 256) * 4;
        float4 yv = *(const float4*)(y + j);
        float4 zv = *(const float4*)(g_zxbcdt + (size_t)row * PROJ + j);
        __half2 h0, h1;
        h0.x = __float2half_rn(yv.x * scale * norm_w[j + 0] / (1.f + expf(-zv.x)));
        h0.y = __float2half_rn(yv.y * scale * norm_w[j + 1] / (1.f + expf(-zv.y)));
        h1.x = __float2half_rn(yv.z * scale * norm_w[j + 2] / (1.f + expf(-zv.z)));
        h1.y = __float2half_rn(yv.w * scale * norm_w[j + 3] / (1.f + expf(-zv.w)));
        *(__half2*)(ph + j) = h0;
        *(__half2*)(ph + j + 2) = h1;
    }
}

// ------------------------- launch ------------------------------------------
extern "C" void kernel_launch(void* const* d_in, const int* in_sizes, int n_in,
                              void* d_out, int out_size)
{
    const float* x         = (const float*)d_in[0];
    const float* state     = (const float*)d_in[1];
    const float* in_proj_w = (const float*)d_in[2];
    const float* conv_w    = (const float*)d_in[3];
    const float* A_log     = (const float*)d_in[4];
    const float* dt_bias   = (const float*)d_in[5];
    const float* D_param   = (const float*)d_in[6];
    const float* norm_w    = (const float*)d_in[7];
    const float* out_proj_w= (const float*)d_in[8];
    float* out = (float*)d_out;

    float* zx;   cudaGetSymbolAddress((void**)&zx, g_zxbcdt);
    __half *xh, *wih, *ych, *woh;
    cudaGetSymbolAddress((void**)&xh, g_xh);
    cudaGetSymbolAddress((void**)&wih, g_wih);
    cudaGetSymbolAddress((void**)&ych, g_ych);
    cudaGetSymbolAddress((void**)&woh, g_woh);

    cudaFuncSetAttribute(gemm_fp16, cudaFuncAttributeMaxDynamicSharedMemorySize, GSMEM_BYTES);
    cudaFuncSetAttribute(dtfix_kernel, cudaFuncAttributeMaxDynamicSharedMemorySize, DTSM_BYTES);

    // 1) merged fp16 converts
    {
        size_t total = CVT_NX + CVT_NW + CVT_NWO;
        cvt_all_kernel<<<(unsigned)((total + 255) / 256), 256>>>(x, in_proj_w, out_proj_w);
    }
    // 2) in_proj GEMM (fp16, 128x128 tiles, BK=64)
    gemm_fp16<<<dim3(PROJPAD / 128, ML / 128), 256, GSMEM_BYTES>>>(
        xh, wih, nullptr, zx, DM, PROJ);
    // 3) exact fp32 dt
    dtfix_kernel<<<ML / 64, 256, DTSM_BYTES>>>(x, in_proj_w, A_log, dt_bias);
    // 4) conv + double silu (smem-tiled)
    conv_kernel<<<dim3(CONVD / 128, Bsz * (Lseq / 32)), 256>>>(conv_w);
    // 5) G = C B^T once per (b,c), 4-way l-split
    gmat_kernel<<<dim3(NCHUNK, Bsz, 4), 256>>>();
    // 6) per-chunk SSD (tensor cores, MUFU-reduced)
    chunk_kernel<<<dim3(NCHUNK, Hh, Bsz), 256>>>();
    // 7) inter-chunk scan + final state
    scan_kernel<<<dim3(Bsz * Hh, 8), 256>>>(state, out + (size_t)ML * DM);
    // 8) Y_off + D*X (tensor cores)
    yoff_kernel<<<dim3(NCHUNK, Hh, Bsz), 256>>>(D_param);
    // 9) RMSNorm + gate + fp16 convert
    rms_cvt_kernel<<<ML, 256>>>(norm_w);
    // 10) out_proj GEMM (fp16) + residual -> d_out
    gemm_fp16<<<dim3(DM / 128, ML / 128), 256, GSMEM_BYTES>>>(
        ych, woh, x, out, DI, DM);
}

// round 15
// speedup vs baseline: 1.1398x; 1.0009x over previous
#include <cuda_runtime.h>
#include <cuda_bf16.h>
#include <cuda_fp16.h>
#include <cstdint>

// Problem constants
#define Bsz 2
#define Lseq 2048
#define DM 1024
#define DI 2048          // d_inner
#define Hh 32            // heads
#define Pp 64            // headdim
#define Nn 128           // d_state
#define CONVD 2304       // conv_dim = d_inner + 2*N
#define PROJ 4384        // 2*DI + 2*N + H
#define PROJPAD 4480     // 35*128
#define CHK 64           // block_len
#define NCHUNK 32        // L / CHK
#define ML (Bsz*Lseq)    // 4096 rows
#define EPSV 1.1920929e-07f

// ------------------------- scratch (device globals) -------------------------
__device__ float g_zxbcdt[(size_t)ML * PROJ];
__device__ float g_xbc[(size_t)ML * CONVD];
__device__ float g_dt[(size_t)ML * Hh];
__device__ float g_adt[(size_t)ML * Hh];
__device__ float g_Y[(size_t)ML * DI];
__device__ float g_states[(size_t)Bsz * NCHUNK * Hh * Pp * Nn];
__device__ float g_lastA[Bsz * NCHUNK * Hh];           // stores exp(lastA)
__device__ float g_cs[Bsz * NCHUNK * Hh * CHK];        // stores exp(cs)
__device__ float g_G[(size_t)Bsz * NCHUNK * CHK * CHK];

// fp16 buffers
__device__ __half g_xh[(size_t)ML * DM];
__device__ __half g_wih[(size_t)PROJPAD * DM];
__device__ __half g_ych[(size_t)ML * DI];
__device__ __half g_woh[(size_t)DM * DI];

// ------------------------- helpers ------------------------------------------
__device__ __forceinline__ uint32_t smem_to_u32(const void* p) {
    uint32_t a;
    asm("{ .reg .u64 t; cvta.to.shared.u64 t, %1; cvt.u32.u64 %0, t; }" : "=r"(a) : "l"(p));
    return a;
}
__device__ __forceinline__ void ldmx4(uint32_t* r, uint32_t addr) {
    asm volatile("ldmatrix.sync.aligned.m8n8.x4.shared.b16 {%0,%1,%2,%3}, [%4];"
                 : "=r"(r[0]), "=r"(r[1]), "=r"(r[2]), "=r"(r[3]) : "r"(addr));
}
__device__ __forceinline__ void ldmx4t(uint32_t* r, uint32_t addr) {
    asm volatile("ldmatrix.sync.aligned.m8n8.x4.trans.shared.b16 {%0,%1,%2,%3}, [%4];"
                 : "=r"(r[0]), "=r"(r[1]), "=r"(r[2]), "=r"(r[3]) : "r"(addr));
}
__device__ __forceinline__ void mma16816h(float* c, const uint32_t* a,
                                          uint32_t b0, uint32_t b1) {
    asm volatile("mma.sync.aligned.m16n8k16.row.col.f32.f16.f16.f32 "
                 "{%0,%1,%2,%3}, {%4,%5,%6,%7}, {%8,%9}, {%0,%1,%2,%3};"
                 : "+f"(c[0]), "+f"(c[1]), "+f"(c[2]), "+f"(c[3])
                 : "r"(a[0]), "r"(a[1]), "r"(a[2]), "r"(a[3]), "r"(b0), "r"(b1));
}
__device__ __forceinline__ void cpasync16(uint32_t dst, const void* src) {
    asm volatile("cp.async.cg.shared.global [%0], [%1], 16;" :: "r"(dst), "l"(src));
}
#define CP_COMMIT() asm volatile("cp.async.commit_group;" ::: "memory")
#define CP_WAIT(n)  asm volatile("cp.async.wait_group %0;" :: "n"(n) : "memory")

// ------------------- merged fp16 convert (x, W_in pad, W_out) ---------------
#define CVT_NX  ((size_t)ML * DM)
#define CVT_NW  ((size_t)PROJPAD * DM)
#define CVT_NWO ((size_t)DM * DI)
__global__ void cvt_all_kernel(const float* __restrict__ x,
                               const float* __restrict__ w_in,
                               const float* __restrict__ w_out)
{
    size_t i = (size_t)blockIdx.x * blockDim.x + threadIdx.x;
    if (i < CVT_NX) {
        g_xh[i] = __float2half_rn(x[i]);
    } else if (i < CVT_NX + CVT_NW) {
        size_t j = i - CVT_NX;
        int r = (int)(j / DM);
        g_wih[j] = __float2half_rn((r < PROJ) ? w_in[j] : 0.f);
    } else if (i < CVT_NX + CVT_NW + CVT_NWO) {
        size_t j = i - CVT_NX - CVT_NW;
        g_woh[j] = __float2half_rn(w_out[j]);
    }
}

// ------------------------- fp16 mma.sync GEMM (128x128 tile, BK=64) ----------
#define SROW 72             // 64 fp16 + 8 pad
#define GST  (128 * SROW)
#define GSMEM_BYTES (2 * 2 * GST * 2)

__global__ __launch_bounds__(256) void gemm_fp16(
    const __half* __restrict__ A, const __half* __restrict__ Bw,
    const float* __restrict__ res, float* __restrict__ C,
    int K, int Nstore)
{
    extern __shared__ __align__(16) __half gsm[];
    int tid = threadIdx.x;
    int lane = tid & 31, wid = tid >> 5;
    int warp_m = wid >> 1, warp_n = wid & 1;
    int bn = blockIdx.x * 128;
    int bm = blockIdx.y * 128;

    int NC = K >> 6;

    float c[2][8][4];
#pragma unroll
    for (int i = 0; i < 2; i++)
#pragma unroll
        for (int j = 0; j < 8; j++)
#pragma unroll
            for (int q = 0; q < 4; q++) c[i][j][q] = 0.f;

    auto load_chunk = [&](int ci, int s) {
        int kk = ci * 64;
#pragma unroll
        for (int it = 0; it < 8; it++) {
            int t = tid + it * 256;
            int tile = t >> 10;
            int idx = t & 1023;
            int row = idx >> 3;
            int sg = idx & 7;
            const __half* src = tile ? (Bw + (size_t)(bn + row) * K + kk + sg * 8)
                                     : (A + (size_t)(bm + row) * K + kk + sg * 8);
            uint32_t dst = smem_to_u32(gsm + (size_t)(s * 2 + tile) * GST + row * SROW + sg * 8);
            cpasync16(dst, src);
        }
        CP_COMMIT();
    };

    load_chunk(0, 0);
    for (int ci = 0; ci < NC; ci++) {
        int s = ci & 1;
        if (ci + 1 < NC) { load_chunk(ci + 1, s ^ 1); CP_WAIT(1); }
        else CP_WAIT(0);
        __syncthreads();

        uint32_t a_base = smem_to_u32(gsm + (size_t)(s * 2 + 0) * GST);
        uint32_t b_base = smem_to_u32(gsm + (size_t)(s * 2 + 1) * GST);
#pragma unroll
        for (int k0 = 0; k0 < 64; k0 += 16) {
            uint32_t a[2][4];
#pragma unroll
            for (int im = 0; im < 2; im++) {
                uint32_t addr = a_base
                    + (uint32_t)(warp_m * 32 + im * 16 + (lane & 15)) * (SROW * 2)
                    + (uint32_t)(k0 + ((lane >> 4) << 3)) * 2;
                ldmx4(a[im], addr);
            }
            uint32_t bf[4][4];
#pragma unroll
            for (int ib = 0; ib < 4; ib++) {
                uint32_t addr = b_base
                    + (uint32_t)(warp_n * 64 + ib * 16 + (((lane >> 3) & 1) << 3) + (lane & 7)) * (SROW * 2)
                    + (uint32_t)(k0 + ((lane >> 4) << 3)) * 2;
                ldmx4(bf[ib], addr);
            }
#pragma unroll
            for (int im = 0; im < 2; im++)
#pragma unroll
                for (int in = 0; in < 8; in++) {
                    int ib = in >> 1, wh = in & 1;
                    mma16816h(c[im][in], a[im], bf[ib][wh], bf[ib][2 + wh]);
                }
        }
        __syncthreads();
    }

    int gp = lane >> 2, tg = lane & 3;
#pragma unroll
    for (int im = 0; im < 2; im++) {
        int m0 = bm + warp_m * 32 + im * 16;
#pragma unroll
        for (int in = 0; in < 8; in++) {
            int n = bn + warp_n * 64 + in * 8 + tg * 2;
            if (n >= Nstore) continue;
#pragma unroll
            for (int half = 0; half < 2; half++) {
                int m = m0 + gp + half * 8;
                float2 v;
                v.x = c[im][in][half * 2 + 0];
                v.y = c[im][in][half * 2 + 1];
                if (res) {
                    const float2 rv = *(const float2*)(res + (size_t)m * Nstore + n);
                    v.x += rv.x; v.y += rv.y;
                }
                *(float2*)(C + (size_t)m * Nstore + n) = v;
            }
        }
    }
}

// ----------------- exact fp32 dt GEMM: 64 blocks x 64 rows ------------------
#define DTS_X   0
#define DTS_W   (64 * 132)
#define DTSM_BYTES ((64 * 132 + 32 * 131) * 4)

__global__ __launch_bounds__(256) void dtfix_kernel(
    const float* __restrict__ x, const float* __restrict__ in_proj_w,
    const float* __restrict__ A_log, const float* __restrict__ dt_bias)
{
    extern __shared__ float dts[];
    float* sx = dts + DTS_X;
    float* sw = dts + DTS_W;
    int r0 = blockIdx.x * 64;
    int tid = threadIdx.x;
    int hg = tid & 7, rg = tid >> 3;
    int rr0 = rg * 2, hh0 = hg * 4;
    float acc[2][4];
#pragma unroll
    for (int i = 0; i < 2; i++)
#pragma unroll
        for (int j = 0; j < 4; j++) acc[i][j] = 0.f;

    for (int kc = 0; kc < 8; kc++) {
        int k0 = kc * 128;
        for (int t = tid; t < 2048; t += 256) {
            int r = t >> 5, q = (t & 31) * 4;
            float4 v = *(const float4*)(x + (size_t)(r0 + r) * DM + k0 + q);
            *(float4*)(sx + r * 132 + q) = v;
        }
        for (int t = tid; t < 1024; t += 256) {
            int r = t >> 5, q = (t & 31) * 4;
            float4 v = *(const float4*)(in_proj_w + (size_t)(DI + CONVD + r) * DM + k0 + q);
            sw[r * 131 + q + 0] = v.x; sw[r * 131 + q + 1] = v.y;
            sw[r * 131 + q + 2] = v.z; sw[r * 131 + q + 3] = v.w;
        }
        __syncthreads();
#pragma unroll 4
        for (int k = 0; k < 128; k++) {
            float x0 = sx[rr0 * 132 + k];
            float x1 = sx[(rr0 + 1) * 132 + k];
            float w0 = sw[(hh0 + 0) * 131 + k];
            float w1 = sw[(hh0 + 1) * 131 + k];
            float w2 = sw[(hh0 + 2) * 131 + k];
            float w3 = sw[(hh0 + 3) * 131 + k];
            acc[0][0] = fmaf(x0, w0, acc[0][0]);
            acc[0][1] = fmaf(x0, w1, acc[0][1]);
            acc[0][2] = fmaf(x0, w2, acc[0][2]);
            acc[0][3] = fmaf(x0, w3, acc[0][3]);
            acc[1][0] = fmaf(x1, w0, acc[1][0]);
            acc[1][1] = fmaf(x1, w1, acc[1][1]);
            acc[1][2] = fmaf(x1, w2, acc[1][2]);
            acc[1][3] = fmaf(x1, w3, acc[1][3]);
        }
        __syncthreads();
    }
#pragma unroll
    for (int i = 0; i < 2; i++) {
        int ml = r0 + rr0 + i;
#pragma unroll
        for (int j = 0; j < 4; j++) {
            int h = hh0 + j;
            float raw = acc[i][j] + dt_bias[h];
            float sp = (raw > 20.f) ? raw : log1pf(expf(raw));   // exact (decay-critical)
            g_dt[ml * Hh + h] = sp;
            g_adt[ml * Hh + h] = -expf(A_log[h]) * sp;
        }
    }
}

// ------------- causal depthwise conv + double silu (smem-tiled) -------------
__device__ __forceinline__ float silu_f(float x) { return x / (1.f + __expf(-x)); }

__global__ __launch_bounds__(256) void conv_kernel(const float* __restrict__ conv_w)
{
    __shared__ float sxm[35][132];
    int cc = blockIdx.x;
    int ytile = blockIdx.y;
    int b = ytile >> 6;
    int l0 = (ytile & 63) * 32;
    int tid = threadIdx.x;
    int ch_base = cc * 128;

    for (int t = tid; t < 35 * 32; t += 256) {
        int r = t >> 5, q = (t & 31) * 4;
        int ls = l0 - 3 + r;
        float4 v = make_float4(0.f, 0.f, 0.f, 0.f);
        if (ls >= 0 && r < 32 + 3)
            v = *(const float4*)(g_zxbcdt + ((size_t)(b * Lseq + ls)) * PROJ + DI + ch_base + q);
        *(float4*)(&sxm[r][q]) = v;
    }
    __syncthreads();

    int tx = tid & 31, ty = tid >> 5;
    int ch4 = tx * 4;
    float4 w0 = *(const float4*)(conv_w + (ch_base + ch4 + 0) * 4);
    float4 w1 = *(const float4*)(conv_w + (ch_base + ch4 + 1) * 4);
    float4 w2 = *(const float4*)(conv_w + (ch_base + ch4 + 2) * 4);
    float4 w3 = *(const float4*)(conv_w + (ch_base + ch4 + 3) * 4);
#pragma unroll
    for (int li = 0; li < 4; li++) {
        int lloc = ty * 4 + li;
        float a0 = 0.f, a1 = 0.f, a2 = 0.f, a3 = 0.f;
#pragma unroll
        for (int j = 0; j < 4; j++) {
            const float* row = &sxm[lloc + j][ch4];
            a0 = fmaf(row[0], (&w0.x)[j], a0);
            a1 = fmaf(row[1], (&w1.x)[j], a1);
            a2 = fmaf(row[2], (&w2.x)[j], a2);
            a3 = fmaf(row[3], (&w3.x)[j], a3);
        }
        float4 o;
        o.x = silu_f(silu_f(a0));
        o.y = silu_f(silu_f(a1));
        o.z = silu_f(silu_f(a2));
        o.w = silu_f(silu_f(a3));
        *(float4*)(g_xbc + (size_t)(b * Lseq + l0 + lloc) * CONVD + ch_base + ch4) = o;
    }
}

// ------------- G = C * B^T per (b,c), 4-way split over l --------------------
__global__ __launch_bounds__(256) void gmat_kernel()
{
    int c = blockIdx.x, b = blockIdx.y, z = blockIdx.z;
    __shared__ float sB[64][33];
    __shared__ float sC[16][33];
    int tid = threadIdx.x;
    int tx = tid & 15, ty = tid >> 4;
    int lloc = ty, s0 = tx * 4;
    size_t rowbase = (size_t)(b * Lseq + c * CHK);
    int lg = z * 16;
    float g4[4] = {0.f, 0.f, 0.f, 0.f};

    for (int nc = 0; nc < Nn; nc += 32) {
        for (int t = tid; t < 64 * 8; t += 256) {
            int l = t >> 3, q = (t & 7) * 4;
            float4 bv = *(const float4*)(g_xbc + (rowbase + l) * CONVD + DI + nc + q);
            sB[l][q + 0] = bv.x; sB[l][q + 1] = bv.y;
            sB[l][q + 2] = bv.z; sB[l][q + 3] = bv.w;
        }
        if (tid < 16 * 8) {
            int l = tid >> 3, q = (tid & 7) * 4;
            float4 cv = *(const float4*)(g_xbc + (rowbase + lg + l) * CONVD + DI + Nn + nc + q);
            sC[l][q + 0] = cv.x; sC[l][q + 1] = cv.y;
            sC[l][q + 2] = cv.z; sC[l][q + 3] = cv.w;
        }
        __syncthreads();
#pragma unroll
        for (int n = 0; n < 32; n++) {
            float cr = sC[lloc][n];
            g4[0] = fmaf(cr, sB[s0 + 0][n], g4[0]);
            g4[1] = fmaf(cr, sB[s0 + 1][n], g4[1]);
            g4[2] = fmaf(cr, sB[s0 + 2][n], g4[2]);
            g4[3] = fmaf(cr, sB[s0 + 3][n], g4[3]);
        }
        __syncthreads();
    }
    float* Gp = g_G + ((size_t)(b * NCHUNK + c)) * (CHK * CHK);
    float4 v = make_float4(g4[0], g4[1], g4[2], g4[3]);
    *(float4*)(Gp + (lg + lloc) * 64 + s0) = v;
}

// -------------- per-chunk SSD via tensor cores (fp16 mma) -------------------
__global__ __launch_bounds__(256) void chunk_kernel()
{
    __shared__ __half sM[64][72];
    __shared__ __half sX[64][72];
    __shared__ __half sXd[64][72];
    __shared__ __half sB[64][136];
    __shared__ float scs[64];
    __shared__ float sDec[64];
    int c = blockIdx.x, h = blockIdx.y, b = blockIdx.z;
    int tid = threadIdx.x, lane = tid & 31, wid = tid >> 5;
    size_t rowbase = (size_t)(b * Lseq + c * CHK);

    if (wid == 0) {
        float v0 = g_adt[(rowbase + lane) * Hh + h];
        float v1 = g_adt[(rowbase + 32 + lane) * Hh + h];
#pragma unroll
        for (int off = 1; off < 32; off <<= 1) {
            float t = __shfl_up_sync(0xFFFFFFFF, v0, off);
            if (lane >= off) v0 += t;
        }
        float tot = __shfl_sync(0xFFFFFFFF, v0, 31);
#pragma unroll
        for (int off = 1; off < 32; off <<= 1) {
            float t = __shfl_up_sync(0xFFFFFFFF, v1, off);
            if (lane >= off) v1 += t;
        }
        v1 += tot;
        float alast = __shfl_sync(0xFFFFFFFF, v1, 31);
        scs[lane] = v0;
        scs[32 + lane] = v1;
        sDec[lane] = __expf(alast - v0);
        sDec[32 + lane] = __expf(alast - v1);
    }
    // B tile (no scs dependency)
    for (int i = tid; i < 64 * 32; i += 256) {
        int l = i >> 5, q = (i & 31) * 4;
        float4 v = *(const float4*)(g_xbc + (rowbase + l) * CONVD + DI + q);
        sB[l][q + 0] = __float2half_rn(v.x);
        sB[l][q + 1] = __float2half_rn(v.y);
        sB[l][q + 2] = __float2half_rn(v.z);
        sB[l][q + 3] = __float2half_rn(v.w);
    }
    __syncthreads();   // scs/sDec ready

    for (int i = tid; i < 64 * 16; i += 256) {
        int l = i >> 4, q = (i & 15) * 4;
        float4 v = *(const float4*)(g_xbc + (rowbase + l) * CONVD + h * 64 + q);
        float d = g_dt[(rowbase + l) * Hh + h];
        float e = sDec[l];
        float x0 = v.x * d, x1 = v.y * d, x2 = v.z * d, x3 = v.w * d;
        sX[l][q + 0] = __float2half_rn(x0);
        sX[l][q + 1] = __float2half_rn(x1);
        sX[l][q + 2] = __float2half_rn(x2);
        sX[l][q + 3] = __float2half_rn(x3);
        sXd[l][q + 0] = __float2half_rn(x0 * e);
        sXd[l][q + 1] = __float2half_rn(x1 * e);
        sXd[l][q + 2] = __float2half_rn(x2 * e);
        sXd[l][q + 3] = __float2half_rn(x3 * e);
    }
    {
        int tx = tid & 15, ty = tid >> 4;
        int l0 = ty * 4, s0 = tx * 4;
        const float* Gp = g_G + ((size_t)(b * NCHUNK + c)) * (CHK * CHK);
#pragma unroll
        for (int i = 0; i < 4; i++) {
            int l = l0 + i;
            if (s0 > l) {
                sM[l][s0 + 0] = __float2half_rn(0.f);
                sM[l][s0 + 1] = __float2half_rn(0.f);
                sM[l][s0 + 2] = __float2half_rn(0.f);
                sM[l][s0 + 3] = __float2half_rn(0.f);
            } else {
                float4 gv = *(const float4*)(Gp + l * 64 + s0);
                float csl = scs[l];
                if (s0 + 3 <= l) {
                    sM[l][s0 + 0] = __float2half_rn(gv.x * __expf(csl - scs[s0 + 0]));
                    sM[l][s0 + 1] = __float2half_rn(gv.y * __expf(csl - scs[s0 + 1]));
                    sM[l][s0 + 2] = __float2half_rn(gv.z * __expf(csl - scs[s0 + 2]));
                    sM[l][s0 + 3] = __float2half_rn(gv.w * __expf(csl - scs[s0 + 3]));
                } else {
                    sM[l][s0 + 0] = __float2half_rn((s0 + 0 <= l) ? gv.x * __expf(csl - scs[s0 + 0]) : 0.f);
                    sM[l][s0 + 1] = __float2half_rn((s0 + 1 <= l) ? gv.y * __expf(csl - scs[s0 + 1]) : 0.f);
                    sM[l][s0 + 2] = __float2half_rn((s0 + 2 <= l) ? gv.z * __expf(csl - scs[s0 + 2]) : 0.f);
                    sM[l][s0 + 3] = __float2half_rn((s0 + 3 <= l) ? gv.w * __expf(csl - scs[s0 + 3]) : 0.f);
                }
            }
        }
    }
    __syncthreads();

    int gp = lane >> 2, tg = lane & 3;
    // matmul1: Y_diag = M @ X
    {
        int wm = wid & 3, wn = wid >> 2;
        float cy[4][4];
#pragma unroll
        for (int i = 0; i < 4; i++)
#pragma unroll
            for (int j = 0; j < 4; j++) cy[i][j] = 0.f;
#pragma unroll
        for (int k0 = 0; k0 < 64; k0 += 16) {
            uint32_t a[4];
            ldmx4(a, smem_to_u32(&sM[wm * 16 + (lane & 15)][k0 + ((lane >> 4) << 3)]));
#pragma unroll
            for (int g = 0; g < 2; g++) {
                uint32_t bf[4];
                ldmx4t(bf, smem_to_u32(&sX[k0 + (lane & 15)][wn * 32 + g * 16 + ((lane >> 4) << 3)]));
                mma16816h(cy[g * 2 + 0], a, bf[0], bf[1]);
                mma16816h(cy[g * 2 + 1], a, bf[2], bf[3]);
            }
        }
#pragma unroll
        for (int nb = 0; nb < 4; nb++) {
            int p = wn * 32 + nb * 8 + tg * 2;
#pragma unroll
            for (int hf = 0; hf < 2; hf++) {
                int l = wm * 16 + gp + hf * 8;
                float2 v = make_float2(cy[nb][hf * 2 + 0], cy[nb][hf * 2 + 1]);
                *(float2*)(g_Y + (rowbase + l) * DI + h * 64 + p) = v;
            }
        }
    }

    // matmul2: S = sXd^T @ B
    {
        int pmw = wid & 3, nw = wid >> 2;
        int p0 = pmw * 16, n0 = nw * 64;
        float cs2[8][4];
#pragma unroll
        for (int i = 0; i < 8; i++)
#pragma unroll
            for (int j = 0; j < 4; j++) cs2[i][j] = 0.f;
#pragma unroll
        for (int k0 = 0; k0 < 64; k0 += 16) {
            uint32_t r[4];
            ldmx4t(r, smem_to_u32(&sXd[k0 + (lane & 15)][p0 + ((lane >> 4) << 3)]));
            uint32_t a[4] = {r[0], r[2], r[1], r[3]};
#pragma unroll
            for (int g = 0; g < 4; g++) {
                uint32_t bf[4];
                ldmx4t(bf, smem_to_u32(&sB[k0 + (lane & 15)][n0 + g * 16 + ((lane >> 4) << 3)]));
                mma16816h(cs2[g * 2 + 0], a, bf[0], bf[1]);
                mma16816h(cs2[g * 2 + 1], a, bf[2], bf[3]);
            }
        }
        size_t sbase = (((size_t)(b * NCHUNK + c)) * Hh + h) * (Pp * Nn);
#pragma unroll
        for (int nb = 0; nb < 8; nb++) {
            int n = n0 + nb * 8 + tg * 2;
#pragma unroll
            for (int hf = 0; hf < 2; hf++) {
                int p = p0 + gp + hf * 8;
                float2 v = make_float2(cs2[nb][hf * 2 + 0], cs2[nb][hf * 2 + 1]);
                *(float2*)(g_states + sbase + (size_t)p * Nn + n) = v;
            }
        }
    }

    // exact expf for cross-chunk decay chain
    if (tid < 64) g_cs[((b * NCHUNK + c) * Hh + h) * CHK + tid] = expf(scs[tid]);
    if (tid == 0) g_lastA[(b * NCHUNK + c) * Hh + h] = expf(scs[63]);
}

// ---------- inter-chunk scan, 8-way sliced, float4 (dec pre-exp'd) ----------
__global__ __launch_bounds__(256) void scan_kernel(const float* __restrict__ init_state,
                                                   float* __restrict__ fstate_out)
{
    int bh = blockIdx.x;
    int h = bh & (Hh - 1), b = bh >> 5;
    int off = blockIdx.y * 1024 + threadIdx.x * 4;
    size_t ibase = ((size_t)(b * Hh + h)) * (Pp * Nn);
    float4 run = *(const float4*)(init_state + ibase + off);
    for (int c = 0; c < NCHUNK; c++) {
        float dec = g_lastA[(b * NCHUNK + c) * Hh + h];
        size_t idx = (((size_t)(b * NCHUNK + c)) * Hh + h) * (Pp * Nn) + off;
        float4 v = *(const float4*)(g_states + idx);
        *(float4*)(g_states + idx) = run;
        run.x = fmaf(dec, run.x, v.x);
        run.y = fmaf(dec, run.y, v.y);
        run.z = fmaf(dec, run.z, v.z);
        run.w = fmaf(dec, run.w, v.w);
    }
    *(float4*)(fstate_out + ibase + off) = run;
}

// --------------- Y_off + D*X epilogue via tensor cores (cs pre-exp'd) -------
__global__ __launch_bounds__(256) void yoff_kernel(const float* __restrict__ D_param)
{
    __shared__ __half sC[64][136];
    __shared__ __half sS[64][136];
    __shared__ float scs[64];
    int c = blockIdx.x, h = blockIdx.y, b = blockIdx.z;
    int tid = threadIdx.x, lane = tid & 31, wid = tid >> 5;
    size_t rowbase = (size_t)(b * Lseq + c * CHK);
    if (tid < 64) scs[tid] = g_cs[((b * NCHUNK + c) * Hh + h) * CHK + tid];

    size_t sbase = (((size_t)(b * NCHUNK + c)) * Hh + h) * (Pp * Nn);
    for (int t = tid; t < 64 * 32; t += 256) {
        int r = t >> 5, q = (t & 31) * 4;
        float4 cv = *(const float4*)(g_xbc + (rowbase + r) * CONVD + DI + Nn + q);
        sC[r][q + 0] = __float2half_rn(cv.x);
        sC[r][q + 1] = __float2half_rn(cv.y);
        sC[r][q + 2] = __float2half_rn(cv.z);
        sC[r][q + 3] = __float2half_rn(cv.w);
        float4 sv = *(const float4*)(g_states + sbase + (size_t)r * Nn + q);
        sS[r][q + 0] = __float2half_rn(sv.x);
        sS[r][q + 1] = __float2half_rn(sv.y);
        sS[r][q + 2] = __float2half_rn(sv.z);
        sS[r][q + 3] = __float2half_rn(sv.w);
    }
    __syncthreads();

    int wm = wid & 3, wn = wid >> 2;
    int l0 = wm * 16, p0 = wn * 32;
    float acc[4][4];
#pragma unroll
    for (int i = 0; i < 4; i++)
#pragma unroll
        for (int j = 0; j < 4; j++) acc[i][j] = 0.f;

#pragma unroll
    for (int k0 = 0; k0 < Nn; k0 += 16) {
        uint32_t a[4];
        ldmx4(a, smem_to_u32(&sC[l0 + (lane & 15)][k0 + ((lane >> 4) << 3)]));
        uint32_t bf[2][4];
#pragma unroll
        for (int g = 0; g < 2; g++)
            ldmx4(bf[g], smem_to_u32(
                &sS[p0 + g * 16 + (((lane >> 3) & 1) << 3) + (lane & 7)][k0 + ((lane >> 4) << 3)]));
#pragma unroll
        for (int nb = 0; nb < 4; nb++) {
            int ib = nb >> 1, wh = nb & 1;
            mma16816h(acc[nb], a, bf[ib][wh], bf[ib][2 + wh]);
        }
    }
    float Dh = D_param[h];
    int gp = lane >> 2, tg = lane & 3;
#pragma unroll
    for (int nb = 0; nb < 4; nb++) {
        int p = p0 + nb * 8 + tg * 2;
#pragma unroll
        for (int hf = 0; hf < 2; hf++) {
            int l = l0 + gp + hf * 8;
            float e = scs[l];
            size_t gi = (rowbase + l) * DI + h * 64 + p;
            float2 yv = *(const float2*)(g_Y + gi);
            float2 xv = *(const float2*)(g_xbc + (rowbase + l) * CONVD + h * 64 + p);
            yv.x += e * acc[nb][hf * 2 + 0] + Dh * xv.x;
            yv.y += e * acc[nb][hf * 2 + 1] + Dh * xv.y;
            *(float2*)(g_Y + gi) = yv;
        }
    }
}

// -------- RMSNorm * norm_w * sigmoid(z) -> fp16 y_core (float4) --------------
__global__ __launch_bounds__(256) void rms_cvt_kernel(const float* __restrict__ norm_w)
{
    int row = blockIdx.x;
    int tid = threadIdx.x, lane = tid & 31, wid = tid >> 5;
    __shared__ float red[8];
    const float* y = g_Y + (size_t)row * DI;
    float ss = 0.f;
#pragma unroll
    for (int it = 0; it < 2; it++) {
        int j = (tid + it * 256) * 4;
        float4 v = *(const float4*)(y + j);
        ss = fmaf(v.x, v.x, ss);
        ss = fmaf(v.y, v.y, ss);
        ss = fmaf(v.z, v.z, ss);
        ss = fmaf(v.w, v.w, ss);
    }
#pragma unroll
    for (int off = 16; off > 0; off >>= 1) ss += __shfl_xor_sync(0xFFFFFFFF, ss, off);
    if (lane == 0) red[wid] = ss;
    __syncthreads();
    if (wid == 0) {
        float v = (lane < 8) ? red[lane] : 0.f;
#pragma unroll
        for (int off = 4; off > 0; off >>= 1) v += __shfl_xor_sync(0xFFFFFFFF, v, off);
        if (lane == 0) red[0] = v;
    }
    __syncthreads();
    float scale = rsqrtf(red[0] / (float)DI + EPSV);
    __half* ph = g_ych + (size_t)row * DI;
#pragma unroll
    for (int it = 0; it < 2; it++) {
        int j = (tid + it * 256) * 4;
        float4 yv = *(const float4*)(y + j);
        float4 zv = *(const float4*)(g_zxbcdt + (size_t)row * PROJ + j);
        __half2 h0, h1;
        h0.x = __float2half_rn(yv.x * scale * norm_w[j + 0] / (1.f + __expf(-zv.x)));
        h0.y = __float2half_rn(yv.y * scale * norm_w[j + 1] / (1.f + __expf(-zv.y)));
        h1.x = __float2half_rn(yv.z * scale * norm_w[j + 2] / (1.f + __expf(-zv.z)));
        h1.y = __float2half_rn(yv.w * scale * norm_w[j + 3] / (1.f + __expf(-zv.w)));
        *(__half2*)(ph + j) = h0;
        *(__half2*)(ph + j + 2) = h1;
    }
}

// ------------------------- launch ------------------------------------------
extern "C" void kernel_launch(void* const* d_in, const int* in_sizes, int n_in,
                              void* d_out, int out_size)
{
    const float* x         = (const float*)d_in[0];
    const float* state     = (const float*)d_in[1];
    const float* in_proj_w = (const float*)d_in[2];
    const float* conv_w    = (const float*)d_in[3];
    const float* A_log     = (const float*)d_in[4];
    const float* dt_bias   = (const float*)d_in[5];
    const float* D_param   = (const float*)d_in[6];
    const float* norm_w    = (const float*)d_in[7];
    const float* out_proj_w= (const float*)d_in[8];
    float* out = (float*)d_out;

    float* zx;   cudaGetSymbolAddress((void**)&zx, g_zxbcdt);
    __half *xh, *wih, *ych, *woh;
    cudaGetSymbolAddress((void**)&xh, g_xh);
    cudaGetSymbolAddress((void**)&wih, g_wih);
    cudaGetSymbolAddress((void**)&ych, g_ych);
    cudaGetSymbolAddress((void**)&woh, g_woh);

    cudaFuncSetAttribute(gemm_fp16, cudaFuncAttributeMaxDynamicSharedMemorySize, GSMEM_BYTES);
    cudaFuncSetAttribute(dtfix_kernel, cudaFuncAttributeMaxDynamicSharedMemorySize, DTSM_BYTES);

    // 1) merged fp16 converts
    {
        size_t total = CVT_NX + CVT_NW + CVT_NWO;
        cvt_all_kernel<<<(unsigned)((total + 255) / 256), 256>>>(x, in_proj_w, out_proj_w);
    }
    // 2) in_proj GEMM (fp16, 128x128 tiles, BK=64)
    gemm_fp16<<<dim3(PROJPAD / 128, ML / 128), 256, GSMEM_BYTES>>>(
        xh, wih, nullptr, zx, DM, PROJ);
    // 3) exact fp32 dt
    dtfix_kernel<<<ML / 64, 256, DTSM_BYTES>>>(x, in_proj_w, A_log, dt_bias);
    // 4) conv + double silu (fast-exp silu)
    conv_kernel<<<dim3(CONVD / 128, Bsz * (Lseq / 32)), 256>>>(conv_w);
    // 5) G = C B^T once per (b,c), 4-way l-split
    gmat_kernel<<<dim3(NCHUNK, Bsz, 4), 256>>>();
    // 6) per-chunk SSD (tensor cores, fast-exp sM)
    chunk_kernel<<<dim3(NCHUNK, Hh, Bsz), 256>>>();
    // 7) inter-chunk scan + final state
    scan_kernel<<<dim3(Bsz * Hh, 8), 256>>>(state, out + (size_t)ML * DM);
    // 8) Y_off + D*X (tensor cores)
    yoff_kernel<<<dim3(NCHUNK, Hh, Bsz), 256>>>(D_param);
    // 9) RMSNorm + gate + fp16 convert (fast-exp sigmoid)
    rms_cvt_kernel<<<ML, 256>>>(norm_w);
    // 10) out_proj GEMM (fp16) + residual -> d_out
    gemm_fp16<<<dim3(DM / 128, ML / 128), 256, GSMEM_BYTES>>>(
        ych, woh, x, out, DI, DM);
}

// round 16
// speedup vs baseline: 1.2701x; 1.1143x over previous
#include <cuda_runtime.h>
#include <cuda_bf16.h>
#include <cuda_fp16.h>
#include <cstdint>

// Problem constants
#define Bsz 2
#define Lseq 2048
#define DM 1024
#define DI 2048          // d_inner
#define Hh 32            // heads
#define Pp 64            // headdim
#define Nn 128           // d_state
#define CONVD 2304       // conv_dim = d_inner + 2*N
#define PROJ 4384        // 2*DI + 2*N + H
#define PROJPAD 4480     // 35*128
#define CHK 64           // block_len
#define NCHUNK 32        // L / CHK
#define ML (Bsz*Lseq)    // 4096 rows
#define EPSV 1.1920929e-07f

// ------------------------- scratch (device globals) -------------------------
__device__ float g_zxbcdt[(size_t)ML * PROJ];
__device__ float g_xbc[(size_t)ML * CONVD];
__device__ float g_dt[(size_t)ML * Hh];
__device__ float g_adt[(size_t)ML * Hh];
__device__ float g_Y[(size_t)ML * DI];
__device__ float g_states[(size_t)Bsz * NCHUNK * Hh * Pp * Nn];
__device__ float g_lastA[Bsz * NCHUNK * Hh];           // stores exp(lastA)
__device__ float g_cs[Bsz * NCHUNK * Hh * CHK];        // stores exp(cs)
__device__ float g_G[(size_t)Bsz * NCHUNK * CHK * CHK];

// fp16 buffers
__device__ __half g_xh[(size_t)ML * DM];
__device__ __half g_wih[(size_t)PROJPAD * DM];
__device__ __half g_ych[(size_t)ML * DI];
__device__ __half g_woh[(size_t)DM * DI];

// ------------------------- helpers ------------------------------------------
__device__ __forceinline__ uint32_t smem_to_u32(const void* p) {
    uint32_t a;
    asm("{ .reg .u64 t; cvta.to.shared.u64 t, %1; cvt.u32.u64 %0, t; }" : "=r"(a) : "l"(p));
    return a;
}
__device__ __forceinline__ void ldmx4(uint32_t* r, uint32_t addr) {
    asm volatile("ldmatrix.sync.aligned.m8n8.x4.shared.b16 {%0,%1,%2,%3}, [%4];"
                 : "=r"(r[0]), "=r"(r[1]), "=r"(r[2]), "=r"(r[3]) : "r"(addr));
}
__device__ __forceinline__ void ldmx4t(uint32_t* r, uint32_t addr) {
    asm volatile("ldmatrix.sync.aligned.m8n8.x4.trans.shared.b16 {%0,%1,%2,%3}, [%4];"
                 : "=r"(r[0]), "=r"(r[1]), "=r"(r[2]), "=r"(r[3]) : "r"(addr));
}
__device__ __forceinline__ void mma16816h(float* c, const uint32_t* a,
                                          uint32_t b0, uint32_t b1) {
    asm volatile("mma.sync.aligned.m16n8k16.row.col.f32.f16.f16.f32 "
                 "{%0,%1,%2,%3}, {%4,%5,%6,%7}, {%8,%9}, {%0,%1,%2,%3};"
                 : "+f"(c[0]), "+f"(c[1]), "+f"(c[2]), "+f"(c[3])
                 : "r"(a[0]), "r"(a[1]), "r"(a[2]), "r"(a[3]), "r"(b0), "r"(b1));
}
__device__ __forceinline__ void cpasync16(uint32_t dst, const void* src) {
    asm volatile("cp.async.cg.shared.global [%0], [%1], 16;" :: "r"(dst), "l"(src));
}
#define CP_COMMIT() asm volatile("cp.async.commit_group;" ::: "memory")
#define CP_WAIT(n)  asm volatile("cp.async.wait_group %0;" :: "n"(n) : "memory")

// ------------------- merged fp16 convert (x, W_in pad, W_out) ---------------
#define CVT_NX  ((size_t)ML * DM)
#define CVT_NW  ((size_t)PROJPAD * DM)
#define CVT_NWO ((size_t)DM * DI)
__global__ void cvt_all_kernel(const float* __restrict__ x,
                               const float* __restrict__ w_in,
                               const float* __restrict__ w_out)
{
    size_t i = (size_t)blockIdx.x * blockDim.x + threadIdx.x;
    if (i < CVT_NX) {
        g_xh[i] = __float2half_rn(x[i]);
    } else if (i < CVT_NX + CVT_NW) {
        size_t j = i - CVT_NX;
        int r = (int)(j / DM);
        g_wih[j] = __float2half_rn((r < PROJ) ? w_in[j] : 0.f);
    } else if (i < CVT_NX + CVT_NW + CVT_NWO) {
        size_t j = i - CVT_NX - CVT_NW;
        g_woh[j] = __float2half_rn(w_out[j]);
    }
}

// ---------------- fp16 mma.sync GEMM (128x128 tile, BK=64, n-offset) --------
#define SROW 72             // 64 fp16 + 8 pad
#define GST  (128 * SROW)
#define GSMEM_BYTES (2 * 2 * GST * 2)

__global__ __launch_bounds__(256) void gemm_fp16(
    const __half* __restrict__ A, const __half* __restrict__ Bw,
    const float* __restrict__ res, float* __restrict__ C,
    int K, int Nstore, int n0)
{
    extern __shared__ __align__(16) __half gsm[];
    int tid = threadIdx.x;
    int lane = tid & 31, wid = tid >> 5;
    int warp_m = wid >> 1, warp_n = wid & 1;
    int bn = n0 + blockIdx.x * 128;
    int bm = blockIdx.y * 128;

    int NC = K >> 6;

    float c[2][8][4];
#pragma unroll
    for (int i = 0; i < 2; i++)
#pragma unroll
        for (int j = 0; j < 8; j++)
#pragma unroll
            for (int q = 0; q < 4; q++) c[i][j][q] = 0.f;

    auto load_chunk = [&](int ci, int s) {
        int kk = ci * 64;
#pragma unroll
        for (int it = 0; it < 8; it++) {
            int t = tid + it * 256;
            int tile = t >> 10;
            int idx = t & 1023;
            int row = idx >> 3;
            int sg = idx & 7;
            const __half* src = tile ? (Bw + (size_t)(bn + row) * K + kk + sg * 8)
                                     : (A + (size_t)(bm + row) * K + kk + sg * 8);
            uint32_t dst = smem_to_u32(gsm + (size_t)(s * 2 + tile) * GST + row * SROW + sg * 8);
            cpasync16(dst, src);
        }
        CP_COMMIT();
    };

    load_chunk(0, 0);
    for (int ci = 0; ci < NC; ci++) {
        int s = ci & 1;
        if (ci + 1 < NC) { load_chunk(ci + 1, s ^ 1); CP_WAIT(1); }
        else CP_WAIT(0);
        __syncthreads();

        uint32_t a_base = smem_to_u32(gsm + (size_t)(s * 2 + 0) * GST);
        uint32_t b_base = smem_to_u32(gsm + (size_t)(s * 2 + 1) * GST);
#pragma unroll
        for (int k0 = 0; k0 < 64; k0 += 16) {
            uint32_t a[2][4];
#pragma unroll
            for (int im = 0; im < 2; im++) {
                uint32_t addr = a_base
                    + (uint32_t)(warp_m * 32 + im * 16 + (lane & 15)) * (SROW * 2)
                    + (uint32_t)(k0 + ((lane >> 4) << 3)) * 2;
                ldmx4(a[im], addr);
            }
            uint32_t bf[4][4];
#pragma unroll
            for (int ib = 0; ib < 4; ib++) {
                uint32_t addr = b_base
                    + (uint32_t)(warp_n * 64 + ib * 16 + (((lane >> 3) & 1) << 3) + (lane & 7)) * (SROW * 2)
                    + (uint32_t)(k0 + ((lane >> 4) << 3)) * 2;
                ldmx4(bf[ib], addr);
            }
#pragma unroll
            for (int im = 0; im < 2; im++)
#pragma unroll
                for (int in = 0; in < 8; in++) {
                    int ib = in >> 1, wh = in & 1;
                    mma16816h(c[im][in], a[im], bf[ib][wh], bf[ib][2 + wh]);
                }
        }
        __syncthreads();
    }

    int gp = lane >> 2, tg = lane & 3;
#pragma unroll
    for (int im = 0; im < 2; im++) {
        int m0 = bm + warp_m * 32 + im * 16;
#pragma unroll
        for (int in = 0; in < 8; in++) {
            int n = bn + warp_n * 64 + in * 8 + tg * 2;
            if (n >= Nstore) continue;
#pragma unroll
            for (int half = 0; half < 2; half++) {
                int m = m0 + gp + half * 8;
                float2 v;
                v.x = c[im][in][half * 2 + 0];
                v.y = c[im][in][half * 2 + 1];
                if (res) {
                    const float2 rv = *(const float2*)(res + (size_t)m * Nstore + n);
                    v.x += rv.x; v.y += rv.y;
                }
                *(float2*)(C + (size_t)m * Nstore + n) = v;
            }
        }
    }
}

// ----------------- exact fp32 dt GEMM: 64 blocks x 64 rows ------------------
#define DTS_X   0
#define DTS_W   (64 * 132)
#define DTSM_BYTES ((64 * 132 + 32 * 131) * 4)

__global__ __launch_bounds__(256) void dtfix_kernel(
    const float* __restrict__ x, const float* __restrict__ in_proj_w,
    const float* __restrict__ A_log, const float* __restrict__ dt_bias)
{
    extern __shared__ float dts[];
    float* sx = dts + DTS_X;
    float* sw = dts + DTS_W;
    int r0 = blockIdx.x * 64;
    int tid = threadIdx.x;
    int hg = tid & 7, rg = tid >> 3;
    int rr0 = rg * 2, hh0 = hg * 4;
    float acc[2][4];
#pragma unroll
    for (int i = 0; i < 2; i++)
#pragma unroll
        for (int j = 0; j < 4; j++) acc[i][j] = 0.f;

    for (int kc = 0; kc < 8; kc++) {
        int k0 = kc * 128;
        for (int t = tid; t < 2048; t += 256) {
            int r = t >> 5, q = (t & 31) * 4;
            float4 v = *(const float4*)(x + (size_t)(r0 + r) * DM + k0 + q);
            *(float4*)(sx + r * 132 + q) = v;
        }
        for (int t = tid; t < 1024; t += 256) {
            int r = t >> 5, q = (t & 31) * 4;
            float4 v = *(const float4*)(in_proj_w + (size_t)(DI + CONVD + r) * DM + k0 + q);
            sw[r * 131 + q + 0] = v.x; sw[r * 131 + q + 1] = v.y;
            sw[r * 131 + q + 2] = v.z; sw[r * 131 + q + 3] = v.w;
        }
        __syncthreads();
#pragma unroll 4
        for (int k = 0; k < 128; k++) {
            float x0 = sx[rr0 * 132 + k];
            float x1 = sx[(rr0 + 1) * 132 + k];
            float w0 = sw[(hh0 + 0) * 131 + k];
            float w1 = sw[(hh0 + 1) * 131 + k];
            float w2 = sw[(hh0 + 2) * 131 + k];
            float w3 = sw[(hh0 + 3) * 131 + k];
            acc[0][0] = fmaf(x0, w0, acc[0][0]);
            acc[0][1] = fmaf(x0, w1, acc[0][1]);
            acc[0][2] = fmaf(x0, w2, acc[0][2]);
            acc[0][3] = fmaf(x0, w3, acc[0][3]);
            acc[1][0] = fmaf(x1, w0, acc[1][0]);
            acc[1][1] = fmaf(x1, w1, acc[1][1]);
            acc[1][2] = fmaf(x1, w2, acc[1][2]);
            acc[1][3] = fmaf(x1, w3, acc[1][3]);
        }
        __syncthreads();
    }
#pragma unroll
    for (int i = 0; i < 2; i++) {
        int ml = r0 + rr0 + i;
#pragma unroll
        for (int j = 0; j < 4; j++) {
            int h = hh0 + j;
            float raw = acc[i][j] + dt_bias[h];
            float sp = (raw > 20.f) ? raw : log1pf(expf(raw));   // exact (decay-critical)
            g_dt[ml * Hh + h] = sp;
            g_adt[ml * Hh + h] = -expf(A_log[h]) * sp;
        }
    }
}

// ------------- causal depthwise conv + double silu (smem-tiled) -------------
__device__ __forceinline__ float silu_f(float x) { return x / (1.f + __expf(-x)); }

__global__ __launch_bounds__(256) void conv_kernel(const float* __restrict__ conv_w)
{
    __shared__ float sxm[35][132];
    int cc = blockIdx.x;
    int ytile = blockIdx.y;
    int b = ytile >> 6;
    int l0 = (ytile & 63) * 32;
    int tid = threadIdx.x;
    int ch_base = cc * 128;

    for (int t = tid; t < 35 * 32; t += 256) {
        int r = t >> 5, q = (t & 31) * 4;
        int ls = l0 - 3 + r;
        float4 v = make_float4(0.f, 0.f, 0.f, 0.f);
        if (ls >= 0 && r < 32 + 3)
            v = *(const float4*)(g_zxbcdt + ((size_t)(b * Lseq + ls)) * PROJ + DI + ch_base + q);
        *(float4*)(&sxm[r][q]) = v;
    }
    __syncthreads();

    int tx = tid & 31, ty = tid >> 5;
    int ch4 = tx * 4;
    float4 w0 = *(const float4*)(conv_w + (ch_base + ch4 + 0) * 4);
    float4 w1 = *(const float4*)(conv_w + (ch_base + ch4 + 1) * 4);
    float4 w2 = *(const float4*)(conv_w + (ch_base + ch4 + 2) * 4);
    float4 w3 = *(const float4*)(conv_w + (ch_base + ch4 + 3) * 4);
#pragma unroll
    for (int li = 0; li < 4; li++) {
        int lloc = ty * 4 + li;
        float a0 = 0.f, a1 = 0.f, a2 = 0.f, a3 = 0.f;
#pragma unroll
        for (int j = 0; j < 4; j++) {
            const float* row = &sxm[lloc + j][ch4];
            a0 = fmaf(row[0], (&w0.x)[j], a0);
            a1 = fmaf(row[1], (&w1.x)[j], a1);
            a2 = fmaf(row[2], (&w2.x)[j], a2);
            a3 = fmaf(row[3], (&w3.x)[j], a3);
        }
        float4 o;
        o.x = silu_f(silu_f(a0));
        o.y = silu_f(silu_f(a1));
        o.z = silu_f(silu_f(a2));
        o.w = silu_f(silu_f(a3));
        *(float4*)(g_xbc + (size_t)(b * Lseq + l0 + lloc) * CONVD + ch_base + ch4) = o;
    }
}

// ------------- G = C * B^T per (b,c), 4-way split over l --------------------
__global__ __launch_bounds__(256) void gmat_kernel()
{
    int c = blockIdx.x, b = blockIdx.y, z = blockIdx.z;
    __shared__ float sB[64][33];
    __shared__ float sC[16][33];
    int tid = threadIdx.x;
    int tx = tid & 15, ty = tid >> 4;
    int lloc = ty, s0 = tx * 4;
    size_t rowbase = (size_t)(b * Lseq + c * CHK);
    int lg = z * 16;
    float g4[4] = {0.f, 0.f, 0.f, 0.f};

    for (int nc = 0; nc < Nn; nc += 32) {
        for (int t = tid; t < 64 * 8; t += 256) {
            int l = t >> 3, q = (t & 7) * 4;
            float4 bv = *(const float4*)(g_xbc + (rowbase + l) * CONVD + DI + nc + q);
            sB[l][q + 0] = bv.x; sB[l][q + 1] = bv.y;
            sB[l][q + 2] = bv.z; sB[l][q + 3] = bv.w;
        }
        if (tid < 16 * 8) {
            int l = tid >> 3, q = (tid & 7) * 4;
            float4 cv = *(const float4*)(g_xbc + (rowbase + lg + l) * CONVD + DI + Nn + nc + q);
            sC[l][q + 0] = cv.x; sC[l][q + 1] = cv.y;
            sC[l][q + 2] = cv.z; sC[l][q + 3] = cv.w;
        }
        __syncthreads();
#pragma unroll
        for (int n = 0; n < 32; n++) {
            float cr = sC[lloc][n];
            g4[0] = fmaf(cr, sB[s0 + 0][n], g4[0]);
            g4[1] = fmaf(cr, sB[s0 + 1][n], g4[1]);
            g4[2] = fmaf(cr, sB[s0 + 2][n], g4[2]);
            g4[3] = fmaf(cr, sB[s0 + 3][n], g4[3]);
        }
        __syncthreads();
    }
    float* Gp = g_G + ((size_t)(b * NCHUNK + c)) * (CHK * CHK);
    float4 v = make_float4(g4[0], g4[1], g4[2], g4[3]);
    *(float4*)(Gp + (lg + lloc) * 64 + s0) = v;
}

// -------------- per-chunk SSD via tensor cores (fp16 mma) -------------------
__global__ __launch_bounds__(256) void chunk_kernel()
{
    __shared__ __half sM[64][72];
    __shared__ __half sX[64][72];
    __shared__ __half sXd[64][72];
    __shared__ __half sB[64][136];
    __shared__ float scs[64];
    __shared__ float sDec[64];
    int c = blockIdx.x, h = blockIdx.y, b = blockIdx.z;
    int tid = threadIdx.x, lane = tid & 31, wid = tid >> 5;
    size_t rowbase = (size_t)(b * Lseq + c * CHK);

    if (wid == 0) {
        float v0 = g_adt[(rowbase + lane) * Hh + h];
        float v1 = g_adt[(rowbase + 32 + lane) * Hh + h];
#pragma unroll
        for (int off = 1; off < 32; off <<= 1) {
            float t = __shfl_up_sync(0xFFFFFFFF, v0, off);
            if (lane >= off) v0 += t;
        }
        float tot = __shfl_sync(0xFFFFFFFF, v0, 31);
#pragma unroll
        for (int off = 1; off < 32; off <<= 1) {
            float t = __shfl_up_sync(0xFFFFFFFF, v1, off);
            if (lane >= off) v1 += t;
        }
        v1 += tot;
        float alast = __shfl_sync(0xFFFFFFFF, v1, 31);
        scs[lane] = v0;
        scs[32 + lane] = v1;
        sDec[lane] = __expf(alast - v0);
        sDec[32 + lane] = __expf(alast - v1);
    }
    for (int i = tid; i < 64 * 32; i += 256) {
        int l = i >> 5, q = (i & 31) * 4;
        float4 v = *(const float4*)(g_xbc + (rowbase + l) * CONVD + DI + q);
        sB[l][q + 0] = __float2half_rn(v.x);
        sB[l][q + 1] = __float2half_rn(v.y);
        sB[l][q + 2] = __float2half_rn(v.z);
        sB[l][q + 3] = __float2half_rn(v.w);
    }
    __syncthreads();

    for (int i = tid; i < 64 * 16; i += 256) {
        int l = i >> 4, q = (i & 15) * 4;
        float4 v = *(const float4*)(g_xbc + (rowbase + l) * CONVD + h * 64 + q);
        float d = g_dt[(rowbase + l) * Hh + h];
        float e = sDec[l];
        float x0 = v.x * d, x1 = v.y * d, x2 = v.z * d, x3 = v.w * d;
        sX[l][q + 0] = __float2half_rn(x0);
        sX[l][q + 1] = __float2half_rn(x1);
        sX[l][q + 2] = __float2half_rn(x2);
        sX[l][q + 3] = __float2half_rn(x3);
        sXd[l][q + 0] = __float2half_rn(x0 * e);
        sXd[l][q + 1] = __float2half_rn(x1 * e);
        sXd[l][q + 2] = __float2half_rn(x2 * e);
        sXd[l][q + 3] = __float2half_rn(x3 * e);
    }
    {
        int tx = tid & 15, ty = tid >> 4;
        int l0 = ty * 4, s0 = tx * 4;
        const float* Gp = g_G + ((size_t)(b * NCHUNK + c)) * (CHK * CHK);
#pragma unroll
        for (int i = 0; i < 4; i++) {
            int l = l0 + i;
            if (s0 > l) {
                sM[l][s0 + 0] = __float2half_rn(0.f);
                sM[l][s0 + 1] = __float2half_rn(0.f);
                sM[l][s0 + 2] = __float2half_rn(0.f);
                sM[l][s0 + 3] = __float2half_rn(0.f);
            } else {
                float4 gv = *(const float4*)(Gp + l * 64 + s0);
                float csl = scs[l];
                if (s0 + 3 <= l) {
                    sM[l][s0 + 0] = __float2half_rn(gv.x * __expf(csl - scs[s0 + 0]));
                    sM[l][s0 + 1] = __float2half_rn(gv.y * __expf(csl - scs[s0 + 1]));
                    sM[l][s0 + 2] = __float2half_rn(gv.z * __expf(csl - scs[s0 + 2]));
                    sM[l][s0 + 3] = __float2half_rn(gv.w * __expf(csl - scs[s0 + 3]));
                } else {
                    sM[l][s0 + 0] = __float2half_rn((s0 + 0 <= l) ? gv.x * __expf(csl - scs[s0 + 0]) : 0.f);
                    sM[l][s0 + 1] = __float2half_rn((s0 + 1 <= l) ? gv.y * __expf(csl - scs[s0 + 1]) : 0.f);
                    sM[l][s0 + 2] = __float2half_rn((s0 + 2 <= l) ? gv.z * __expf(csl - scs[s0 + 2]) : 0.f);
                    sM[l][s0 + 3] = __float2half_rn((s0 + 3 <= l) ? gv.w * __expf(csl - scs[s0 + 3]) : 0.f);
                }
            }
        }
    }
    __syncthreads();

    int gp = lane >> 2, tg = lane & 3;
    {
        int wm = wid & 3, wn = wid >> 2;
        float cy[4][4];
#pragma unroll
        for (int i = 0; i < 4; i++)
#pragma unroll
            for (int j = 0; j < 4; j++) cy[i][j] = 0.f;
#pragma unroll
        for (int k0 = 0; k0 < 64; k0 += 16) {
            uint32_t a[4];
            ldmx4(a, smem_to_u32(&sM[wm * 16 + (lane & 15)][k0 + ((lane >> 4) << 3)]));
#pragma unroll
            for (int g = 0; g < 2; g++) {
                uint32_t bf[4];
                ldmx4t(bf, smem_to_u32(&sX[k0 + (lane & 15)][wn * 32 + g * 16 + ((lane >> 4) << 3)]));
                mma16816h(cy[g * 2 + 0], a, bf[0], bf[1]);
                mma16816h(cy[g * 2 + 1], a, bf[2], bf[3]);
            }
        }
#pragma unroll
        for (int nb = 0; nb < 4; nb++) {
            int p = wn * 32 + nb * 8 + tg * 2;
#pragma unroll
            for (int hf = 0; hf < 2; hf++) {
                int l = wm * 16 + gp + hf * 8;
                float2 v = make_float2(cy[nb][hf * 2 + 0], cy[nb][hf * 2 + 1]);
                *(float2*)(g_Y + (rowbase + l) * DI + h * 64 + p) = v;
            }
        }
    }

    {
        int pmw = wid & 3, nw = wid >> 2;
        int p0 = pmw * 16, n0 = nw * 64;
        float cs2[8][4];
#pragma unroll
        for (int i = 0; i < 8; i++)
#pragma unroll
            for (int j = 0; j < 4; j++) cs2[i][j] = 0.f;
#pragma unroll
        for (int k0 = 0; k0 < 64; k0 += 16) {
            uint32_t r[4];
            ldmx4t(r, smem_to_u32(&sXd[k0 + (lane & 15)][p0 + ((lane >> 4) << 3)]));
            uint32_t a[4] = {r[0], r[2], r[1], r[3]};
#pragma unroll
            for (int g = 0; g < 4; g++) {
                uint32_t bf[4];
                ldmx4t(bf, smem_to_u32(&sB[k0 + (lane & 15)][n0 + g * 16 + ((lane >> 4) << 3)]));
                mma16816h(cs2[g * 2 + 0], a, bf[0], bf[1]);
                mma16816h(cs2[g * 2 + 1], a, bf[2], bf[3]);
            }
        }
        size_t sbase = (((size_t)(b * NCHUNK + c)) * Hh + h) * (Pp * Nn);
#pragma unroll
        for (int nb = 0; nb < 8; nb++) {
            int n = n0 + nb * 8 + tg * 2;
#pragma unroll
            for (int hf = 0; hf < 2; hf++) {
                int p = p0 + gp + hf * 8;
                float2 v = make_float2(cs2[nb][hf * 2 + 0], cs2[nb][hf * 2 + 1]);
                *(float2*)(g_states + sbase + (size_t)p * Nn + n) = v;
            }
        }
    }

    if (tid < 64) g_cs[((b * NCHUNK + c) * Hh + h) * CHK + tid] = expf(scs[tid]);
    if (tid == 0) g_lastA[(b * NCHUNK + c) * Hh + h] = expf(scs[63]);
}

// ---------- inter-chunk scan, 8-way sliced, float4 (dec pre-exp'd) ----------
__global__ __launch_bounds__(256) void scan_kernel(const float* __restrict__ init_state,
                                                   float* __restrict__ fstate_out)
{
    int bh = blockIdx.x;
    int h = bh & (Hh - 1), b = bh >> 5;
    int off = blockIdx.y * 1024 + threadIdx.x * 4;
    size_t ibase = ((size_t)(b * Hh + h)) * (Pp * Nn);
    float4 run = *(const float4*)(init_state + ibase + off);
    for (int c = 0; c < NCHUNK; c++) {
        float dec = g_lastA[(b * NCHUNK + c) * Hh + h];
        size_t idx = (((size_t)(b * NCHUNK + c)) * Hh + h) * (Pp * Nn) + off;
        float4 v = *(const float4*)(g_states + idx);
        *(float4*)(g_states + idx) = run;
        run.x = fmaf(dec, run.x, v.x);
        run.y = fmaf(dec, run.y, v.y);
        run.z = fmaf(dec, run.z, v.z);
        run.w = fmaf(dec, run.w, v.w);
    }
    *(float4*)(fstate_out + ibase + off) = run;
}

// --------------- Y_off + D*X epilogue via tensor cores (cs pre-exp'd) -------
__global__ __launch_bounds__(256) void yoff_kernel(const float* __restrict__ D_param)
{
    __shared__ __half sC[64][136];
    __shared__ __half sS[64][136];
    __shared__ float scs[64];
    int c = blockIdx.x, h = blockIdx.y, b = blockIdx.z;
    int tid = threadIdx.x, lane = tid & 31, wid = tid >> 5;
    size_t rowbase = (size_t)(b * Lseq + c * CHK);
    if (tid < 64) scs[tid] = g_cs[((b * NCHUNK + c) * Hh + h) * CHK + tid];

    size_t sbase = (((size_t)(b * NCHUNK + c)) * Hh + h) * (Pp * Nn);
    for (int t = tid; t < 64 * 32; t += 256) {
        int r = t >> 5, q = (t & 31) * 4;
        float4 cv = *(const float4*)(g_xbc + (rowbase + r) * CONVD + DI + Nn + q);
        sC[r][q + 0] = __float2half_rn(cv.x);
        sC[r][q + 1] = __float2half_rn(cv.y);
        sC[r][q + 2] = __float2half_rn(cv.z);
        sC[r][q + 3] = __float2half_rn(cv.w);
        float4 sv = *(const float4*)(g_states + sbase + (size_t)r * Nn + q);
        sS[r][q + 0] = __float2half_rn(sv.x);
        sS[r][q + 1] = __float2half_rn(sv.y);
        sS[r][q + 2] = __float2half_rn(sv.z);
        sS[r][q + 3] = __float2half_rn(sv.w);
    }
    __syncthreads();

    int wm = wid & 3, wn = wid >> 2;
    int l0 = wm * 16, p0 = wn * 32;
    float acc[4][4];
#pragma unroll
    for (int i = 0; i < 4; i++)
#pragma unroll
        for (int j = 0; j < 4; j++) acc[i][j] = 0.f;

#pragma unroll
    for (int k0 = 0; k0 < Nn; k0 += 16) {
        uint32_t a[4];
        ldmx4(a, smem_to_u32(&sC[l0 + (lane & 15)][k0 + ((lane >> 4) << 3)]));
        uint32_t bf[2][4];
#pragma unroll
        for (int g = 0; g < 2; g++)
            ldmx4(bf[g], smem_to_u32(
                &sS[p0 + g * 16 + (((lane >> 3) & 1) << 3) + (lane & 7)][k0 + ((lane >> 4) << 3)]));
#pragma unroll
        for (int nb = 0; nb < 4; nb++) {
            int ib = nb >> 1, wh = nb & 1;
            mma16816h(acc[nb], a, bf[ib][wh], bf[ib][2 + wh]);
        }
    }
    float Dh = D_param[h];
    int gp = lane >> 2, tg = lane & 3;
#pragma unroll
    for (int nb = 0; nb < 4; nb++) {
        int p = p0 + nb * 8 + tg * 2;
#pragma unroll
        for (int hf = 0; hf < 2; hf++) {
            int l = l0 + gp + hf * 8;
            float e = scs[l];
            size_t gi = (rowbase + l) * DI + h * 64 + p;
            float2 yv = *(const float2*)(g_Y + gi);
            float2 xv = *(const float2*)(g_xbc + (rowbase + l) * CONVD + h * 64 + p);
            yv.x += e * acc[nb][hf * 2 + 0] + Dh * xv.x;
            yv.y += e * acc[nb][hf * 2 + 1] + Dh * xv.y;
            *(float2*)(g_Y + gi) = yv;
        }
    }
}

// -------- RMSNorm * norm_w * sigmoid(z) -> fp16 y_core (float4) --------------
__global__ __launch_bounds__(256) void rms_cvt_kernel(const float* __restrict__ norm_w)
{
    int row = blockIdx.x;
    int tid = threadIdx.x, lane = tid & 31, wid = tid >> 5;
    __shared__ float red[8];
    const float* y = g_Y + (size_t)row * DI;
    float ss = 0.f;
#pragma unroll
    for (int it = 0; it < 2; it++) {
        int j = (tid + it * 256) * 4;
        float4 v = *(const float4*)(y + j);
        ss = fmaf(v.x, v.x, ss);
        ss = fmaf(v.y, v.y, ss);
        ss = fmaf(v.z, v.z, ss);
        ss = fmaf(v.w, v.w, ss);
    }
#pragma unroll
    for (int off = 16; off > 0; off >>= 1) ss += __shfl_xor_sync(0xFFFFFFFF, ss, off);
    if (lane == 0) red[wid] = ss;
    __syncthreads();
    if (wid == 0) {
        float v = (lane < 8) ? red[lane] : 0.f;
#pragma unroll
        for (int off = 4; off > 0; off >>= 1) v += __shfl_xor_sync(0xFFFFFFFF, v, off);
        if (lane == 0) red[0] = v;
    }
    __syncthreads();
    float scale = rsqrtf(red[0] / (float)DI + EPSV);
    __half* ph = g_ych + (size_t)row * DI;
#pragma unroll
    for (int it = 0; it < 2; it++) {
        int j = (tid + it * 256) * 4;
        float4 yv = *(const float4*)(y + j);
        float4 zv = *(const float4*)(g_zxbcdt + (size_t)row * PROJ + j);
        __half2 h0, h1;
        h0.x = __float2half_rn(yv.x * scale * norm_w[j + 0] / (1.f + __expf(-zv.x)));
        h0.y = __float2half_rn(yv.y * scale * norm_w[j + 1] / (1.f + __expf(-zv.y)));
        h1.x = __float2half_rn(yv.z * scale * norm_w[j + 2] / (1.f + __expf(-zv.z)));
        h1.y = __float2half_rn(yv.w * scale * norm_w[j + 3] / (1.f + __expf(-zv.w)));
        *(__half2*)(ph + j) = h0;
        *(__half2*)(ph + j + 2) = h1;
    }
}

// ------------------------- launch ------------------------------------------
extern "C" void kernel_launch(void* const* d_in, const int* in_sizes, int n_in,
                              void* d_out, int out_size)
{
    const float* x         = (const float*)d_in[0];
    const float* state     = (const float*)d_in[1];
    const float* in_proj_w = (const float*)d_in[2];
    const float* conv_w    = (const float*)d_in[3];
    const float* A_log     = (const float*)d_in[4];
    const float* dt_bias   = (const float*)d_in[5];
    const float* D_param   = (const float*)d_in[6];
    const float* norm_w    = (const float*)d_in[7];
    const float* out_proj_w= (const float*)d_in[8];
    float* out = (float*)d_out;

    float* zx;   cudaGetSymbolAddress((void**)&zx, g_zxbcdt);
    __half *xh, *wih, *ych, *woh;
    cudaGetSymbolAddress((void**)&xh, g_xh);
    cudaGetSymbolAddress((void**)&wih, g_wih);
    cudaGetSymbolAddress((void**)&ych, g_ych);
    cudaGetSymbolAddress((void**)&woh, g_woh);

    cudaFuncSetAttribute(gemm_fp16, cudaFuncAttributeMaxDynamicSharedMemorySize, GSMEM_BYTES);
    cudaFuncSetAttribute(dtfix_kernel, cudaFuncAttributeMaxDynamicSharedMemorySize, DTSM_BYTES);

    // side streams + events (created once; idempotent infra setup)
    static cudaStream_t s1 = nullptr, s2 = nullptr;
    static cudaEvent_t ev_root = nullptr, ev_cvt = nullptr, ev_p2 = nullptr, ev_dt = nullptr;
    if (!s1) {
        cudaStreamCreateWithFlags(&s1, cudaStreamNonBlocking);
        cudaStreamCreateWithFlags(&s2, cudaStreamNonBlocking);
        cudaEventCreateWithFlags(&ev_root, cudaEventDisableTiming);
        cudaEventCreateWithFlags(&ev_cvt, cudaEventDisableTiming);
        cudaEventCreateWithFlags(&ev_p2, cudaEventDisableTiming);
        cudaEventCreateWithFlags(&ev_dt, cudaEventDisableTiming);
    }

    // fork root for dtfix (depends only on raw inputs)
    cudaEventRecord(ev_root, 0);
    cudaStreamWaitEvent(s2, ev_root, 0);
    dtfix_kernel<<<ML / 64, 256, DTSM_BYTES, s2>>>(x, in_proj_w, A_log, dt_bias);
    cudaEventRecord(ev_dt, s2);

    // 1) merged fp16 converts (main)
    {
        size_t total = CVT_NX + CVT_NW + CVT_NWO;
        cvt_all_kernel<<<(unsigned)((total + 255) / 256), 256>>>(x, in_proj_w, out_proj_w);
    }
    cudaEventRecord(ev_cvt, 0);

    // 2a) in_proj GEMM part1: columns [DI, PROJPAD) — feeds conv (main)
    gemm_fp16<<<dim3((PROJPAD - DI) / 128, ML / 128), 256, GSMEM_BYTES>>>(
        xh, wih, nullptr, zx, DM, PROJ, DI);
    // 2b) in_proj GEMM part2: z columns [0, DI) — forked, overlaps SSD chain
    cudaStreamWaitEvent(s1, ev_cvt, 0);
    gemm_fp16<<<dim3(DI / 128, ML / 128), 256, GSMEM_BYTES, s1>>>(
        xh, wih, nullptr, zx, DM, PROJ, 0);
    cudaEventRecord(ev_p2, s1);

    // 3) conv + double silu (main, after part1)
    conv_kernel<<<dim3(CONVD / 128, Bsz * (Lseq / 32)), 256>>>(conv_w);
    // 4) G = C B^T once per (b,c)
    gmat_kernel<<<dim3(NCHUNK, Bsz, 4), 256>>>();
    // 5) per-chunk SSD (needs dtfix)
    cudaStreamWaitEvent(0, ev_dt, 0);
    chunk_kernel<<<dim3(NCHUNK, Hh, Bsz), 256>>>();
    // 6) inter-chunk scan + final state
    scan_kernel<<<dim3(Bsz * Hh, 8), 256>>>(state, out + (size_t)ML * DM);
    // 7) Y_off + D*X
    yoff_kernel<<<dim3(NCHUNK, Hh, Bsz), 256>>>(D_param);
    // 8) RMSNorm + gate + fp16 convert (needs z from gemm part2)
    cudaStreamWaitEvent(0, ev_p2, 0);
    rms_cvt_kernel<<<ML, 256>>>(norm_w);
    // 9) out_proj GEMM + residual -> d_out
    gemm_fp16<<<dim3(DM / 128, ML / 128), 256, GSMEM_BYTES>>>(
        ych, woh, x, out, DI, DM, 0);
}

// round 17
// speedup vs baseline: 1.2707x; 1.0005x over previous
#include <cuda_runtime.h>
#include <cuda_bf16.h>
#include <cuda_fp16.h>
#include <cstdint>

// Problem constants
#define Bsz 2
#define Lseq 2048
#define DM 1024
#define DI 2048          // d_inner
#define Hh 32            // heads
#define Pp 64            // headdim
#define Nn 128           // d_state
#define CONVD 2304       // conv_dim = d_inner + 2*N
#define PROJ 4384        // 2*DI + 2*N + H
#define PROJPAD 4480     // 35*128
#define CHK 64           // block_len
#define NCHUNK 32        // L / CHK
#define ML (Bsz*Lseq)    // 4096 rows
#define EPSV 1.1920929e-07f

// ------------------------- scratch (device globals) -------------------------
__device__ float g_zxbcdt[(size_t)ML * PROJ];
__device__ float g_xbc[(size_t)ML * CONVD];
__device__ float g_dt[(size_t)ML * Hh];
__device__ float g_adt[(size_t)ML * Hh];
__device__ float g_Y[(size_t)ML * DI];
__device__ float g_states[(size_t)Bsz * NCHUNK * Hh * Pp * Nn];
__device__ float g_lastA[Bsz * NCHUNK * Hh];           // stores exp(lastA)
__device__ float g_cs[Bsz * NCHUNK * Hh * CHK];        // stores exp(cs)
__device__ float g_G[(size_t)Bsz * NCHUNK * CHK * CHK];

// fp16 buffers
__device__ __half g_xh[(size_t)ML * DM];
__device__ __half g_wih[(size_t)PROJPAD * DM];
__device__ __half g_ych[(size_t)ML * DI];
__device__ __half g_woh[(size_t)DM * DI];

// ------------------------- helpers ------------------------------------------
__device__ __forceinline__ uint32_t smem_to_u32(const void* p) {
    uint32_t a;
    asm("{ .reg .u64 t; cvta.to.shared.u64 t, %1; cvt.u32.u64 %0, t; }" : "=r"(a) : "l"(p));
    return a;
}
__device__ __forceinline__ void ldmx4(uint32_t* r, uint32_t addr) {
    asm volatile("ldmatrix.sync.aligned.m8n8.x4.shared.b16 {%0,%1,%2,%3}, [%4];"
                 : "=r"(r[0]), "=r"(r[1]), "=r"(r[2]), "=r"(r[3]) : "r"(addr));
}
__device__ __forceinline__ void ldmx4t(uint32_t* r, uint32_t addr) {
    asm volatile("ldmatrix.sync.aligned.m8n8.x4.trans.shared.b16 {%0,%1,%2,%3}, [%4];"
                 : "=r"(r[0]), "=r"(r[1]), "=r"(r[2]), "=r"(r[3]) : "r"(addr));
}
__device__ __forceinline__ void mma16816h(float* c, const uint32_t* a,
                                          uint32_t b0, uint32_t b1) {
    asm volatile("mma.sync.aligned.m16n8k16.row.col.f32.f16.f16.f32 "
                 "{%0,%1,%2,%3}, {%4,%5,%6,%7}, {%8,%9}, {%0,%1,%2,%3};"
                 : "+f"(c[0]), "+f"(c[1]), "+f"(c[2]), "+f"(c[3])
                 : "r"(a[0]), "r"(a[1]), "r"(a[2]), "r"(a[3]), "r"(b0), "r"(b1));
}
__device__ __forceinline__ void cpasync16(uint32_t dst, const void* src) {
    asm volatile("cp.async.cg.shared.global [%0], [%1], 16;" :: "r"(dst), "l"(src));
}
#define CP_COMMIT() asm volatile("cp.async.commit_group;" ::: "memory")
#define CP_WAIT(n)  asm volatile("cp.async.wait_group %0;" :: "n"(n) : "memory")

// ------------------- fp16 converts (split) ----------------------------------
#define CVT_NX  ((size_t)ML * DM)
#define CVT_NW  ((size_t)PROJPAD * DM)
#define CVT_NWO ((size_t)DM * DI)
__global__ void cvt_xw_kernel(const float* __restrict__ x,
                              const float* __restrict__ w_in)
{
    size_t i = (size_t)blockIdx.x * blockDim.x + threadIdx.x;
    if (i < CVT_NX) {
        g_xh[i] = __float2half_rn(x[i]);
    } else if (i < CVT_NX + CVT_NW) {
        size_t j = i - CVT_NX;
        int r = (int)(j / DM);
        g_wih[j] = __float2half_rn((r < PROJ) ? w_in[j] : 0.f);
    }
}
__global__ void cvt_wo_kernel(const float* __restrict__ w_out)
{
    size_t i = (size_t)blockIdx.x * blockDim.x + threadIdx.x;
    if (i < CVT_NWO) g_woh[i] = __float2half_rn(w_out[i]);
}

// ---------------- fp16 mma.sync GEMM (128x128 tile, BK=64, n-offset) --------
#define SROW 72             // 64 fp16 + 8 pad
#define GST  (128 * SROW)
#define GSMEM_BYTES (2 * 2 * GST * 2)

__global__ __launch_bounds__(256) void gemm_fp16(
    const __half* __restrict__ A, const __half* __restrict__ Bw,
    const float* __restrict__ res, float* __restrict__ C,
    int K, int Nstore, int n0)
{
    extern __shared__ __align__(16) __half gsm[];
    int tid = threadIdx.x;
    int lane = tid & 31, wid = tid >> 5;
    int warp_m = wid >> 1, warp_n = wid & 1;
    int bn = n0 + blockIdx.x * 128;
    int bm = blockIdx.y * 128;

    int NC = K >> 6;

    float c[2][8][4];
#pragma unroll
    for (int i = 0; i < 2; i++)
#pragma unroll
        for (int j = 0; j < 8; j++)
#pragma unroll
            for (int q = 0; q < 4; q++) c[i][j][q] = 0.f;

    auto load_chunk = [&](int ci, int s) {
        int kk = ci * 64;
#pragma unroll
        for (int it = 0; it < 8; it++) {
            int t = tid + it * 256;
            int tile = t >> 10;
            int idx = t & 1023;
            int row = idx >> 3;
            int sg = idx & 7;
            const __half* src = tile ? (Bw + (size_t)(bn + row) * K + kk + sg * 8)
                                     : (A + (size_t)(bm + row) * K + kk + sg * 8);
            uint32_t dst = smem_to_u32(gsm + (size_t)(s * 2 + tile) * GST + row * SROW + sg * 8);
            cpasync16(dst, src);
        }
        CP_COMMIT();
    };

    load_chunk(0, 0);
    for (int ci = 0; ci < NC; ci++) {
        int s = ci & 1;
        if (ci + 1 < NC) { load_chunk(ci + 1, s ^ 1); CP_WAIT(1); }
        else CP_WAIT(0);
        __syncthreads();

        uint32_t a_base = smem_to_u32(gsm + (size_t)(s * 2 + 0) * GST);
        uint32_t b_base = smem_to_u32(gsm + (size_t)(s * 2 + 1) * GST);
#pragma unroll
        for (int k0 = 0; k0 < 64; k0 += 16) {
            uint32_t a[2][4];
#pragma unroll
            for (int im = 0; im < 2; im++) {
                uint32_t addr = a_base
                    + (uint32_t)(warp_m * 32 + im * 16 + (lane & 15)) * (SROW * 2)
                    + (uint32_t)(k0 + ((lane >> 4) << 3)) * 2;
                ldmx4(a[im], addr);
            }
            uint32_t bf[4][4];
#pragma unroll
            for (int ib = 0; ib < 4; ib++) {
                uint32_t addr = b_base
                    + (uint32_t)(warp_n * 64 + ib * 16 + (((lane >> 3) & 1) << 3) + (lane & 7)) * (SROW * 2)
                    + (uint32_t)(k0 + ((lane >> 4) << 3)) * 2;
                ldmx4(bf[ib], addr);
            }
#pragma unroll
            for (int im = 0; im < 2; im++)
#pragma unroll
                for (int in = 0; in < 8; in++) {
                    int ib = in >> 1, wh = in & 1;
                    mma16816h(c[im][in], a[im], bf[ib][wh], bf[ib][2 + wh]);
                }
        }
        __syncthreads();
    }

    int gp = lane >> 2, tg = lane & 3;
#pragma unroll
    for (int im = 0; im < 2; im++) {
        int m0 = bm + warp_m * 32 + im * 16;
#pragma unroll
        for (int in = 0; in < 8; in++) {
            int n = bn + warp_n * 64 + in * 8 + tg * 2;
            if (n >= Nstore) continue;
#pragma unroll
            for (int half = 0; half < 2; half++) {
                int m = m0 + gp + half * 8;
                float2 v;
                v.x = c[im][in][half * 2 + 0];
                v.y = c[im][in][half * 2 + 1];
                if (res) {
                    const float2 rv = *(const float2*)(res + (size_t)m * Nstore + n);
                    v.x += rv.x; v.y += rv.y;
                }
                *(float2*)(C + (size_t)m * Nstore + n) = v;
            }
        }
    }
}

// ----------------- exact fp32 dt GEMM: 64 blocks x 64 rows ------------------
#define DTS_X   0
#define DTS_W   (64 * 132)
#define DTSM_BYTES ((64 * 132 + 32 * 131) * 4)

__global__ __launch_bounds__(256) void dtfix_kernel(
    const float* __restrict__ x, const float* __restrict__ in_proj_w,
    const float* __restrict__ A_log, const float* __restrict__ dt_bias)
{
    extern __shared__ float dts[];
    float* sx = dts + DTS_X;
    float* sw = dts + DTS_W;
    int r0 = blockIdx.x * 64;
    int tid = threadIdx.x;
    int hg = tid & 7, rg = tid >> 3;
    int rr0 = rg * 2, hh0 = hg * 4;
    float acc[2][4];
#pragma unroll
    for (int i = 0; i < 2; i++)
#pragma unroll
        for (int j = 0; j < 4; j++) acc[i][j] = 0.f;

    for (int kc = 0; kc < 8; kc++) {
        int k0 = kc * 128;
        for (int t = tid; t < 2048; t += 256) {
            int r = t >> 5, q = (t & 31) * 4;
            float4 v = *(const float4*)(x + (size_t)(r0 + r) * DM + k0 + q);
            *(float4*)(sx + r * 132 + q) = v;
        }
        for (int t = tid; t < 1024; t += 256) {
            int r = t >> 5, q = (t & 31) * 4;
            float4 v = *(const float4*)(in_proj_w + (size_t)(DI + CONVD + r) * DM + k0 + q);
            sw[r * 131 + q + 0] = v.x; sw[r * 131 + q + 1] = v.y;
            sw[r * 131 + q + 2] = v.z; sw[r * 131 + q + 3] = v.w;
        }
        __syncthreads();
#pragma unroll 4
        for (int k = 0; k < 128; k++) {
            float x0 = sx[rr0 * 132 + k];
            float x1 = sx[(rr0 + 1) * 132 + k];
            float w0 = sw[(hh0 + 0) * 131 + k];
            float w1 = sw[(hh0 + 1) * 131 + k];
            float w2 = sw[(hh0 + 2) * 131 + k];
            float w3 = sw[(hh0 + 3) * 131 + k];
            acc[0][0] = fmaf(x0, w0, acc[0][0]);
            acc[0][1] = fmaf(x0, w1, acc[0][1]);
            acc[0][2] = fmaf(x0, w2, acc[0][2]);
            acc[0][3] = fmaf(x0, w3, acc[0][3]);
            acc[1][0] = fmaf(x1, w0, acc[1][0]);
            acc[1][1] = fmaf(x1, w1, acc[1][1]);
            acc[1][2] = fmaf(x1, w2, acc[1][2]);
            acc[1][3] = fmaf(x1, w3, acc[1][3]);
        }
        __syncthreads();
    }
#pragma unroll
    for (int i = 0; i < 2; i++) {
        int ml = r0 + rr0 + i;
#pragma unroll
        for (int j = 0; j < 4; j++) {
            int h = hh0 + j;
            float raw = acc[i][j] + dt_bias[h];
            float sp = (raw > 20.f) ? raw : log1pf(expf(raw));   // exact (decay-critical)
            g_dt[ml * Hh + h] = sp;
            g_adt[ml * Hh + h] = -expf(A_log[h]) * sp;
        }
    }
}

// ------- causal depthwise conv + double silu (smem-tiled, channel range) ----
__device__ __forceinline__ float silu_f(float x) { return x / (1.f + __expf(-x)); }

__global__ __launch_bounds__(256) void conv_kernel(const float* __restrict__ conv_w,
                                                   int cc_base)
{
    __shared__ float sxm[35][132];
    int cc = cc_base + blockIdx.x;
    int ytile = blockIdx.y;
    int b = ytile >> 6;
    int l0 = (ytile & 63) * 32;
    int tid = threadIdx.x;
    int ch_base = cc * 128;

    for (int t = tid; t < 35 * 32; t += 256) {
        int r = t >> 5, q = (t & 31) * 4;
        int ls = l0 - 3 + r;
        float4 v = make_float4(0.f, 0.f, 0.f, 0.f);
        if (ls >= 0 && r < 32 + 3)
            v = *(const float4*)(g_zxbcdt + ((size_t)(b * Lseq + ls)) * PROJ + DI + ch_base + q);
        *(float4*)(&sxm[r][q]) = v;
    }
    __syncthreads();

    int tx = tid & 31, ty = tid >> 5;
    int ch4 = tx * 4;
    float4 w0 = *(const float4*)(conv_w + (ch_base + ch4 + 0) * 4);
    float4 w1 = *(const float4*)(conv_w + (ch_base + ch4 + 1) * 4);
    float4 w2 = *(const float4*)(conv_w + (ch_base + ch4 + 2) * 4);
    float4 w3 = *(const float4*)(conv_w + (ch_base + ch4 + 3) * 4);
#pragma unroll
    for (int li = 0; li < 4; li++) {
        int lloc = ty * 4 + li;
        float a0 = 0.f, a1 = 0.f, a2 = 0.f, a3 = 0.f;
#pragma unroll
        for (int j = 0; j < 4; j++) {
            const float* row = &sxm[lloc + j][ch4];
            a0 = fmaf(row[0], (&w0.x)[j], a0);
            a1 = fmaf(row[1], (&w1.x)[j], a1);
            a2 = fmaf(row[2], (&w2.x)[j], a2);
            a3 = fmaf(row[3], (&w3.x)[j], a3);
        }
        float4 o;
        o.x = silu_f(silu_f(a0));
        o.y = silu_f(silu_f(a1));
        o.z = silu_f(silu_f(a2));
        o.w = silu_f(silu_f(a3));
        *(float4*)(g_xbc + (size_t)(b * Lseq + l0 + lloc) * CONVD + ch_base + ch4) = o;
    }
}

// ------------- G = C * B^T per (b,c), 4-way split over l --------------------
__global__ __launch_bounds__(256) void gmat_kernel()
{
    int c = blockIdx.x, b = blockIdx.y, z = blockIdx.z;
    __shared__ float sB[64][33];
    __shared__ float sC[16][33];
    int tid = threadIdx.x;
    int tx = tid & 15, ty = tid >> 4;
    int lloc = ty, s0 = tx * 4;
    size_t rowbase = (size_t)(b * Lseq + c * CHK);
    int lg = z * 16;
    float g4[4] = {0.f, 0.f, 0.f, 0.f};

    for (int nc = 0; nc < Nn; nc += 32) {
        for (int t = tid; t < 64 * 8; t += 256) {
            int l = t >> 3, q = (t & 7) * 4;
            float4 bv = *(const float4*)(g_xbc + (rowbase + l) * CONVD + DI + nc + q);
            sB[l][q + 0] = bv.x; sB[l][q + 1] = bv.y;
            sB[l][q + 2] = bv.z; sB[l][q + 3] = bv.w;
        }
        if (tid < 16 * 8) {
            int l = tid >> 3, q = (tid & 7) * 4;
            float4 cv = *(const float4*)(g_xbc + (rowbase + lg + l) * CONVD + DI + Nn + nc + q);
            sC[l][q + 0] = cv.x; sC[l][q + 1] = cv.y;
            sC[l][q + 2] = cv.z; sC[l][q + 3] = cv.w;
        }
        __syncthreads();
#pragma unroll
        for (int n = 0; n < 32; n++) {
            float cr = sC[lloc][n];
            g4[0] = fmaf(cr, sB[s0 + 0][n], g4[0]);
            g4[1] = fmaf(cr, sB[s0 + 1][n], g4[1]);
            g4[2] = fmaf(cr, sB[s0 + 2][n], g4[2]);
            g4[3] = fmaf(cr, sB[s0 + 3][n], g4[3]);
        }
        __syncthreads();
    }
    float* Gp = g_G + ((size_t)(b * NCHUNK + c)) * (CHK * CHK);
    float4 v = make_float4(g4[0], g4[1], g4[2], g4[3]);
    *(float4*)(Gp + (lg + lloc) * 64 + s0) = v;
}

// -------------- per-chunk SSD via tensor cores (fp16 mma) -------------------
__global__ __launch_bounds__(256) void chunk_kernel()
{
    __shared__ __half sM[64][72];
    __shared__ __half sX[64][72];
    __shared__ __half sXd[64][72];
    __shared__ __half sB[64][136];
    __shared__ float scs[64];
    __shared__ float sDec[64];
    int c = blockIdx.x, h = blockIdx.y, b = blockIdx.z;
    int tid = threadIdx.x, lane = tid & 31, wid = tid >> 5;
    size_t rowbase = (size_t)(b * Lseq + c * CHK);

    if (wid == 0) {
        float v0 = g_adt[(rowbase + lane) * Hh + h];
        float v1 = g_adt[(rowbase + 32 + lane) * Hh + h];
#pragma unroll
        for (int off = 1; off < 32; off <<= 1) {
            float t = __shfl_up_sync(0xFFFFFFFF, v0, off);
            if (lane >= off) v0 += t;
        }
        float tot = __shfl_sync(0xFFFFFFFF, v0, 31);
#pragma unroll
        for (int off = 1; off < 32; off <<= 1) {
            float t = __shfl_up_sync(0xFFFFFFFF, v1, off);
            if (lane >= off) v1 += t;
        }
        v1 += tot;
        float alast = __shfl_sync(0xFFFFFFFF, v1, 31);
        scs[lane] = v0;
        scs[32 + lane] = v1;
        sDec[lane] = __expf(alast - v0);
        sDec[32 + lane] = __expf(alast - v1);
    }
    for (int i = tid; i < 64 * 32; i += 256) {
        int l = i >> 5, q = (i & 31) * 4;
        float4 v = *(const float4*)(g_xbc + (rowbase + l) * CONVD + DI + q);
        sB[l][q + 0] = __float2half_rn(v.x);
        sB[l][q + 1] = __float2half_rn(v.y);
        sB[l][q + 2] = __float2half_rn(v.z);
        sB[l][q + 3] = __float2half_rn(v.w);
    }
    __syncthreads();

    for (int i = tid; i < 64 * 16; i += 256) {
        int l = i >> 4, q = (i & 15) * 4;
        float4 v = *(const float4*)(g_xbc + (rowbase + l) * CONVD + h * 64 + q);
        float d = g_dt[(rowbase + l) * Hh + h];
        float e = sDec[l];
        float x0 = v.x * d, x1 = v.y * d, x2 = v.z * d, x3 = v.w * d;
        sX[l][q + 0] = __float2half_rn(x0);
        sX[l][q + 1] = __float2half_rn(x1);
        sX[l][q + 2] = __float2half_rn(x2);
        sX[l][q + 3] = __float2half_rn(x3);
        sXd[l][q + 0] = __float2half_rn(x0 * e);
        sXd[l][q + 1] = __float2half_rn(x1 * e);
        sXd[l][q + 2] = __float2half_rn(x2 * e);
        sXd[l][q + 3] = __float2half_rn(x3 * e);
    }
    {
        int tx = tid & 15, ty = tid >> 4;
        int l0 = ty * 4, s0 = tx * 4;
        const float* Gp = g_G + ((size_t)(b * NCHUNK + c)) * (CHK * CHK);
#pragma unroll
        for (int i = 0; i < 4; i++) {
            int l = l0 + i;
            if (s0 > l) {
                sM[l][s0 + 0] = __float2half_rn(0.f);
                sM[l][s0 + 1] = __float2half_rn(0.f);
                sM[l][s0 + 2] = __float2half_rn(0.f);
                sM[l][s0 + 3] = __float2half_rn(0.f);
            } else {
                float4 gv = *(const float4*)(Gp + l * 64 + s0);
                float csl = scs[l];
                if (s0 + 3 <= l) {
                    sM[l][s0 + 0] = __float2half_rn(gv.x * __expf(csl - scs[s0 + 0]));
                    sM[l][s0 + 1] = __float2half_rn(gv.y * __expf(csl - scs[s0 + 1]));
                    sM[l][s0 + 2] = __float2half_rn(gv.z * __expf(csl - scs[s0 + 2]));
                    sM[l][s0 + 3] = __float2half_rn(gv.w * __expf(csl - scs[s0 + 3]));
                } else {
                    sM[l][s0 + 0] = __float2half_rn((s0 + 0 <= l) ? gv.x * __expf(csl - scs[s0 + 0]) : 0.f);
                    sM[l][s0 + 1] = __float2half_rn((s0 + 1 <= l) ? gv.y * __expf(csl - scs[s0 + 1]) : 0.f);
                    sM[l][s0 + 2] = __float2half_rn((s0 + 2 <= l) ? gv.z * __expf(csl - scs[s0 + 2]) : 0.f);
                    sM[l][s0 + 3] = __float2half_rn((s0 + 3 <= l) ? gv.w * __expf(csl - scs[s0 + 3]) : 0.f);
                }
            }
        }
    }
    __syncthreads();

    int gp = lane >> 2, tg = lane & 3;
    {
        int wm = wid & 3, wn = wid >> 2;
        float cy[4][4];
#pragma unroll
        for (int i = 0; i < 4; i++)
#pragma unroll
            for (int j = 0; j < 4; j++) cy[i][j] = 0.f;
#pragma unroll
        for (int k0 = 0; k0 < 64; k0 += 16) {
            uint32_t a[4];
            ldmx4(a, smem_to_u32(&sM[wm * 16 + (lane & 15)][k0 + ((lane >> 4) << 3)]));
#pragma unroll
            for (int g = 0; g < 2; g++) {
                uint32_t bf[4];
                ldmx4t(bf, smem_to_u32(&sX[k0 + (lane & 15)][wn * 32 + g * 16 + ((lane >> 4) << 3)]));
                mma16816h(cy[g * 2 + 0], a, bf[0], bf[1]);
                mma16816h(cy[g * 2 + 1], a, bf[2], bf[3]);
            }
        }
#pragma unroll
        for (int nb = 0; nb < 4; nb++) {
            int p = wn * 32 + nb * 8 + tg * 2;
#pragma unroll
            for (int hf = 0; hf < 2; hf++) {
                int l = wm * 16 + gp + hf * 8;
                float2 v = make_float2(cy[nb][hf * 2 + 0], cy[nb][hf * 2 + 1]);
                *(float2*)(g_Y + (rowbase + l) * DI + h * 64 + p) = v;
            }
        }
    }

    {
        int pmw = wid & 3, nw = wid >> 2;
        int p0 = pmw * 16, n0 = nw * 64;
        float cs2[8][4];
#pragma unroll
        for (int i = 0; i < 8; i++)
#pragma unroll
            for (int j = 0; j < 4; j++) cs2[i][j] = 0.f;
#pragma unroll
        for (int k0 = 0; k0 < 64; k0 += 16) {
            uint32_t r[4];
            ldmx4t(r, smem_to_u32(&sXd[k0 + (lane & 15)][p0 + ((lane >> 4) << 3)]));
            uint32_t a[4] = {r[0], r[2], r[1], r[3]};
#pragma unroll
            for (int g = 0; g < 4; g++) {
                uint32_t bf[4];
                ldmx4t(bf, smem_to_u32(&sB[k0 + (lane & 15)][n0 + g * 16 + ((lane >> 4) << 3)]));
                mma16816h(cs2[g * 2 + 0], a, bf[0], bf[1]);
                mma16816h(cs2[g * 2 + 1], a, bf[2], bf[3]);
            }
        }
        size_t sbase = (((size_t)(b * NCHUNK + c)) * Hh + h) * (Pp * Nn);
#pragma unroll
        for (int nb = 0; nb < 8; nb++) {
            int n = n0 + nb * 8 + tg * 2;
#pragma unroll
            for (int hf = 0; hf < 2; hf++) {
                int p = p0 + gp + hf * 8;
                float2 v = make_float2(cs2[nb][hf * 2 + 0], cs2[nb][hf * 2 + 1]);
                *(float2*)(g_states + sbase + (size_t)p * Nn + n) = v;
            }
        }
    }

    if (tid < 64) g_cs[((b * NCHUNK + c) * Hh + h) * CHK + tid] = expf(scs[tid]);
    if (tid == 0) g_lastA[(b * NCHUNK + c) * Hh + h] = expf(scs[63]);
}

// ---------- inter-chunk scan, 8-way sliced, float4 (dec pre-exp'd) ----------
__global__ __launch_bounds__(256) void scan_kernel(const float* __restrict__ init_state,
                                                   float* __restrict__ fstate_out)
{
    int bh = blockIdx.x;
    int h = bh & (Hh - 1), b = bh >> 5;
    int off = blockIdx.y * 1024 + threadIdx.x * 4;
    size_t ibase = ((size_t)(b * Hh + h)) * (Pp * Nn);
    float4 run = *(const float4*)(init_state + ibase + off);
    for (int c = 0; c < NCHUNK; c++) {
        float dec = g_lastA[(b * NCHUNK + c) * Hh + h];
        size_t idx = (((size_t)(b * NCHUNK + c)) * Hh + h) * (Pp * Nn) + off;
        float4 v = *(const float4*)(g_states + idx);
        *(float4*)(g_states + idx) = run;
        run.x = fmaf(dec, run.x, v.x);
        run.y = fmaf(dec, run.y, v.y);
        run.z = fmaf(dec, run.z, v.z);
        run.w = fmaf(dec, run.w, v.w);
    }
    *(float4*)(fstate_out + ibase + off) = run;
}

// --------------- Y_off + D*X epilogue via tensor cores (cs pre-exp'd) -------
__global__ __launch_bounds__(256) void yoff_kernel(const float* __restrict__ D_param)
{
    __shared__ __half sC[64][136];
    __shared__ __half sS[64][136];
    __shared__ float scs[64];
    int c = blockIdx.x, h = blockIdx.y, b = blockIdx.z;
    int tid = threadIdx.x, lane = tid & 31, wid = tid >> 5;
    size_t rowbase = (size_t)(b * Lseq + c * CHK);
    if (tid < 64) scs[tid] = g_cs[((b * NCHUNK + c) * Hh + h) * CHK + tid];

    size_t sbase = (((size_t)(b * NCHUNK + c)) * Hh + h) * (Pp * Nn);
    for (int t = tid; t < 64 * 32; t += 256) {
        int r = t >> 5, q = (t & 31) * 4;
        float4 cv = *(const float4*)(g_xbc + (rowbase + r) * CONVD + DI + Nn + q);
        sC[r][q + 0] = __float2half_rn(cv.x);
        sC[r][q + 1] = __float2half_rn(cv.y);
        sC[r][q + 2] = __float2half_rn(cv.z);
        sC[r][q + 3] = __float2half_rn(cv.w);
        float4 sv = *(const float4*)(g_states + sbase + (size_t)r * Nn + q);
        sS[r][q + 0] = __float2half_rn(sv.x);
        sS[r][q + 1] = __float2half_rn(sv.y);
        sS[r][q + 2] = __float2half_rn(sv.z);
        sS[r][q + 3] = __float2half_rn(sv.w);
    }
    __syncthreads();

    int wm = wid & 3, wn = wid >> 2;
    int l0 = wm * 16, p0 = wn * 32;
    float acc[4][4];
#pragma unroll
    for (int i = 0; i < 4; i++)
#pragma unroll
        for (int j = 0; j < 4; j++) acc[i][j] = 0.f;

#pragma unroll
    for (int k0 = 0; k0 < Nn; k0 += 16) {
        uint32_t a[4];
        ldmx4(a, smem_to_u32(&sC[l0 + (lane & 15)][k0 + ((lane >> 4) << 3)]));
        uint32_t bf[2][4];
#pragma unroll
        for (int g = 0; g < 2; g++)
            ldmx4(bf[g], smem_to_u32(
                &sS[p0 + g * 16 + (((lane >> 3) & 1) << 3) + (lane & 7)][k0 + ((lane >> 4) << 3)]));
#pragma unroll
        for (int nb = 0; nb < 4; nb++) {
            int ib = nb >> 1, wh = nb & 1;
            mma16816h(acc[nb], a, bf[ib][wh], bf[ib][2 + wh]);
        }
    }
    float Dh = D_param[h];
    int gp = lane >> 2, tg = lane & 3;
#pragma unroll
    for (int nb = 0; nb < 4; nb++) {
        int p = p0 + nb * 8 + tg * 2;
#pragma unroll
        for (int hf = 0; hf < 2; hf++) {
            int l = l0 + gp + hf * 8;
            float e = scs[l];
            size_t gi = (rowbase + l) * DI + h * 64 + p;
            float2 yv = *(const float2*)(g_Y + gi);
            float2 xv = *(const float2*)(g_xbc + (rowbase + l) * CONVD + h * 64 + p);
            yv.x += e * acc[nb][hf * 2 + 0] + Dh * xv.x;
            yv.y += e * acc[nb][hf * 2 + 1] + Dh * xv.y;
            *(float2*)(g_Y + gi) = yv;
        }
    }
}

// -------- RMSNorm * norm_w * sigmoid(z) -> fp16 y_core (float4) --------------
__global__ __launch_bounds__(256) void rms_cvt_kernel(const float* __restrict__ norm_w)
{
    int row = blockIdx.x;
    int tid = threadIdx.x, lane = tid & 31, wid = tid >> 5;
    __shared__ float red[8];
    const float* y = g_Y + (size_t)row * DI;
    float ss = 0.f;
#pragma unroll
    for (int it = 0; it < 2; it++) {
        int j = (tid + it * 256) * 4;
        float4 v = *(const float4*)(y + j);
        ss = fmaf(v.x, v.x, ss);
        ss = fmaf(v.y, v.y, ss);
        ss = fmaf(v.z, v.z, ss);
        ss = fmaf(v.w, v.w, ss);
    }
#pragma unroll
    for (int off = 16; off > 0; off >>= 1) ss += __shfl_xor_sync(0xFFFFFFFF, ss, off);
    if (lane == 0) red[wid] = ss;
    __syncthreads();
    if (wid == 0) {
        float v = (lane < 8) ? red[lane] : 0.f;
#pragma unroll
        for (int off = 4; off > 0; off >>= 1) v += __shfl_xor_sync(0xFFFFFFFF, v, off);
        if (lane == 0) red[0] = v;
    }
    __syncthreads();
    float scale = rsqrtf(red[0] / (float)DI + EPSV);
    __half* ph = g_ych + (size_t)row * DI;
#pragma unroll
    for (int it = 0; it < 2; it++) {
        int j = (tid + it * 256) * 4;
        float4 yv = *(const float4*)(y + j);
        float4 zv = *(const float4*)(g_zxbcdt + (size_t)row * PROJ + j);
        __half2 h0, h1;
        h0.x = __float2half_rn(yv.x * scale * norm_w[j + 0] / (1.f + __expf(-zv.x)));
        h0.y = __float2half_rn(yv.y * scale * norm_w[j + 1] / (1.f + __expf(-zv.y)));
        h1.x = __float2half_rn(yv.z * scale * norm_w[j + 2] / (1.f + __expf(-zv.z)));
        h1.y = __float2half_rn(yv.w * scale * norm_w[j + 3] / (1.f + __expf(-zv.w)));
        *(__half2*)(ph + j) = h0;
        *(__half2*)(ph + j + 2) = h1;
    }
}

// ------------------------- launch ------------------------------------------
extern "C" void kernel_launch(void* const* d_in, const int* in_sizes, int n_in,
                              void* d_out, int out_size)
{
    const float* x         = (const float*)d_in[0];
    const float* state     = (const float*)d_in[1];
    const float* in_proj_w = (const float*)d_in[2];
    const float* conv_w    = (const float*)d_in[3];
    const float* A_log     = (const float*)d_in[4];
    const float* dt_bias   = (const float*)d_in[5];
    const float* D_param   = (const float*)d_in[6];
    const float* norm_w    = (const float*)d_in[7];
    const float* out_proj_w= (const float*)d_in[8];
    float* out = (float*)d_out;

    float* zx;   cudaGetSymbolAddress((void**)&zx, g_zxbcdt);
    __half *xh, *wih, *ych, *woh;
    cudaGetSymbolAddress((void**)&xh, g_xh);
    cudaGetSymbolAddress((void**)&wih, g_wih);
    cudaGetSymbolAddress((void**)&ych, g_ych);
    cudaGetSymbolAddress((void**)&woh, g_woh);

    cudaFuncSetAttribute(gemm_fp16, cudaFuncAttributeMaxDynamicSharedMemorySize, GSMEM_BYTES);
    cudaFuncSetAttribute(dtfix_kernel, cudaFuncAttributeMaxDynamicSharedMemorySize, DTSM_BYTES);

    // side streams + events (created once)
    static cudaStream_t s1 = nullptr, s2 = nullptr, s3 = nullptr;
    static cudaEvent_t ev_root = nullptr, ev_cvt = nullptr, ev_p2 = nullptr,
                       ev_dt = nullptr, ev_g1 = nullptr, ev_cx = nullptr, ev_wo = nullptr;
    if (!s1) {
        cudaStreamCreateWithFlags(&s1, cudaStreamNonBlocking);
        cudaStreamCreateWithFlags(&s2, cudaStreamNonBlocking);
        cudaStreamCreateWithFlags(&s3, cudaStreamNonBlocking);
        cudaEventCreateWithFlags(&ev_root, cudaEventDisableTiming);
        cudaEventCreateWithFlags(&ev_cvt, cudaEventDisableTiming);
        cudaEventCreateWithFlags(&ev_p2, cudaEventDisableTiming);
        cudaEventCreateWithFlags(&ev_dt, cudaEventDisableTiming);
        cudaEventCreateWithFlags(&ev_g1, cudaEventDisableTiming);
        cudaEventCreateWithFlags(&ev_cx, cudaEventDisableTiming);
        cudaEventCreateWithFlags(&ev_wo, cudaEventDisableTiming);
    }

    // fork root: dtfix + w_out convert on s2
    cudaEventRecord(ev_root, 0);
    cudaStreamWaitEvent(s2, ev_root, 0);
    dtfix_kernel<<<ML / 64, 256, DTSM_BYTES, s2>>>(x, in_proj_w, A_log, dt_bias);
    cudaEventRecord(ev_dt, s2);
    cvt_wo_kernel<<<(unsigned)((CVT_NWO + 255) / 256), 256, 0, s2>>>(out_proj_w);
    cudaEventRecord(ev_wo, s2);

    // 1) x + W_in converts (main, critical)
    {
        size_t total = CVT_NX + CVT_NW;
        cvt_xw_kernel<<<(unsigned)((total + 255) / 256), 256>>>(x, in_proj_w);
    }
    cudaEventRecord(ev_cvt, 0);

    // 2a) in_proj GEMM part1: columns [DI, PROJPAD) — feeds conv (main)
    gemm_fp16<<<dim3((PROJPAD - DI) / 128, ML / 128), 256, GSMEM_BYTES>>>(
        xh, wih, nullptr, zx, DM, PROJ, DI);
    cudaEventRecord(ev_g1, 0);
    // 2b) in_proj GEMM part2: z columns [0, DI) — forked
    cudaStreamWaitEvent(s1, ev_cvt, 0);
    gemm_fp16<<<dim3(DI / 128, ML / 128), 256, GSMEM_BYTES, s1>>>(
        xh, wih, nullptr, zx, DM, PROJ, 0);
    cudaEventRecord(ev_p2, s1);

    // 3a) conv B/C channels (chunks 16,17) — main, feeds gmat
    conv_kernel<<<dim3(2, Bsz * (Lseq / 32)), 256>>>(conv_w, 16);
    // 3b) conv x channels (chunks 0..15) — forked on s3
    cudaStreamWaitEvent(s3, ev_g1, 0);
    conv_kernel<<<dim3(16, Bsz * (Lseq / 32)), 256, 0, s3>>>(conv_w, 0);
    cudaEventRecord(ev_cx, s3);

    // 4) G = C B^T (main, needs only B/C)
    gmat_kernel<<<dim3(NCHUNK, Bsz, 4), 256>>>();
    // 5) per-chunk SSD (needs dtfix + conv_x)
    cudaStreamWaitEvent(0, ev_dt, 0);
    cudaStreamWaitEvent(0, ev_cx, 0);
    chunk_kernel<<<dim3(NCHUNK, Hh, Bsz), 256>>>();
    // 6) inter-chunk scan + final state
    scan_kernel<<<dim3(Bsz * Hh, 8), 256>>>(state, out + (size_t)ML * DM);
    // 7) Y_off + D*X
    yoff_kernel<<<dim3(NCHUNK, Hh, Bsz), 256>>>(D_param);
    // 8) RMSNorm + gate + fp16 convert (needs z from gemm part2)
    cudaStreamWaitEvent(0, ev_p2, 0);
    rms_cvt_kernel<<<ML, 256>>>(norm_w);
    // 9) out_proj GEMM + residual -> d_out (needs w_out convert)
    cudaStreamWaitEvent(0, ev_wo, 0);
    gemm_fp16<<<dim3(DM / 128, ML / 128), 256, GSMEM_BYTES>>>(
        ych, woh, x, out, DI, DM, 0);
}